// round 1
// baseline (speedup 1.0000x reference)
#include <cuda_runtime.h>

#define NB 16
#define NPOS 4096
#define SCALE 0.17677669529663687f   // 32^-0.5
#define INVN (1.0f / 4096.0f)
#define NCHUNK 8

// ---------------- scratch (device globals; no runtime allocation) ----------------
__device__ float g_qkv[NB * 384 * NPOS];        // 96 MB: rows 0..127 q(raw), 128..255 k(FiLM), 256..383 v(FiLM,/n)
__device__ float g_film[NB * 512];              // [sk(128), shk(128), sv(128), shv(128)] per batch
__device__ float g_kmax[NB * 128];              // per (b, k-channel) max over n
__device__ float g_Sp[NCHUNK * NB * 4 * 32 * 32]; // partial context numerators per n-chunk
__device__ float g_Zp[NCHUNK * NB * 128];       // partial softmax denominators per n-chunk
__device__ float g_M[NB * 256 * 128];           // M_b = W_out * blockdiag(context)

// ---------------- FiLM: cond -> (sk, shk, sv, shv) ----------------
__global__ void film_kernel(const float* __restrict__ cond,
                            const float* __restrict__ Wc,
                            const float* __restrict__ bc) {
    int b = blockIdx.x, t = threadIdx.x;
    __shared__ float sc[256];
    if (t < 256) {
        float xv = cond[b * 256 + t];
        sc[t] = xv / (1.0f + __expf(-xv));   // silu
    }
    __syncthreads();
    const float* wr = Wc + t * 256;
    float acc = bc[t];
#pragma unroll 8
    for (int j = 0; j < 256; j++) acc += wr[j] * sc[j];
    g_film[b * 512 + t] = acc;
}

// ---------------- qkv GEMM: (384x256) @ (256x4096) per batch, FiLM epilogue ----------------
// 128x128x8 tile, 256 threads, 8x8 micro-tile per thread.
__global__ void __launch_bounds__(256) qkv_gemm(const float* __restrict__ Wq,
                                                const float* __restrict__ X) {
    int b = blockIdx.z;
    int m0 = blockIdx.y * 128, n0 = blockIdx.x * 128;
    __shared__ float As[8][128];   // transposed: As[k][m]
    __shared__ float Bs[8][128];
    int t = threadIdx.x;
    int tx = t & 15, ty = t >> 4;

    float acc[8][8];
#pragma unroll
    for (int i = 0; i < 8; i++)
#pragma unroll
        for (int j = 0; j < 8; j++) acc[i][j] = 0.0f;

    int arow = t >> 1, acol = (t & 1) << 2;      // A tile: 128 rows x 8 k
    int brow = t >> 5, bcol = (t & 31) << 2;     // B tile: 8 k x 128 cols
    const float* Aptr = Wq + (m0 + arow) * 256 + acol;
    const float* Bptr = X + (size_t)b * 256 * NPOS + (size_t)brow * NPOS + n0 + bcol;

    for (int kk = 0; kk < 256; kk += 8) {
        float4 av = *(const float4*)(Aptr + kk);
        float4 bv = *(const float4*)(Bptr + (size_t)kk * NPOS);
        __syncthreads();
        As[acol + 0][arow] = av.x;
        As[acol + 1][arow] = av.y;
        As[acol + 2][arow] = av.z;
        As[acol + 3][arow] = av.w;
        *(float4*)&Bs[brow][bcol] = bv;
        __syncthreads();
#pragma unroll
        for (int k = 0; k < 8; k++) {
            float4 a0 = *(const float4*)&As[k][ty << 3];
            float4 a1 = *(const float4*)&As[k][(ty << 3) + 4];
            float4 b0 = *(const float4*)&Bs[k][tx << 3];
            float4 b1 = *(const float4*)&Bs[k][(tx << 3) + 4];
            float ar[8] = {a0.x, a0.y, a0.z, a0.w, a1.x, a1.y, a1.z, a1.w};
            float br[8] = {b0.x, b0.y, b0.z, b0.w, b1.x, b1.y, b1.z, b1.w};
#pragma unroll
            for (int i = 0; i < 8; i++)
#pragma unroll
                for (int j = 0; j < 8; j++) acc[i][j] += ar[i] * br[j];
        }
    }

    const float* fb = g_film + b * 512;
    float* C = g_qkv + (size_t)b * 384 * NPOS;
#pragma unroll
    for (int i = 0; i < 8; i++) {
        int m = m0 + (ty << 3) + i;
        float alpha = 1.0f, beta = 0.0f;
        if (m >= 256) {                       // v rows: ((1+sv)v + shv)/n
            int c = m - 256;
            alpha = (1.0f + fb[256 + c]) * INVN;
            beta = fb[384 + c] * INVN;
        } else if (m >= 128) {                // k rows: (1+sk)k + shk
            int c = m - 128;
            alpha = 1.0f + fb[c];
            beta = fb[128 + c];
        }
        float4 o0, o1;
        o0.x = fmaf(alpha, acc[i][0], beta);
        o0.y = fmaf(alpha, acc[i][1], beta);
        o0.z = fmaf(alpha, acc[i][2], beta);
        o0.w = fmaf(alpha, acc[i][3], beta);
        o1.x = fmaf(alpha, acc[i][4], beta);
        o1.y = fmaf(alpha, acc[i][5], beta);
        o1.z = fmaf(alpha, acc[i][6], beta);
        o1.w = fmaf(alpha, acc[i][7], beta);
        *(float4*)&C[(size_t)m * NPOS + n0 + (tx << 3)] = o0;
        *(float4*)&C[(size_t)m * NPOS + n0 + (tx << 3) + 4] = o1;
    }
}

// ---------------- per (b, k-channel) max over n ----------------
__global__ void kmax_kernel() {
    int b = blockIdx.y, c = blockIdx.x, t = threadIdx.x;
    const float* row = g_qkv + ((size_t)b * 384 + 128 + c) * NPOS;
    float m = -1e30f;
    for (int i = t; i < NPOS; i += 256) m = fmaxf(m, row[i]);
    __shared__ float red[8];
#pragma unroll
    for (int o = 16; o; o >>= 1) m = fmaxf(m, __shfl_xor_sync(0xffffffffu, m, o));
    if ((t & 31) == 0) red[t >> 5] = m;
    __syncthreads();
    if (t < 8) {
        m = red[t];
#pragma unroll
        for (int o = 4; o; o >>= 1) m = fmaxf(m, __shfl_xor_sync(0xffu, m, o));
        if (t == 0) g_kmax[b * 128 + c] = m;
    }
}

// ---------------- context partials: S[c][e] = sum_n exp(k[c][n]-m[c]) * v[e][n] ----------------
// grid (chunk=8, head=4, batch=16), 256 threads. Deterministic: each chunk writes its own slot.
__global__ void __launch_bounds__(256) ctx_kernel() {
    int b = blockIdx.z, h = blockIdx.y, chunk = blockIdx.x;
    int nbase = chunk * 512;
    int t = threadIdx.x;
    __shared__ float Et[32][65];
    __shared__ float Vt[32][65];
    int c = t & 31, e4 = t >> 5;                 // compute mapping: S[c][e4*4 .. +3]
    int rF = t >> 3, cF = (t & 7) << 3;          // fill mapping
    const float* Kb = g_qkv + ((size_t)b * 384 + 128 + h * 32 + rF) * NPOS + nbase + cF;
    const float* Vb = g_qkv + ((size_t)b * 384 + 256 + h * 32 + rF) * NPOS + nbase + cF;
    float km = g_kmax[b * 128 + h * 32 + rF];

    float a0 = 0.f, a1 = 0.f, a2 = 0.f, a3 = 0.f, z = 0.f;
    for (int sub = 0; sub < 8; sub++) {
        float4 k0 = *(const float4*)(Kb + sub * 64);
        float4 k1 = *(const float4*)(Kb + sub * 64 + 4);
        float4 v0 = *(const float4*)(Vb + sub * 64);
        float4 v1 = *(const float4*)(Vb + sub * 64 + 4);
        __syncthreads();
        Et[rF][cF + 0] = __expf(k0.x - km);
        Et[rF][cF + 1] = __expf(k0.y - km);
        Et[rF][cF + 2] = __expf(k0.z - km);
        Et[rF][cF + 3] = __expf(k0.w - km);
        Et[rF][cF + 4] = __expf(k1.x - km);
        Et[rF][cF + 5] = __expf(k1.y - km);
        Et[rF][cF + 6] = __expf(k1.z - km);
        Et[rF][cF + 7] = __expf(k1.w - km);
        Vt[rF][cF + 0] = v0.x; Vt[rF][cF + 1] = v0.y;
        Vt[rF][cF + 2] = v0.z; Vt[rF][cF + 3] = v0.w;
        Vt[rF][cF + 4] = v1.x; Vt[rF][cF + 5] = v1.y;
        Vt[rF][cF + 6] = v1.z; Vt[rF][cF + 7] = v1.w;
        __syncthreads();
#pragma unroll 16
        for (int n = 0; n < 64; n++) {
            float ec = Et[c][n];
            if (e4 == 0) z += ec;                // warp-uniform predicate
            a0 += ec * Vt[(e4 << 2) + 0][n];
            a1 += ec * Vt[(e4 << 2) + 1][n];
            a2 += ec * Vt[(e4 << 2) + 2][n];
            a3 += ec * Vt[(e4 << 2) + 3][n];
        }
    }
    float* Sp = g_Sp + ((((size_t)chunk * NB + b) * 4 + h) * 32 + c) * 32 + (e4 << 2);
    Sp[0] = a0; Sp[1] = a1; Sp[2] = a2; Sp[3] = a3;
    if (e4 == 0) g_Zp[((size_t)chunk * NB + b) * 128 + h * 32 + c] = z;
}

// ---------------- build M_b = W_out * blockdiag(context_b) ----------------
__global__ void buildM_kernel(const float* __restrict__ Wout) {
    int b = blockIdx.x, t = threadIdx.x;
    __shared__ float ctxs[4096];   // [h][c][e]
    __shared__ float zsm[128];
    if (t < 128) {
        float zz = 0.f;
#pragma unroll
        for (int ch = 0; ch < NCHUNK; ch++) zz += g_Zp[((size_t)ch * NB + b) * 128 + t];
        zsm[t] = zz;
    }
    __syncthreads();
    for (int i = t; i < 4096; i += 256) {
        int h = i >> 10, c = (i >> 5) & 31;
        float s = 0.f;
#pragma unroll
        for (int ch = 0; ch < NCHUNK; ch++) s += g_Sp[((size_t)ch * NB + b) * 4096 + i];
        ctxs[i] = s / zsm[h * 32 + c];
    }
    __syncthreads();
    const float* wr = Wout + t * 128;
    float* Mr = g_M + (size_t)b * 32768 + t * 128;
    for (int h = 0; h < 4; h++) {
        float w[32];
#pragma unroll
        for (int e = 0; e < 32; e++) w[e] = wr[h * 32 + e];
        for (int c2 = 0; c2 < 32; c2++) {
            float s = 0.f;
#pragma unroll
            for (int e = 0; e < 32; e++) s += w[e] * ctxs[h * 1024 + c2 * 32 + e];
            Mr[h * 32 + c2] = s;
        }
    }
}

// ---------------- final: y = M_b @ softmax_c(q)*scale + b_out, then LayerNorm*g ----------------
// grid (chunk=8, batch=16), 256 threads. M_b (256x128) staged in smem (pad 129),
// q tile 128x32 staged+softmaxed in smem (pad 36). Thread: 8 rows x 4 cols.
#define SM_MS   (256 * 129)
#define SM_QS   (128 * 36)
#define SM_TOT  (SM_MS + SM_QS + 256 + 256 + 32 + 32 + 256 + 256)

__global__ void __launch_bounds__(256) final_kernel(const float* __restrict__ bout,
                                                    const float* __restrict__ gam,
                                                    float* __restrict__ out) {
    extern __shared__ float sm[];
    float* Msm = sm;
    float* qs = sm + SM_MS;
    float* bsm = qs + SM_QS;
    float* gsm = bsm + 256;
    float* csum = gsm + 256;
    float* csq = csum + 32;
    float* wsum = csq + 32;      // [8 warps][32 cols]
    float* wsq = wsum + 256;

    int b = blockIdx.y, chunk = blockIdx.x, t = threadIdx.x;
    for (int i = t; i < 32768; i += 256)
        Msm[(i >> 7) * 129 + (i & 127)] = g_M[(size_t)b * 32768 + i];
    bsm[t] = bout[t];
    gsm[t] = gam[t];
    const float* Q = g_qkv + (size_t)b * 384 * NPOS;
    int j4 = t & 7, rg = (t >> 3) << 3;
    int w = t >> 5;

    for (int s = 0; s < 16; s++) {
        int n0 = chunk * 512 + s * 32;
        __syncthreads();
        // load q tile (raw channels 0..127 x 32 cols)
        for (int i = t; i < 4096; i += 256)
            qs[(i >> 5) * 36 + (i & 31)] = Q[(size_t)(i >> 5) * NPOS + n0 + (i & 31)];
        __syncthreads();
        // per-(head, col) softmax over 32 channels, *scale
        if (t < 128) {
            float* col = qs + (t >> 5) * 32 * 36 + (t & 31);
            float mx = col[0];
#pragma unroll
            for (int cI = 1; cI < 32; cI++) mx = fmaxf(mx, col[cI * 36]);
            float ssum = 0.f;
#pragma unroll
            for (int cI = 0; cI < 32; cI++) {
                float e = __expf(col[cI * 36] - mx);
                ssum += e;
                col[cI * 36] = e;
            }
            float inv = SCALE / ssum;
#pragma unroll
            for (int cI = 0; cI < 32; cI++) col[cI * 36] *= inv;
        }
        __syncthreads();
        // GEMM: 256x32 tile
        float acc[8][4];
#pragma unroll
        for (int i = 0; i < 8; i++)
#pragma unroll
            for (int j = 0; j < 4; j++) acc[i][j] = 0.0f;
#pragma unroll 8
        for (int kk = 0; kk < 128; kk++) {
            float4 qv = *(const float4*)&qs[kk * 36 + (j4 << 2)];
#pragma unroll
            for (int i = 0; i < 8; i++) {
                float mv = Msm[(rg + i) * 129 + kk];
                acc[i][0] += mv * qv.x;
                acc[i][1] += mv * qv.y;
                acc[i][2] += mv * qv.z;
                acc[i][3] += mv * qv.w;
            }
        }
        // + bias, column stats
        float ps[4] = {0.f, 0.f, 0.f, 0.f}, pq[4] = {0.f, 0.f, 0.f, 0.f};
#pragma unroll
        for (int i = 0; i < 8; i++) {
            float bo = bsm[rg + i];
#pragma unroll
            for (int j = 0; j < 4; j++) {
                float v = acc[i][j] + bo;
                acc[i][j] = v;
                ps[j] += v;
                pq[j] += v * v;
            }
        }
#pragma unroll
        for (int j = 0; j < 4; j++) {
            ps[j] += __shfl_xor_sync(0xffffffffu, ps[j], 8);
            ps[j] += __shfl_xor_sync(0xffffffffu, ps[j], 16);
            pq[j] += __shfl_xor_sync(0xffffffffu, pq[j], 8);
            pq[j] += __shfl_xor_sync(0xffffffffu, pq[j], 16);
        }
        if ((t & 24) == 0) {    // lanes 0..7 of each warp hold warp totals
#pragma unroll
            for (int j = 0; j < 4; j++) {
                wsum[w * 32 + (j4 << 2) + j] = ps[j];
                wsq[w * 32 + (j4 << 2) + j] = pq[j];
            }
        }
        __syncthreads();
        if (t < 32) {           // deterministic 8-warp reduction
            float sx = 0.f, sq2 = 0.f;
#pragma unroll
            for (int w2 = 0; w2 < 8; w2++) {
                sx += wsum[w2 * 32 + t];
                sq2 += wsq[w2 * 32 + t];
            }
            csum[t] = sx;
            csq[t] = sq2;
        }
        __syncthreads();
        float mean[4], rs[4];
#pragma unroll
        for (int j = 0; j < 4; j++) {
            float mu = csum[(j4 << 2) + j] * (1.0f / 256.0f);
            float var = csq[(j4 << 2) + j] * (1.0f / 256.0f) - mu * mu;
            mean[j] = mu;
            rs[j] = rsqrtf(var + 1e-5f);
        }
#pragma unroll
        for (int i = 0; i < 8; i++) {
            float gr = gsm[rg + i];
            float4 o;
            o.x = (acc[i][0] - mean[0]) * rs[0] * gr;
            o.y = (acc[i][1] - mean[1]) * rs[1] * gr;
            o.z = (acc[i][2] - mean[2]) * rs[2] * gr;
            o.w = (acc[i][3] - mean[3]) * rs[3] * gr;
            *(float4*)&out[((size_t)(b * 256 + rg + i)) * NPOS + n0 + (j4 << 2)] = o;
        }
    }
}

// ---------------- launch ----------------
extern "C" void kernel_launch(void* const* d_in, const int* in_sizes, int n_in,
                              void* d_out, int out_size) {
    (void)in_sizes; (void)n_in; (void)out_size;
    const float* x = (const float*)d_in[0];
    const float* cond = (const float*)d_in[1];
    const float* W_qkv = (const float*)d_in[2];
    const float* W_cond = (const float*)d_in[3];
    const float* b_cond = (const float*)d_in[4];
    const float* W_out = (const float*)d_in[5];
    const float* b_out = (const float*)d_in[6];
    const float* g = (const float*)d_in[7];
    float* out = (float*)d_out;

    film_kernel<<<NB, 512>>>(cond, W_cond, b_cond);
    qkv_gemm<<<dim3(32, 3, NB), 256>>>(W_qkv, x);
    kmax_kernel<<<dim3(128, NB), 256>>>();
    ctx_kernel<<<dim3(NCHUNK, 4, NB), 256>>>();
    buildM_kernel<<<NB, 256>>>(W_out);

    int smbytes = SM_TOT * (int)sizeof(float);
    cudaFuncSetAttribute(final_kernel, cudaFuncAttributeMaxDynamicSharedMemorySize, smbytes);
    final_kernel<<<dim3(NCHUNK, NB), 256, smbytes>>>(b_out, g, out);
}

// round 2
// speedup vs baseline: 1.0984x; 1.0984x over previous
#include <cuda_runtime.h>

#define NB 16
#define NPOS 4096
#define SCALE 0.17677669529663687f   // 32^-0.5
#define INVN (1.0f / 4096.0f)
#define NCHUNK 8

// ---------------- scratch (device globals; no runtime allocation) ----------------
__device__ float g_qkv[NB * 384 * NPOS];        // 96 MB: rows 0..127 q(raw), 128..255 k(FiLM), 256..383 v(FiLM,/n)
__device__ float g_film[NB * 512];              // [sk(128), shk(128), sv(128), shv(128)] per batch
__device__ float g_kmax[NB * 128];              // per (b, k-channel) max over n
__device__ float g_Sp[NCHUNK * NB * 4 * 32 * 32]; // partial context numerators per n-chunk
__device__ float g_Zp[NCHUNK * NB * 128];       // partial softmax denominators per n-chunk
__device__ float g_M[NB * 256 * 128];           // M_b = W_out * blockdiag(context)

// ---------------- FiLM: cond -> (sk, shk, sv, shv) ----------------
__global__ void film_kernel(const float* __restrict__ cond,
                            const float* __restrict__ Wc,
                            const float* __restrict__ bc) {
    int b = blockIdx.x, t = threadIdx.x;
    __shared__ float sc[256];
    if (t < 256) {
        float xv = cond[b * 256 + t];
        sc[t] = xv / (1.0f + __expf(-xv));   // silu
    }
    __syncthreads();
    const float* wr = Wc + t * 256;
    float acc = bc[t];
#pragma unroll 8
    for (int j = 0; j < 256; j++) acc += wr[j] * sc[j];
    g_film[b * 512 + t] = acc;
}

// ================= qkv GEMM on tensor cores: 3xTF32 split =================
// C(384x4096) = W_qkv(384x256) @ x_b(256x4096) per batch, FiLM epilogue.
// Block tile 128x128, BK=16, 8 warps in 2x4, warp tile 64x32, mma m16n8k8.
// Split: v = hi + lo, hi = v with low 13 mantissa bits zeroed (exact in tf32).
// C = Ah*Bh + Ah*Bl + Al*Bh  (error ~2^-21, effectively fp32).

__device__ __forceinline__ unsigned f2b(float v) { return __float_as_uint(v); }

__device__ __forceinline__ void mma_tf32(float c[4], const unsigned a[4], const unsigned b[2]) {
    asm volatile(
        "mma.sync.aligned.m16n8k8.row.col.f32.tf32.tf32.f32 "
        "{%0,%1,%2,%3}, {%4,%5,%6,%7}, {%8,%9}, {%0,%1,%2,%3};\n"
        : "+f"(c[0]), "+f"(c[1]), "+f"(c[2]), "+f"(c[3])
        : "r"(a[0]), "r"(a[1]), "r"(a[2]), "r"(a[3]), "r"(b[0]), "r"(b[1]));
}

__device__ __forceinline__ void filmAB(int m, const float* __restrict__ fb,
                                       float& alpha, float& beta) {
    alpha = 1.0f; beta = 0.0f;
    if (m >= 256) {
        int c = m - 256;
        alpha = (1.0f + fb[256 + c]) * INVN;
        beta = fb[384 + c] * INVN;
    } else if (m >= 128) {
        int c = m - 128;
        alpha = 1.0f + fb[c];
        beta = fb[128 + c];
    }
}

#define APAD 20
#define BPAD 132

__global__ void __launch_bounds__(256, 1) qkv_gemm_tc(const float* __restrict__ Wq,
                                                      const float* __restrict__ X) {
    __shared__ float Ah[128][APAD], Al[128][APAD];
    __shared__ float Bhs[16][BPAD], Bls[16][BPAD];

    int b = blockIdx.z;
    int m0 = blockIdx.y * 128, n0 = blockIdx.x * 128;
    int t = threadIdx.x;
    int lane = t & 31, w = t >> 5;
    int wr = w >> 2, wc = w & 3;
    int lq = lane >> 2, lr = lane & 3;   // quad row / k-lane

    float acc[4][4][4];
#pragma unroll
    for (int mt = 0; mt < 4; mt++)
#pragma unroll
        for (int nt = 0; nt < 4; nt++)
#pragma unroll
            for (int r = 0; r < 4; r++) acc[mt][nt][r] = 0.0f;

    // global load mapping: two float4 per thread per tile
    int fA0 = 2 * t, fA1 = 2 * t + 1;
    int arow0 = fA0 >> 2, ac40 = fA0 & 3;
    int arow1 = fA1 >> 2, ac41 = fA1 & 3;
    int brow0 = fA0 >> 5, bc40 = fA0 & 31;
    int brow1 = fA1 >> 5, bc41 = fA1 & 31;
    const float* Ag0 = Wq + (size_t)(m0 + arow0) * 256 + ac40 * 4;
    const float* Ag1 = Wq + (size_t)(m0 + arow1) * 256 + ac41 * 4;
    const float* Bg0 = X + (size_t)b * 256 * NPOS + (size_t)brow0 * NPOS + n0 + bc40 * 4;
    const float* Bg1 = X + (size_t)b * 256 * NPOS + (size_t)brow1 * NPOS + n0 + bc41 * 4;

    float4 ra0, ra1, rb0, rb1;
    ra0 = *(const float4*)(Ag0);
    ra1 = *(const float4*)(Ag1);
    rb0 = *(const float4*)(Bg0);
    rb1 = *(const float4*)(Bg1);

#define SPLIT_STORE(dstH, dstL, row, c4, v)                                    \
    {                                                                          \
        float4 hi, lo;                                                         \
        hi.x = __uint_as_float(f2b(v.x) & 0xFFFFE000u); lo.x = v.x - hi.x;     \
        hi.y = __uint_as_float(f2b(v.y) & 0xFFFFE000u); lo.y = v.y - hi.y;     \
        hi.z = __uint_as_float(f2b(v.z) & 0xFFFFE000u); lo.z = v.z - hi.z;     \
        hi.w = __uint_as_float(f2b(v.w) & 0xFFFFE000u); lo.w = v.w - hi.w;     \
        *(float4*)&dstH[row][(c4) * 4] = hi;                                   \
        *(float4*)&dstL[row][(c4) * 4] = lo;                                   \
    }

    SPLIT_STORE(Ah, Al, arow0, ac40, ra0);
    SPLIT_STORE(Ah, Al, arow1, ac41, ra1);
    SPLIT_STORE(Bhs, Bls, brow0, bc40, rb0);
    SPLIT_STORE(Bhs, Bls, brow1, bc41, rb1);
    __syncthreads();

    for (int kk = 0; kk < 256; kk += 16) {
        if (kk < 240) {
            ra0 = *(const float4*)(Ag0 + kk + 16);
            ra1 = *(const float4*)(Ag1 + kk + 16);
            rb0 = *(const float4*)(Bg0 + (size_t)(kk + 16) * NPOS);
            rb1 = *(const float4*)(Bg1 + (size_t)(kk + 16) * NPOS);
        }
#pragma unroll
        for (int ks = 0; ks < 16; ks += 8) {
            unsigned afh[4][4], afl[4][4], bfh[4][2], bfl[4][2];
#pragma unroll
            for (int mt = 0; mt < 4; mt++) {
                int r0 = wr * 64 + mt * 16 + lq;
                int kq = ks + lr;
                afh[mt][0] = f2b(Ah[r0][kq]);
                afh[mt][1] = f2b(Ah[r0 + 8][kq]);
                afh[mt][2] = f2b(Ah[r0][kq + 4]);
                afh[mt][3] = f2b(Ah[r0 + 8][kq + 4]);
                afl[mt][0] = f2b(Al[r0][kq]);
                afl[mt][1] = f2b(Al[r0 + 8][kq]);
                afl[mt][2] = f2b(Al[r0][kq + 4]);
                afl[mt][3] = f2b(Al[r0 + 8][kq + 4]);
            }
#pragma unroll
            for (int nt = 0; nt < 4; nt++) {
                int cc = wc * 32 + nt * 8 + lq;
                int kq = ks + lr;
                bfh[nt][0] = f2b(Bhs[kq][cc]);
                bfh[nt][1] = f2b(Bhs[kq + 4][cc]);
                bfl[nt][0] = f2b(Bls[kq][cc]);
                bfl[nt][1] = f2b(Bls[kq + 4][cc]);
            }
#pragma unroll
            for (int mt = 0; mt < 4; mt++)
#pragma unroll
                for (int nt = 0; nt < 4; nt++) {
                    mma_tf32(acc[mt][nt], afh[mt], bfh[nt]);
                    mma_tf32(acc[mt][nt], afh[mt], bfl[nt]);
                    mma_tf32(acc[mt][nt], afl[mt], bfh[nt]);
                }
        }
        __syncthreads();
        if (kk < 240) {
            SPLIT_STORE(Ah, Al, arow0, ac40, ra0);
            SPLIT_STORE(Ah, Al, arow1, ac41, ra1);
            SPLIT_STORE(Bhs, Bls, brow0, bc40, rb0);
            SPLIT_STORE(Bhs, Bls, brow1, bc41, rb1);
            __syncthreads();
        }
    }

    // FiLM epilogue + store
    const float* fb = g_film + b * 512;
    float* C = g_qkv + (size_t)b * 384 * NPOS;
#pragma unroll
    for (int mt = 0; mt < 4; mt++) {
        int mA = m0 + wr * 64 + mt * 16 + lq;
        int mB = mA + 8;
        float aA, bA, aB, bB;
        filmAB(mA, fb, aA, bA);
        filmAB(mB, fb, aB, bB);
#pragma unroll
        for (int nt = 0; nt < 4; nt++) {
            int cc = n0 + wc * 32 + nt * 8 + 2 * lr;
            float2 o0, o1;
            o0.x = fmaf(aA, acc[mt][nt][0], bA);
            o0.y = fmaf(aA, acc[mt][nt][1], bA);
            o1.x = fmaf(aB, acc[mt][nt][2], bB);
            o1.y = fmaf(aB, acc[mt][nt][3], bB);
            *(float2*)&C[(size_t)mA * NPOS + cc] = o0;
            *(float2*)&C[(size_t)mB * NPOS + cc] = o1;
        }
    }
}

// ---------------- per (b, k-channel) max over n ----------------
__global__ void kmax_kernel() {
    int b = blockIdx.y, c = blockIdx.x, t = threadIdx.x;
    const float* row = g_qkv + ((size_t)b * 384 + 128 + c) * NPOS;
    float m = -1e30f;
    for (int i = t; i < NPOS; i += 256) m = fmaxf(m, row[i]);
    __shared__ float red[8];
#pragma unroll
    for (int o = 16; o; o >>= 1) m = fmaxf(m, __shfl_xor_sync(0xffffffffu, m, o));
    if ((t & 31) == 0) red[t >> 5] = m;
    __syncthreads();
    if (t < 8) {
        m = red[t];
#pragma unroll
        for (int o = 4; o; o >>= 1) m = fmaxf(m, __shfl_xor_sync(0xffu, m, o));
        if (t == 0) g_kmax[b * 128 + c] = m;
    }
}

// ---------------- context partials: S[c][e] = sum_n exp(k[c][n]-m[c]) * v[e][n] ----------------
__global__ void __launch_bounds__(256) ctx_kernel() {
    int b = blockIdx.z, h = blockIdx.y, chunk = blockIdx.x;
    int nbase = chunk * 512;
    int t = threadIdx.x;
    __shared__ float Et[32][65];
    __shared__ float Vt[32][65];
    int c = t & 31, e4 = t >> 5;
    int rF = t >> 3, cF = (t & 7) << 3;
    const float* Kb = g_qkv + ((size_t)b * 384 + 128 + h * 32 + rF) * NPOS + nbase + cF;
    const float* Vb = g_qkv + ((size_t)b * 384 + 256 + h * 32 + rF) * NPOS + nbase + cF;
    float km = g_kmax[b * 128 + h * 32 + rF];

    float a0 = 0.f, a1 = 0.f, a2 = 0.f, a3 = 0.f, z = 0.f;
    for (int sub = 0; sub < 8; sub++) {
        float4 k0 = *(const float4*)(Kb + sub * 64);
        float4 k1 = *(const float4*)(Kb + sub * 64 + 4);
        float4 v0 = *(const float4*)(Vb + sub * 64);
        float4 v1 = *(const float4*)(Vb + sub * 64 + 4);
        __syncthreads();
        Et[rF][cF + 0] = __expf(k0.x - km);
        Et[rF][cF + 1] = __expf(k0.y - km);
        Et[rF][cF + 2] = __expf(k0.z - km);
        Et[rF][cF + 3] = __expf(k0.w - km);
        Et[rF][cF + 4] = __expf(k1.x - km);
        Et[rF][cF + 5] = __expf(k1.y - km);
        Et[rF][cF + 6] = __expf(k1.z - km);
        Et[rF][cF + 7] = __expf(k1.w - km);
        Vt[rF][cF + 0] = v0.x; Vt[rF][cF + 1] = v0.y;
        Vt[rF][cF + 2] = v0.z; Vt[rF][cF + 3] = v0.w;
        Vt[rF][cF + 4] = v1.x; Vt[rF][cF + 5] = v1.y;
        Vt[rF][cF + 6] = v1.z; Vt[rF][cF + 7] = v1.w;
        __syncthreads();
#pragma unroll 16
        for (int n = 0; n < 64; n++) {
            float ec = Et[c][n];
            if (e4 == 0) z += ec;
            a0 += ec * Vt[(e4 << 2) + 0][n];
            a1 += ec * Vt[(e4 << 2) + 1][n];
            a2 += ec * Vt[(e4 << 2) + 2][n];
            a3 += ec * Vt[(e4 << 2) + 3][n];
        }
    }
    float* Sp = g_Sp + ((((size_t)chunk * NB + b) * 4 + h) * 32 + c) * 32 + (e4 << 2);
    Sp[0] = a0; Sp[1] = a1; Sp[2] = a2; Sp[3] = a3;
    if (e4 == 0) g_Zp[((size_t)chunk * NB + b) * 128 + h * 32 + c] = z;
}

// ---------------- build M_b = W_out * blockdiag(context_b) ----------------
__global__ void buildM_kernel(const float* __restrict__ Wout) {
    int b = blockIdx.x, t = threadIdx.x;
    __shared__ float ctxs[4096];
    __shared__ float zsm[128];
    if (t < 128) {
        float zz = 0.f;
#pragma unroll
        for (int ch = 0; ch < NCHUNK; ch++) zz += g_Zp[((size_t)ch * NB + b) * 128 + t];
        zsm[t] = zz;
    }
    __syncthreads();
    for (int i = t; i < 4096; i += 256) {
        int h = i >> 10, c = (i >> 5) & 31;
        float s = 0.f;
#pragma unroll
        for (int ch = 0; ch < NCHUNK; ch++) s += g_Sp[((size_t)ch * NB + b) * 4096 + i];
        ctxs[i] = s / zsm[h * 32 + c];
    }
    __syncthreads();
    const float* wr = Wout + t * 128;
    float* Mr = g_M + (size_t)b * 32768 + t * 128;
    for (int h = 0; h < 4; h++) {
        float w[32];
#pragma unroll
        for (int e = 0; e < 32; e++) w[e] = wr[h * 32 + e];
        for (int c2 = 0; c2 < 32; c2++) {
            float s = 0.f;
#pragma unroll
            for (int e = 0; e < 32; e++) s += w[e] * ctxs[h * 1024 + c2 * 32 + e];
            Mr[h * 32 + c2] = s;
        }
    }
}

// ---------------- final: y = M_b @ softmax_c(q)*scale + b_out, then LayerNorm*g ----------------
#define SM_MS   (256 * 129)
#define SM_QS   (128 * 36)
#define SM_TOT  (SM_MS + SM_QS + 256 + 256 + 32 + 32 + 256 + 256)

__global__ void __launch_bounds__(256) final_kernel(const float* __restrict__ bout,
                                                    const float* __restrict__ gam,
                                                    float* __restrict__ out) {
    extern __shared__ float sm[];
    float* Msm = sm;
    float* qs = sm + SM_MS;
    float* bsm = qs + SM_QS;
    float* gsm = bsm + 256;
    float* csum = gsm + 256;
    float* csq = csum + 32;
    float* wsum = csq + 32;
    float* wsq = wsum + 256;

    int b = blockIdx.y, chunk = blockIdx.x, t = threadIdx.x;
    for (int i = t; i < 32768; i += 256)
        Msm[(i >> 7) * 129 + (i & 127)] = g_M[(size_t)b * 32768 + i];
    bsm[t] = bout[t];
    gsm[t] = gam[t];
    const float* Q = g_qkv + (size_t)b * 384 * NPOS;
    int j4 = t & 7, rg = (t >> 3) << 3;
    int w = t >> 5;

    for (int s = 0; s < 16; s++) {
        int n0 = chunk * 512 + s * 32;
        __syncthreads();
        for (int i = t; i < 4096; i += 256)
            qs[(i >> 5) * 36 + (i & 31)] = Q[(size_t)(i >> 5) * NPOS + n0 + (i & 31)];
        __syncthreads();
        if (t < 128) {
            float* col = qs + (t >> 5) * 32 * 36 + (t & 31);
            float mx = col[0];
#pragma unroll
            for (int cI = 1; cI < 32; cI++) mx = fmaxf(mx, col[cI * 36]);
            float ssum = 0.f;
#pragma unroll
            for (int cI = 0; cI < 32; cI++) {
                float e = __expf(col[cI * 36] - mx);
                ssum += e;
                col[cI * 36] = e;
            }
            float inv = SCALE / ssum;
#pragma unroll
            for (int cI = 0; cI < 32; cI++) col[cI * 36] *= inv;
        }
        __syncthreads();
        float acc[8][4];
#pragma unroll
        for (int i = 0; i < 8; i++)
#pragma unroll
            for (int j = 0; j < 4; j++) acc[i][j] = 0.0f;
#pragma unroll 8
        for (int kk = 0; kk < 128; kk++) {
            float4 qv = *(const float4*)&qs[kk * 36 + (j4 << 2)];
#pragma unroll
            for (int i = 0; i < 8; i++) {
                float mv = Msm[(rg + i) * 129 + kk];
                acc[i][0] += mv * qv.x;
                acc[i][1] += mv * qv.y;
                acc[i][2] += mv * qv.z;
                acc[i][3] += mv * qv.w;
            }
        }
        float ps[4] = {0.f, 0.f, 0.f, 0.f}, pq[4] = {0.f, 0.f, 0.f, 0.f};
#pragma unroll
        for (int i = 0; i < 8; i++) {
            float bo = bsm[rg + i];
#pragma unroll
            for (int j = 0; j < 4; j++) {
                float v = acc[i][j] + bo;
                acc[i][j] = v;
                ps[j] += v;
                pq[j] += v * v;
            }
        }
#pragma unroll
        for (int j = 0; j < 4; j++) {
            ps[j] += __shfl_xor_sync(0xffffffffu, ps[j], 8);
            ps[j] += __shfl_xor_sync(0xffffffffu, ps[j], 16);
            pq[j] += __shfl_xor_sync(0xffffffffu, pq[j], 8);
            pq[j] += __shfl_xor_sync(0xffffffffu, pq[j], 16);
        }
        if ((t & 24) == 0) {
#pragma unroll
            for (int j = 0; j < 4; j++) {
                wsum[w * 32 + (j4 << 2) + j] = ps[j];
                wsq[w * 32 + (j4 << 2) + j] = pq[j];
            }
        }
        __syncthreads();
        if (t < 32) {
            float sx = 0.f, sq2 = 0.f;
#pragma unroll
            for (int w2 = 0; w2 < 8; w2++) {
                sx += wsum[w2 * 32 + t];
                sq2 += wsq[w2 * 32 + t];
            }
            csum[t] = sx;
            csq[t] = sq2;
        }
        __syncthreads();
        float mean[4], rs[4];
#pragma unroll
        for (int j = 0; j < 4; j++) {
            float mu = csum[(j4 << 2) + j] * (1.0f / 256.0f);
            float var = csq[(j4 << 2) + j] * (1.0f / 256.0f) - mu * mu;
            mean[j] = mu;
            rs[j] = rsqrtf(var + 1e-5f);
        }
#pragma unroll
        for (int i = 0; i < 8; i++) {
            float gr = gsm[rg + i];
            float4 o;
            o.x = (acc[i][0] - mean[0]) * rs[0] * gr;
            o.y = (acc[i][1] - mean[1]) * rs[1] * gr;
            o.z = (acc[i][2] - mean[2]) * rs[2] * gr;
            o.w = (acc[i][3] - mean[3]) * rs[3] * gr;
            *(float4*)&out[((size_t)(b * 256 + rg + i)) * NPOS + n0 + (j4 << 2)] = o;
        }
    }
}

// ---------------- launch ----------------
extern "C" void kernel_launch(void* const* d_in, const int* in_sizes, int n_in,
                              void* d_out, int out_size) {
    (void)in_sizes; (void)n_in; (void)out_size;
    const float* x = (const float*)d_in[0];
    const float* cond = (const float*)d_in[1];
    const float* W_qkv = (const float*)d_in[2];
    const float* W_cond = (const float*)d_in[3];
    const float* b_cond = (const float*)d_in[4];
    const float* W_out = (const float*)d_in[5];
    const float* b_out = (const float*)d_in[6];
    const float* g = (const float*)d_in[7];
    float* out = (float*)d_out;

    film_kernel<<<NB, 512>>>(cond, W_cond, b_cond);
    qkv_gemm_tc<<<dim3(32, 3, NB), 256>>>(W_qkv, x);
    kmax_kernel<<<dim3(128, NB), 256>>>();
    ctx_kernel<<<dim3(NCHUNK, 4, NB), 256>>>();
    buildM_kernel<<<NB, 256>>>(W_out);

    int smbytes = SM_TOT * (int)sizeof(float);
    cudaFuncSetAttribute(final_kernel, cudaFuncAttributeMaxDynamicSharedMemorySize, smbytes);
    final_kernel<<<dim3(NCHUNK, NB), 256, smbytes>>>(b_out, g, out);
}

// round 4
// speedup vs baseline: 1.6414x; 1.4944x over previous
#include <cuda_runtime.h>
#include <cuda_bf16.h>
#include <cstdint>

#define NB 16
#define NPOS 4096
#define SCALE 0.17677669529663687f   // 32^-0.5
#define INVN (1.0f / 4096.0f)
#define NCHUNK 8
#define NCHUNK_F 16

// ---------------- scratch (device globals; no runtime allocation) ----------------
__device__ float g_qkv[NB * 384 * NPOS];          // q(raw) / k(FiLM) / v(FiLM,/n) fp32
__device__ float g_film[NB * 512];
__device__ float g_kmax[NB * 128];
__device__ float g_Sp[NCHUNK * NB * 4 * 32 * 32];
__device__ float g_Zp[NCHUNK * NB * 128];
__device__ float g_M[NB * 256 * 128];
__device__ __nv_bfloat16 g_xt[(size_t)NB * NPOS * 256];  // X transposed: [b][n][k], k contiguous
__device__ __nv_bfloat16 g_wt[384 * 256];                // W_qkv bf16, k contiguous

// ---------------- FiLM ----------------
__global__ void film_kernel(const float* __restrict__ cond,
                            const float* __restrict__ Wc,
                            const float* __restrict__ bc) {
    int b = blockIdx.x, t = threadIdx.x;
    __shared__ float sc[256];
    if (t < 256) {
        float xv = cond[b * 256 + t];
        sc[t] = xv / (1.0f + __expf(-xv));
    }
    __syncthreads();
    const float* wr = Wc + t * 256;
    float acc = bc[t];
#pragma unroll 8
    for (int j = 0; j < 256; j++) acc += wr[j] * sc[j];
    g_film[b * 512 + t] = acc;
}

// ---------------- converts ----------------
__global__ void wconv_kernel(const float* __restrict__ W) {
    int i = blockIdx.x * 1024 + threadIdx.x;
    if (i < 384 * 256) g_wt[i] = __float2bfloat16(W[i]);
}

// X [b][256 k][4096 n] fp32 -> g_xt [b][4096 n][256 k] bf16 (32x32 tiles)
__global__ void xpose_kernel(const float* __restrict__ X) {
    __shared__ float s[32][33];
    int b = blockIdx.z, k0 = blockIdx.y * 32, n0 = blockIdx.x * 32;
    int tx = threadIdx.x, ty = threadIdx.y;
    const float* src = X + ((size_t)b * 256 + k0) * NPOS + n0;
#pragma unroll
    for (int i = 0; i < 4; i++)
        s[ty + 8 * i][tx] = src[(size_t)(ty + 8 * i) * NPOS + tx];
    __syncthreads();
    __nv_bfloat16* dst = g_xt + ((size_t)b * NPOS + n0) * 256 + k0;
#pragma unroll
    for (int i = 0; i < 4; i++)
        dst[(size_t)(ty + 8 * i) * 256 + tx] = __float2bfloat16(s[tx][ty + 8 * i]);
}

// ================= qkv GEMM: bf16 mma.sync m16n8k16 =================
// C[grp*128+m][n] = sum_k W[.][k] * X[b][k][n], FiLM epilogue -> g_qkv fp32.
// Block 128x128x32, 8 warps (2x4), warp 64x32. A=[m][k] bf16, B=[n][k] bf16.
#define KW 20   // smem row stride in 32-bit words (16 data + 4 pad)

__device__ __forceinline__ void mma_bf16(float c[4], const uint32_t a[4], const uint32_t b[2]) {
    asm volatile(
        "mma.sync.aligned.m16n8k16.row.col.f32.bf16.bf16.f32 "
        "{%0,%1,%2,%3}, {%4,%5,%6,%7}, {%8,%9}, {%0,%1,%2,%3};\n"
        : "+f"(c[0]), "+f"(c[1]), "+f"(c[2]), "+f"(c[3])
        : "r"(a[0]), "r"(a[1]), "r"(a[2]), "r"(a[3]), "r"(b[0]), "r"(b[1]));
}

__device__ __forceinline__ void filmAB(int m, const float* __restrict__ fb,
                                       float& alpha, float& beta) {
    alpha = 1.0f; beta = 0.0f;
    if (m >= 256) {
        int c = m - 256;
        alpha = (1.0f + fb[256 + c]) * INVN;
        beta = fb[384 + c] * INVN;
    } else if (m >= 128) {
        int c = m - 128;
        alpha = 1.0f + fb[c];
        beta = fb[128 + c];
    }
}

__global__ void __launch_bounds__(256, 1) qkv_mma(void) {
    __shared__ uint32_t As[2][128 * KW];
    __shared__ uint32_t Bs[2][128 * KW];

    int b = blockIdx.z, grp = blockIdx.y;
    int m0 = grp * 128, n0 = blockIdx.x * 128;
    int t = threadIdx.x, lane = t & 31, w = t >> 5;
    int wr = w >> 2, wc = w & 3;
    int lq = lane >> 2, lr = lane & 3;

    float acc[4][4][4];
#pragma unroll
    for (int mt = 0; mt < 4; mt++)
#pragma unroll
        for (int nt = 0; nt < 4; nt++)
#pragma unroll
            for (int r = 0; r < 4; r++) acc[mt][nt][r] = 0.0f;

    // global->smem mapping: 2 uint4 (8 bf16) per thread per operand per stage
    int f0 = 2 * t, f1 = 2 * t + 1;
    int ar0 = f0 >> 2, ak0 = f0 & 3;
    int ar1 = f1 >> 2, ak1 = f1 & 3;
    const __nv_bfloat16* Awg = g_wt + (size_t)(m0 + ar0) * 256 + ak0 * 8;
    const __nv_bfloat16* Awg1 = g_wt + (size_t)(m0 + ar1) * 256 + ak1 * 8;
    const __nv_bfloat16* Bxg = g_xt + ((size_t)b * NPOS + n0 + ar0) * 256 + ak0 * 8;
    const __nv_bfloat16* Bxg1 = g_xt + ((size_t)b * NPOS + n0 + ar1) * 256 + ak1 * 8;

    uint4 ra0 = *(const uint4*)(Awg);
    uint4 ra1 = *(const uint4*)(Awg1);
    uint4 rb0 = *(const uint4*)(Bxg);
    uint4 rb1 = *(const uint4*)(Bxg1);
    *(uint4*)&As[0][ar0 * KW + ak0 * 4] = ra0;
    *(uint4*)&As[0][ar1 * KW + ak1 * 4] = ra1;
    *(uint4*)&Bs[0][ar0 * KW + ak0 * 4] = rb0;
    *(uint4*)&Bs[0][ar1 * KW + ak1 * 4] = rb1;
    __syncthreads();

    for (int kk = 0; kk < 8; kk++) {
        int cur = kk & 1;
        if (kk < 7) {
            int ko = (kk + 1) * 16;   // bf16 elements: 32 per stage, base offset in elems
            ra0 = *(const uint4*)(Awg + ko * 2);
            ra1 = *(const uint4*)(Awg1 + ko * 2);
            rb0 = *(const uint4*)(Bxg + ko * 2);
            rb1 = *(const uint4*)(Bxg1 + ko * 2);
        }
#pragma unroll
        for (int ks = 0; ks < 2; ks++) {
            int ksw = ks * 8;
            uint32_t af[4][4], bf[4][2];
#pragma unroll
            for (int mt = 0; mt < 4; mt++) {
                int r0 = wr * 64 + mt * 16 + lq;
                af[mt][0] = As[cur][r0 * KW + ksw + lr];
                af[mt][1] = As[cur][(r0 + 8) * KW + ksw + lr];
                af[mt][2] = As[cur][r0 * KW + ksw + lr + 4];
                af[mt][3] = As[cur][(r0 + 8) * KW + ksw + lr + 4];
            }
#pragma unroll
            for (int nt = 0; nt < 4; nt++) {
                int n = wc * 32 + nt * 8 + lq;
                bf[nt][0] = Bs[cur][n * KW + ksw + lr];
                bf[nt][1] = Bs[cur][n * KW + ksw + lr + 4];
            }
#pragma unroll
            for (int mt = 0; mt < 4; mt++)
#pragma unroll
                for (int nt = 0; nt < 4; nt++) mma_bf16(acc[mt][nt], af[mt], bf[nt]);
        }
        if (kk < 7) {
            int nxt = 1 - cur;
            *(uint4*)&As[nxt][ar0 * KW + ak0 * 4] = ra0;
            *(uint4*)&As[nxt][ar1 * KW + ak1 * 4] = ra1;
            *(uint4*)&Bs[nxt][ar0 * KW + ak0 * 4] = rb0;
            *(uint4*)&Bs[nxt][ar1 * KW + ak1 * 4] = rb1;
            __syncthreads();
        }
    }

    // FiLM epilogue -> g_qkv fp32
    const float* fb = g_film + b * 512;
    float* C = g_qkv + (size_t)b * 384 * NPOS;
#pragma unroll
    for (int mt = 0; mt < 4; mt++) {
        int mA = m0 + wr * 64 + mt * 16 + lq;
        int mB = mA + 8;
        float aA, bA, aB, bB;
        filmAB(mA, fb, aA, bA);
        filmAB(mB, fb, aB, bB);
#pragma unroll
        for (int nt = 0; nt < 4; nt++) {
            int cc = n0 + wc * 32 + nt * 8 + 2 * lr;
            float2 o0, o1;
            o0.x = fmaf(aA, acc[mt][nt][0], bA);
            o0.y = fmaf(aA, acc[mt][nt][1], bA);
            o1.x = fmaf(aB, acc[mt][nt][2], bB);
            o1.y = fmaf(aB, acc[mt][nt][3], bB);
            *(float2*)&C[(size_t)mA * NPOS + cc] = o0;
            *(float2*)&C[(size_t)mB * NPOS + cc] = o1;
        }
    }
}

// ---------------- per (b, k-channel) max over n ----------------
__global__ void kmax_kernel() {
    int b = blockIdx.y, c = blockIdx.x, t = threadIdx.x;
    const float* row = g_qkv + ((size_t)b * 384 + 128 + c) * NPOS;
    float m = -1e30f;
    for (int i = t; i < NPOS; i += 256) m = fmaxf(m, row[i]);
    __shared__ float red[8];
#pragma unroll
    for (int o = 16; o; o >>= 1) m = fmaxf(m, __shfl_xor_sync(0xffffffffu, m, o));
    if ((t & 31) == 0) red[t >> 5] = m;
    __syncthreads();
    if (t < 8) {
        m = red[t];
#pragma unroll
        for (int o = 4; o; o >>= 1) m = fmaxf(m, __shfl_xor_sync(0xffu, m, o));
        if (t == 0) g_kmax[b * 128 + c] = m;
    }
}

// ---------------- context partials ----------------
__global__ void __launch_bounds__(256) ctx_kernel() {
    int b = blockIdx.z, h = blockIdx.y, chunk = blockIdx.x;
    int nbase = chunk * 512;
    int t = threadIdx.x;
    __shared__ float Et[32][65];
    __shared__ float Vt[32][65];
    int c = t & 31, e4 = t >> 5;
    int rF = t >> 3, cF = (t & 7) << 3;
    const float* Kb = g_qkv + ((size_t)b * 384 + 128 + h * 32 + rF) * NPOS + nbase + cF;
    const float* Vb = g_qkv + ((size_t)b * 384 + 256 + h * 32 + rF) * NPOS + nbase + cF;
    float km = g_kmax[b * 128 + h * 32 + rF];

    float a0 = 0.f, a1 = 0.f, a2 = 0.f, a3 = 0.f, z = 0.f;
    for (int sub = 0; sub < 8; sub++) {
        float4 k0 = *(const float4*)(Kb + sub * 64);
        float4 k1 = *(const float4*)(Kb + sub * 64 + 4);
        float4 v0 = *(const float4*)(Vb + sub * 64);
        float4 v1 = *(const float4*)(Vb + sub * 64 + 4);
        __syncthreads();
        Et[rF][cF + 0] = __expf(k0.x - km);
        Et[rF][cF + 1] = __expf(k0.y - km);
        Et[rF][cF + 2] = __expf(k0.z - km);
        Et[rF][cF + 3] = __expf(k0.w - km);
        Et[rF][cF + 4] = __expf(k1.x - km);
        Et[rF][cF + 5] = __expf(k1.y - km);
        Et[rF][cF + 6] = __expf(k1.z - km);
        Et[rF][cF + 7] = __expf(k1.w - km);
        Vt[rF][cF + 0] = v0.x; Vt[rF][cF + 1] = v0.y;
        Vt[rF][cF + 2] = v0.z; Vt[rF][cF + 3] = v0.w;
        Vt[rF][cF + 4] = v1.x; Vt[rF][cF + 5] = v1.y;
        Vt[rF][cF + 6] = v1.z; Vt[rF][cF + 7] = v1.w;
        __syncthreads();
#pragma unroll 16
        for (int n = 0; n < 64; n++) {
            float ec = Et[c][n];
            if (e4 == 0) z += ec;
            a0 += ec * Vt[(e4 << 2) + 0][n];
            a1 += ec * Vt[(e4 << 2) + 1][n];
            a2 += ec * Vt[(e4 << 2) + 2][n];
            a3 += ec * Vt[(e4 << 2) + 3][n];
        }
    }
    float* Sp = g_Sp + ((((size_t)chunk * NB + b) * 4 + h) * 32 + c) * 32 + (e4 << 2);
    Sp[0] = a0; Sp[1] = a1; Sp[2] = a2; Sp[3] = a3;
    if (e4 == 0) g_Zp[((size_t)chunk * NB + b) * 128 + h * 32 + c] = z;
}

// ---------------- build M_b ----------------
__global__ void buildM_kernel(const float* __restrict__ Wout) {
    int b = blockIdx.x, t = threadIdx.x;
    __shared__ float ctxs[4096];
    __shared__ float zsm[128];
    if (t < 128) {
        float zz = 0.f;
#pragma unroll
        for (int ch = 0; ch < NCHUNK; ch++) zz += g_Zp[((size_t)ch * NB + b) * 128 + t];
        zsm[t] = zz;
    }
    __syncthreads();
    for (int i = t; i < 4096; i += 256) {
        int h = i >> 10, c = (i >> 5) & 31;
        float s = 0.f;
#pragma unroll
        for (int ch = 0; ch < NCHUNK; ch++) s += g_Sp[((size_t)ch * NB + b) * 4096 + i];
        ctxs[i] = s / zsm[h * 32 + c];
    }
    __syncthreads();
    const float* wr = Wout + t * 128;
    float* Mr = g_M + (size_t)b * 32768 + t * 128;
    for (int h = 0; h < 4; h++) {
        float w[32];
#pragma unroll
        for (int e = 0; e < 32; e++) w[e] = wr[h * 32 + e];
        for (int c2 = 0; c2 < 32; c2++) {
            float s = 0.f;
#pragma unroll
            for (int e = 0; e < 32; e++) s += w[e] * ctxs[h * 1024 + c2 * 32 + e];
            Mr[h * 32 + c2] = s;
        }
    }
}

// ---------------- final: HFMA2 bf16 GEMM + bias + LN ----------------
// smem word layout (floats/uints): Mp[256*66] qs[128*36] qp[64*32] bsm gsm csum csq wsum wsq
#define OFF_QS 16896
#define OFF_QP 21504
#define OFF_B  23552
#define OFF_G  23808
#define OFF_CS 24064
#define OFF_CQ 24096
#define OFF_WS 24128
#define OFF_WQ 24384
#define F_TOT  24640

__global__ void __launch_bounds__(256) final_kernel(const float* __restrict__ bout,
                                                    const float* __restrict__ gam,
                                                    float* __restrict__ out) {
    extern __shared__ float sm[];
    uint32_t* Mp = (uint32_t*)sm;
    float* qs = sm + OFF_QS;
    uint32_t* qp = (uint32_t*)(sm + OFF_QP);
    float* bsm = sm + OFF_B;
    float* gsm = sm + OFF_G;
    float* csum = sm + OFF_CS;
    float* csq = sm + OFF_CQ;
    float* wsum = sm + OFF_WS;
    float* wsq = sm + OFF_WQ;

    int b = blockIdx.y, chunk = blockIdx.x, t = threadIdx.x;
    // pack M -> bf16x2 [row][k2], stride 66
    for (int i = t; i < 256 * 64; i += 256) {
        int row = i >> 6, k2 = i & 63;
        float2 mv = *(const float2*)&g_M[(size_t)b * 32768 + row * 128 + 2 * k2];
        __nv_bfloat162 p = __floats2bfloat162_rn(mv.x, mv.y);
        Mp[row * 66 + k2] = *(uint32_t*)&p;
    }
    bsm[t] = bout[t];
    gsm[t] = gam[t];
    const float* Q = g_qkv + (size_t)b * 384 * NPOS;
    int j4 = t & 7, rg = (t >> 3) << 3;
    int w = t >> 5;

    for (int s = 0; s < 8; s++) {
        int n0 = chunk * 256 + s * 32;
        __syncthreads();
        for (int i = t; i < 4096; i += 256)
            qs[(i >> 5) * 36 + (i & 31)] = Q[(size_t)(i >> 5) * NPOS + n0 + (i & 31)];
        __syncthreads();
        if (t < 128) {
            float* col = qs + (t >> 5) * 32 * 36 + (t & 31);
            float mx = col[0];
#pragma unroll
            for (int cI = 1; cI < 32; cI++) mx = fmaxf(mx, col[cI * 36]);
            float ssum = 0.f;
#pragma unroll
            for (int cI = 0; cI < 32; cI++) {
                float e = __expf(col[cI * 36] - mx);
                ssum += e;
                col[cI * 36] = e;
            }
            float inv = SCALE / ssum;
#pragma unroll
            for (int cI = 0; cI < 32; cI++) col[cI * 36] *= inv;
        }
        __syncthreads();
        // pack qs -> bf16x2 along k
        for (int i = t; i < 2048; i += 256) {
            int k2 = i >> 5, col = i & 31;
            __nv_bfloat162 p = __floats2bfloat162_rn(qs[(2 * k2) * 36 + col],
                                                     qs[(2 * k2 + 1) * 36 + col]);
            qp[k2 * 32 + col] = *(uint32_t*)&p;
        }
        __syncthreads();
        // GEMM: 256x32 tile via HFMA2
        __nv_bfloat162 acc2[8][4];
        __nv_bfloat162 zz = __floats2bfloat162_rn(0.f, 0.f);
#pragma unroll
        for (int i = 0; i < 8; i++)
#pragma unroll
            for (int j = 0; j < 4; j++) acc2[i][j] = zz;
#pragma unroll 4
        for (int k2 = 0; k2 < 64; k2++) {
            uint4 qv4 = *(const uint4*)&qp[k2 * 32 + (j4 << 2)];
            __nv_bfloat162 q0 = *(__nv_bfloat162*)&qv4.x;
            __nv_bfloat162 q1 = *(__nv_bfloat162*)&qv4.y;
            __nv_bfloat162 q2 = *(__nv_bfloat162*)&qv4.z;
            __nv_bfloat162 q3 = *(__nv_bfloat162*)&qv4.w;
#pragma unroll
            for (int i = 0; i < 8; i++) {
                uint32_t mw = Mp[(rg + i) * 66 + k2];
                __nv_bfloat162 mv = *(__nv_bfloat162*)&mw;
                acc2[i][0] = __hfma2(mv, q0, acc2[i][0]);
                acc2[i][1] = __hfma2(mv, q1, acc2[i][1]);
                acc2[i][2] = __hfma2(mv, q2, acc2[i][2]);
                acc2[i][3] = __hfma2(mv, q3, acc2[i][3]);
            }
        }
        float accf[8][4];
        float ps[4] = {0.f, 0.f, 0.f, 0.f}, pq[4] = {0.f, 0.f, 0.f, 0.f};
#pragma unroll
        for (int i = 0; i < 8; i++) {
            float bo = bsm[rg + i];
#pragma unroll
            for (int j = 0; j < 4; j++) {
                float v = __low2float(acc2[i][j]) + __high2float(acc2[i][j]) + bo;
                accf[i][j] = v;
                ps[j] += v;
                pq[j] += v * v;
            }
        }
#pragma unroll
        for (int j = 0; j < 4; j++) {
            ps[j] += __shfl_xor_sync(0xffffffffu, ps[j], 8);
            ps[j] += __shfl_xor_sync(0xffffffffu, ps[j], 16);
            pq[j] += __shfl_xor_sync(0xffffffffu, pq[j], 8);
            pq[j] += __shfl_xor_sync(0xffffffffu, pq[j], 16);
        }
        if ((t & 24) == 0) {
#pragma unroll
            for (int j = 0; j < 4; j++) {
                wsum[w * 32 + (j4 << 2) + j] = ps[j];
                wsq[w * 32 + (j4 << 2) + j] = pq[j];
            }
        }
        __syncthreads();
        if (t < 32) {
            float sx = 0.f, sq2 = 0.f;
#pragma unroll
            for (int w2 = 0; w2 < 8; w2++) {
                sx += wsum[w2 * 32 + t];
                sq2 += wsq[w2 * 32 + t];
            }
            csum[t] = sx;
            csq[t] = sq2;
        }
        __syncthreads();
        float mean[4], rs[4];
#pragma unroll
        for (int j = 0; j < 4; j++) {
            float mu = csum[(j4 << 2) + j] * (1.0f / 256.0f);
            float var = csq[(j4 << 2) + j] * (1.0f / 256.0f) - mu * mu;
            mean[j] = mu;
            rs[j] = rsqrtf(var + 1e-5f);
        }
#pragma unroll
        for (int i = 0; i < 8; i++) {
            float gr = gsm[rg + i];
            float4 o;
            o.x = (accf[i][0] - mean[0]) * rs[0] * gr;
            o.y = (accf[i][1] - mean[1]) * rs[1] * gr;
            o.z = (accf[i][2] - mean[2]) * rs[2] * gr;
            o.w = (accf[i][3] - mean[3]) * rs[3] * gr;
            *(float4*)&out[((size_t)(b * 256 + rg + i)) * NPOS + n0 + (j4 << 2)] = o;
        }
    }
}

// ---------------- launch ----------------
extern "C" void kernel_launch(void* const* d_in, const int* in_sizes, int n_in,
                              void* d_out, int out_size) {
    (void)in_sizes; (void)n_in; (void)out_size;
    const float* x = (const float*)d_in[0];
    const float* cond = (const float*)d_in[1];
    const float* W_qkv = (const float*)d_in[2];
    const float* W_cond = (const float*)d_in[3];
    const float* b_cond = (const float*)d_in[4];
    const float* W_out = (const float*)d_in[5];
    const float* b_out = (const float*)d_in[6];
    const float* g = (const float*)d_in[7];
    float* out = (float*)d_out;

    film_kernel<<<NB, 512>>>(cond, W_cond, b_cond);
    wconv_kernel<<<96, 1024>>>(W_qkv);
    xpose_kernel<<<dim3(128, 8, NB), dim3(32, 8)>>>(x);
    qkv_mma<<<dim3(32, 3, NB), 256>>>();
    kmax_kernel<<<dim3(128, NB), 256>>>();
    ctx_kernel<<<dim3(NCHUNK, 4, NB), 256>>>();
    buildM_kernel<<<NB, 256>>>(W_out);

    int smbytes = F_TOT * (int)sizeof(float);
    cudaFuncSetAttribute(final_kernel, cudaFuncAttributeMaxDynamicSharedMemorySize, smbytes);
    final_kernel<<<dim3(NCHUNK_F, NB), 256, smbytes>>>(b_out, g, out);
}

// round 5
// speedup vs baseline: 1.9334x; 1.1779x over previous
#include <cuda_runtime.h>
#include <cuda_bf16.h>
#include <cstdint>

#define NB 16
#define NPOS 4096
#define SCALE 0.17677669529663687f   // 32^-0.5
#define INVN (1.0f / 4096.0f)
#define NCHUNK 8

// ---------------- scratch (device globals; no runtime allocation) ----------------
__device__ float g_qkv[NB * 384 * NPOS];          // q(raw) / k(FiLM) / v(FiLM,/n) fp32
__device__ float g_film[NB * 512];
__device__ float g_kmax[NB * 128];
__device__ float g_Sp[NCHUNK * NB * 4 * 32 * 32];
__device__ float g_Zp[NCHUNK * NB * 128];
__device__ __nv_bfloat16 g_Mb[NB * 256 * 128];           // M_b bf16, k contiguous
__device__ __nv_bfloat16 g_qsm[(size_t)NB * NPOS * 128]; // softmaxed q, [b][n][k] bf16
__device__ __nv_bfloat16 g_xt[(size_t)NB * NPOS * 256];  // X transposed: [b][n][k] bf16
__device__ __nv_bfloat16 g_wt[384 * 256];                // W_qkv bf16, k contiguous

// ---------------- FiLM ----------------
__global__ void film_kernel(const float* __restrict__ cond,
                            const float* __restrict__ Wc,
                            const float* __restrict__ bc) {
    int b = blockIdx.x, t = threadIdx.x;
    __shared__ float sc[256];
    if (t < 256) {
        float xv = cond[b * 256 + t];
        sc[t] = xv / (1.0f + __expf(-xv));
    }
    __syncthreads();
    const float* wr = Wc + t * 256;
    float acc = bc[t];
#pragma unroll 8
    for (int j = 0; j < 256; j++) acc += wr[j] * sc[j];
    g_film[b * 512 + t] = acc;
}

// ---------------- converts ----------------
__global__ void wconv_kernel(const float* __restrict__ W) {
    int i = blockIdx.x * 1024 + threadIdx.x;
    if (i < 384 * 256) g_wt[i] = __float2bfloat16(W[i]);
}

// X [b][256 k][4096 n] fp32 -> g_xt [b][4096 n][256 k] bf16 (32x32 tiles)
__global__ void xpose_kernel(const float* __restrict__ X) {
    __shared__ float s[32][33];
    int b = blockIdx.z, k0 = blockIdx.y * 32, n0 = blockIdx.x * 32;
    int tx = threadIdx.x, ty = threadIdx.y;
    const float* src = X + ((size_t)b * 256 + k0) * NPOS + n0;
#pragma unroll
    for (int i = 0; i < 4; i++)
        s[ty + 8 * i][tx] = src[(size_t)(ty + 8 * i) * NPOS + tx];
    __syncthreads();
    __nv_bfloat16* dst = g_xt + ((size_t)b * NPOS + n0) * 256 + k0;
#pragma unroll
    for (int i = 0; i < 4; i++)
        dst[(size_t)(ty + 8 * i) * 256 + tx] = __float2bfloat16(s[tx][ty + 8 * i]);
}

// ================= mma helpers =================
__device__ __forceinline__ uint32_t smem_u32(const void* p) {
    uint32_t a;
    asm("{ .reg .u64 t; cvta.to.shared.u64 t, %1; cvt.u32.u64 %0, t; }" : "=r"(a) : "l"(p));
    return a;
}
__device__ __forceinline__ void cpa16(uint32_t dst, const void* src) {
    asm volatile("cp.async.cg.shared.global [%0], [%1], 16;"
                 :: "r"(dst), "l"(__cvta_generic_to_global(src)));
}
#define CPA_COMMIT() asm volatile("cp.async.commit_group;" ::: "memory")
#define CPA_WAIT0()  asm volatile("cp.async.wait_group 0;" ::: "memory")

__device__ __forceinline__ void mma_bf16(float c[4], const uint32_t a[4], const uint32_t b[2]) {
    asm volatile(
        "mma.sync.aligned.m16n8k16.row.col.f32.bf16.bf16.f32 "
        "{%0,%1,%2,%3}, {%4,%5,%6,%7}, {%8,%9}, {%0,%1,%2,%3};\n"
        : "+f"(c[0]), "+f"(c[1]), "+f"(c[2]), "+f"(c[3])
        : "r"(a[0]), "r"(a[1]), "r"(a[2]), "r"(a[3]), "r"(b[0]), "r"(b[1]));
}

__device__ __forceinline__ void filmAB(int m, const float* __restrict__ fb,
                                       float& alpha, float& beta) {
    alpha = 1.0f; beta = 0.0f;
    if (m >= 256) {
        int c = m - 256;
        alpha = (1.0f + fb[256 + c]) * INVN;
        beta = fb[384 + c] * INVN;
    } else if (m >= 128) {
        int c = m - 128;
        alpha = 1.0f + fb[c];
        beta = fb[128 + c];
    }
}

// ================= qkv GEMM: bf16 mma, cp.async double buffer =================
#define KW 20   // smem row stride in 32-bit words (16 data + 4 pad)

__global__ void __launch_bounds__(256, 2) qkv_mma(void) {
    __shared__ uint32_t As[2][128 * KW];
    __shared__ uint32_t Bs[2][128 * KW];

    int b = blockIdx.z, grp = blockIdx.y;
    int m0 = grp * 128, n0 = blockIdx.x * 128;
    int t = threadIdx.x, lane = t & 31, w = t >> 5;
    int wr = w >> 2, wc = w & 3;
    int lq = lane >> 2, lr = lane & 3;

    float acc[4][4][4];
#pragma unroll
    for (int mt = 0; mt < 4; mt++)
#pragma unroll
        for (int nt = 0; nt < 4; nt++)
#pragma unroll
            for (int r = 0; r < 4; r++) acc[mt][nt][r] = 0.0f;

    int f0 = 2 * t, f1 = 2 * t + 1;
    int ar0 = f0 >> 2, ak0 = f0 & 3;
    int ar1 = f1 >> 2, ak1 = f1 & 3;
    const __nv_bfloat16* Awg0 = g_wt + (size_t)(m0 + ar0) * 256 + ak0 * 8;
    const __nv_bfloat16* Awg1 = g_wt + (size_t)(m0 + ar1) * 256 + ak1 * 8;
    const __nv_bfloat16* Bxg0 = g_xt + ((size_t)b * NPOS + n0 + ar0) * 256 + ak0 * 8;
    const __nv_bfloat16* Bxg1 = g_xt + ((size_t)b * NPOS + n0 + ar1) * 256 + ak1 * 8;

    uint32_t dA0[2], dA1[2], dB0[2], dB1[2];
#pragma unroll
    for (int s = 0; s < 2; s++) {
        dA0[s] = smem_u32(&As[s][ar0 * KW + ak0 * 4]);
        dA1[s] = smem_u32(&As[s][ar1 * KW + ak1 * 4]);
        dB0[s] = smem_u32(&Bs[s][ar0 * KW + ak0 * 4]);
        dB1[s] = smem_u32(&Bs[s][ar1 * KW + ak1 * 4]);
    }

    // preload stage 0
    cpa16(dA0[0], Awg0); cpa16(dA1[0], Awg1);
    cpa16(dB0[0], Bxg0); cpa16(dB1[0], Bxg1);
    CPA_COMMIT(); CPA_WAIT0();
    __syncthreads();

    for (int kk = 0; kk < 8; kk++) {
        int cur = kk & 1;
        if (kk < 7) {
            int nxt = 1 - cur, ko = (kk + 1) * 32;
            cpa16(dA0[nxt], Awg0 + ko); cpa16(dA1[nxt], Awg1 + ko);
            cpa16(dB0[nxt], Bxg0 + ko); cpa16(dB1[nxt], Bxg1 + ko);
            CPA_COMMIT();
        }
#pragma unroll
        for (int ks = 0; ks < 2; ks++) {
            int ksw = ks * 8;
            uint32_t af[4][4], bf[4][2];
#pragma unroll
            for (int mt = 0; mt < 4; mt++) {
                int r0 = wr * 64 + mt * 16 + lq;
                af[mt][0] = As[cur][r0 * KW + ksw + lr];
                af[mt][1] = As[cur][(r0 + 8) * KW + ksw + lr];
                af[mt][2] = As[cur][r0 * KW + ksw + lr + 4];
                af[mt][3] = As[cur][(r0 + 8) * KW + ksw + lr + 4];
            }
#pragma unroll
            for (int nt = 0; nt < 4; nt++) {
                int n = wc * 32 + nt * 8 + lq;
                bf[nt][0] = Bs[cur][n * KW + ksw + lr];
                bf[nt][1] = Bs[cur][n * KW + ksw + lr + 4];
            }
#pragma unroll
            for (int mt = 0; mt < 4; mt++)
#pragma unroll
                for (int nt = 0; nt < 4; nt++) mma_bf16(acc[mt][nt], af[mt], bf[nt]);
        }
        if (kk < 7) {
            CPA_WAIT0();
            __syncthreads();
        }
    }

    const float* fb = g_film + b * 512;
    float* C = g_qkv + (size_t)b * 384 * NPOS;
#pragma unroll
    for (int mt = 0; mt < 4; mt++) {
        int mA = m0 + wr * 64 + mt * 16 + lq;
        int mB = mA + 8;
        float aA, bA, aB, bB;
        filmAB(mA, fb, aA, bA);
        filmAB(mB, fb, aB, bB);
#pragma unroll
        for (int nt = 0; nt < 4; nt++) {
            int cc = n0 + wc * 32 + nt * 8 + 2 * lr;
            float2 o0, o1;
            o0.x = fmaf(aA, acc[mt][nt][0], bA);
            o0.y = fmaf(aA, acc[mt][nt][1], bA);
            o1.x = fmaf(aB, acc[mt][nt][2], bB);
            o1.y = fmaf(aB, acc[mt][nt][3], bB);
            *(float2*)&C[(size_t)mA * NPOS + cc] = o0;
            *(float2*)&C[(size_t)mB * NPOS + cc] = o1;
        }
    }
}

// ---------------- per (b, k-channel) max over n ----------------
__global__ void kmax_kernel() {
    int b = blockIdx.y, c = blockIdx.x, t = threadIdx.x;
    const float* row = g_qkv + ((size_t)b * 384 + 128 + c) * NPOS;
    float m = -1e30f;
    for (int i = t; i < NPOS; i += 256) m = fmaxf(m, row[i]);
    __shared__ float red[8];
#pragma unroll
    for (int o = 16; o; o >>= 1) m = fmaxf(m, __shfl_xor_sync(0xffffffffu, m, o));
    if ((t & 31) == 0) red[t >> 5] = m;
    __syncthreads();
    if (t < 8) {
        m = red[t];
#pragma unroll
        for (int o = 4; o; o >>= 1) m = fmaxf(m, __shfl_xor_sync(0xffu, m, o));
        if (t == 0) g_kmax[b * 128 + c] = m;
    }
}

// ---------------- context partials ----------------
__global__ void __launch_bounds__(256) ctx_kernel() {
    int b = blockIdx.z, h = blockIdx.y, chunk = blockIdx.x;
    int nbase = chunk * 512;
    int t = threadIdx.x;
    __shared__ float Et[32][65];
    __shared__ float Vt[32][65];
    int c = t & 31, e4 = t >> 5;
    int rF = t >> 3, cF = (t & 7) << 3;
    const float* Kb = g_qkv + ((size_t)b * 384 + 128 + h * 32 + rF) * NPOS + nbase + cF;
    const float* Vb = g_qkv + ((size_t)b * 384 + 256 + h * 32 + rF) * NPOS + nbase + cF;
    float km = g_kmax[b * 128 + h * 32 + rF];

    float a0 = 0.f, a1 = 0.f, a2 = 0.f, a3 = 0.f, z = 0.f;
    for (int sub = 0; sub < 8; sub++) {
        float4 k0 = *(const float4*)(Kb + sub * 64);
        float4 k1 = *(const float4*)(Kb + sub * 64 + 4);
        float4 v0 = *(const float4*)(Vb + sub * 64);
        float4 v1 = *(const float4*)(Vb + sub * 64 + 4);
        __syncthreads();
        Et[rF][cF + 0] = __expf(k0.x - km);
        Et[rF][cF + 1] = __expf(k0.y - km);
        Et[rF][cF + 2] = __expf(k0.z - km);
        Et[rF][cF + 3] = __expf(k0.w - km);
        Et[rF][cF + 4] = __expf(k1.x - km);
        Et[rF][cF + 5] = __expf(k1.y - km);
        Et[rF][cF + 6] = __expf(k1.z - km);
        Et[rF][cF + 7] = __expf(k1.w - km);
        Vt[rF][cF + 0] = v0.x; Vt[rF][cF + 1] = v0.y;
        Vt[rF][cF + 2] = v0.z; Vt[rF][cF + 3] = v0.w;
        Vt[rF][cF + 4] = v1.x; Vt[rF][cF + 5] = v1.y;
        Vt[rF][cF + 6] = v1.z; Vt[rF][cF + 7] = v1.w;
        __syncthreads();
#pragma unroll 16
        for (int n = 0; n < 64; n++) {
            float ec = Et[c][n];
            if (e4 == 0) z += ec;
            a0 += ec * Vt[(e4 << 2) + 0][n];
            a1 += ec * Vt[(e4 << 2) + 1][n];
            a2 += ec * Vt[(e4 << 2) + 2][n];
            a3 += ec * Vt[(e4 << 2) + 3][n];
        }
    }
    float* Sp = g_Sp + ((((size_t)chunk * NB + b) * 4 + h) * 32 + c) * 32 + (e4 << 2);
    Sp[0] = a0; Sp[1] = a1; Sp[2] = a2; Sp[3] = a3;
    if (e4 == 0) g_Zp[((size_t)chunk * NB + b) * 128 + h * 32 + c] = z;
}

// ---------------- build M_b (bf16 out) ----------------
__global__ void buildM_kernel(const float* __restrict__ Wout) {
    int b = blockIdx.x, t = threadIdx.x;
    __shared__ float ctxs[4096];
    __shared__ float zsm[128];
    if (t < 128) {
        float zz = 0.f;
#pragma unroll
        for (int ch = 0; ch < NCHUNK; ch++) zz += g_Zp[((size_t)ch * NB + b) * 128 + t];
        zsm[t] = zz;
    }
    __syncthreads();
    for (int i = t; i < 4096; i += 256) {
        int h = i >> 10, c = (i >> 5) & 31;
        float s = 0.f;
#pragma unroll
        for (int ch = 0; ch < NCHUNK; ch++) s += g_Sp[((size_t)ch * NB + b) * 4096 + i];
        ctxs[i] = s / zsm[h * 32 + c];
    }
    __syncthreads();
    const float* wr = Wout + t * 128;
    __nv_bfloat16* Mr = g_Mb + (size_t)b * 32768 + t * 128;
    for (int h = 0; h < 4; h++) {
        float w[32];
#pragma unroll
        for (int e = 0; e < 32; e++) w[e] = wr[h * 32 + e];
        for (int c2 = 0; c2 < 32; c2++) {
            float s = 0.f;
#pragma unroll
            for (int e = 0; e < 32; e++) s += w[e] * ctxs[h * 1024 + c2 * 32 + e];
            Mr[h * 32 + c2] = __float2bfloat16(s);
        }
    }
}

// ---------------- q softmax -> g_qsm [b][n][128] bf16 ----------------
// grid (64, NB), block 256. Tile: channels 0..127 x 64 positions.
__global__ void __launch_bounds__(256) qsm_kernel() {
    __shared__ float s[128][65];
    int b = blockIdx.y, n0 = blockIdx.x * 64, t = threadIdx.x;
    const float* Q = g_qkv + (size_t)b * 384 * NPOS;
    for (int i = t; i < 8192; i += 256) {
        int c = i >> 6, j = i & 63;
        s[c][j] = Q[(size_t)c * NPOS + n0 + j];
    }
    __syncthreads();
    int nl = t >> 2, h = t & 3;
    float v[32];
    float mx = -1e30f;
#pragma unroll
    for (int i = 0; i < 32; i++) {
        v[i] = s[h * 32 + i][nl];
        mx = fmaxf(mx, v[i]);
    }
    float ssum = 0.f;
#pragma unroll
    for (int i = 0; i < 32; i++) {
        v[i] = __expf(v[i] - mx);
        ssum += v[i];
    }
    float inv = SCALE / ssum;
    uint4 ow[4];
    uint32_t* owp = (uint32_t*)ow;
#pragma unroll
    for (int i = 0; i < 16; i++) {
        __nv_bfloat162 p = __floats2bfloat162_rn(v[2 * i] * inv, v[2 * i + 1] * inv);
        owp[i] = *(uint32_t*)&p;
    }
    uint4* dst = (uint4*)(g_qsm + ((size_t)b * NPOS + n0 + nl) * 128 + h * 32);
#pragma unroll
    for (int i = 0; i < 4; i++) dst[i] = ow[i];
}

// ---------------- final: out = M_b @ q_sm + b_out, LN, via mma ----------------
// grid (64, NB), block 256 (8 warps: wr=w>>1 in 0..3 covers 64 rows; wc=w&1 covers 32 cols).
// Block tile: 256 rows x 64 cols, K=128 from smem in one shot.
#define KW2 72               // 64 data words + 8 pad per row
#define FO_M  0              // 256*72 = 18432 words
#define FO_Q  18432          // 64*72 = 4608
#define FO_B  23040          // 256
#define FO_G  23296          // 256
#define FO_WS 23552          // 8*32 = 256
#define FO_WQ 23808          // 256
#define FO_CS 24064          // 64
#define FO_CQ 24128          // 64
#define F_TOT 24192          // words (96768 B)

__global__ void __launch_bounds__(256) final_mma(const float* __restrict__ bout,
                                                 const float* __restrict__ gam,
                                                 float* __restrict__ out) {
    extern __shared__ uint32_t fsm[];
    uint32_t* Msm = fsm + FO_M;
    uint32_t* Qsm = fsm + FO_Q;
    float* bsm = (float*)(fsm + FO_B);
    float* gsm = (float*)(fsm + FO_G);
    float* wsum = (float*)(fsm + FO_WS);
    float* wsq = (float*)(fsm + FO_WQ);
    float* csum = (float*)(fsm + FO_CS);
    float* csq = (float*)(fsm + FO_CQ);

    int b = blockIdx.y, n0 = blockIdx.x * 64, t = threadIdx.x;
    int lane = t & 31, w = t >> 5;
    int wr = w >> 1, wc = w & 1;
    int lq = lane >> 2, lr = lane & 3;

    // load M_b (256x128 bf16) and q tile (64x128 bf16) into smem
    const uint4* Mg = (const uint4*)(g_Mb + (size_t)b * 32768);
    for (int i = t; i < 4096; i += 256) {
        int row = i >> 4, q4 = i & 15;
        *(uint4*)&Msm[row * KW2 + q4 * 4] = Mg[i];
    }
    const uint4* Qg = (const uint4*)(g_qsm + ((size_t)b * NPOS + n0) * 128);
    for (int i = t; i < 1024; i += 256) {
        int row = i >> 4, q4 = i & 15;
        *(uint4*)&Qsm[row * KW2 + q4 * 4] = Qg[i];
    }
    bsm[t] = bout[t];
    gsm[t] = gam[t];
    __syncthreads();

    float acc[4][4][4];
#pragma unroll
    for (int mt = 0; mt < 4; mt++)
#pragma unroll
        for (int nt = 0; nt < 4; nt++)
#pragma unroll
            for (int r = 0; r < 4; r++) acc[mt][nt][r] = 0.0f;

#pragma unroll
    for (int ks = 0; ks < 8; ks++) {
        int ksw = ks * 8;
        uint32_t af[4][4], bf[4][2];
#pragma unroll
        for (int mt = 0; mt < 4; mt++) {
            int r0 = wr * 64 + mt * 16 + lq;
            af[mt][0] = Msm[r0 * KW2 + ksw + lr];
            af[mt][1] = Msm[(r0 + 8) * KW2 + ksw + lr];
            af[mt][2] = Msm[r0 * KW2 + ksw + lr + 4];
            af[mt][3] = Msm[(r0 + 8) * KW2 + ksw + lr + 4];
        }
#pragma unroll
        for (int nt = 0; nt < 4; nt++) {
            int n = wc * 32 + nt * 8 + lq;
            bf[nt][0] = Qsm[n * KW2 + ksw + lr];
            bf[nt][1] = Qsm[n * KW2 + ksw + lr + 4];
        }
#pragma unroll
        for (int mt = 0; mt < 4; mt++)
#pragma unroll
            for (int nt = 0; nt < 4; nt++) mma_bf16(acc[mt][nt], af[mt], bf[nt]);
    }

    // + bias, per-column partial stats over this thread's 8 rows
    float ps[4][2], pq[4][2];
#pragma unroll
    for (int nt = 0; nt < 4; nt++)
#pragma unroll
        for (int j = 0; j < 2; j++) { ps[nt][j] = 0.f; pq[nt][j] = 0.f; }
#pragma unroll
    for (int mt = 0; mt < 4; mt++) {
        float b0v = bsm[wr * 64 + mt * 16 + lq];
        float b1v = bsm[wr * 64 + mt * 16 + lq + 8];
#pragma unroll
        for (int nt = 0; nt < 4; nt++) {
            acc[mt][nt][0] += b0v; acc[mt][nt][1] += b0v;
            acc[mt][nt][2] += b1v; acc[mt][nt][3] += b1v;
#pragma unroll
            for (int j = 0; j < 2; j++) {
                float v0 = acc[mt][nt][j], v1 = acc[mt][nt][2 + j];
                ps[nt][j] += v0 + v1;
                pq[nt][j] += v0 * v0 + v1 * v1;
            }
        }
    }
    // reduce across lq lanes (same lr): xor 4, 8, 16
#pragma unroll
    for (int nt = 0; nt < 4; nt++)
#pragma unroll
        for (int j = 0; j < 2; j++) {
#pragma unroll
            for (int o = 4; o <= 16; o <<= 1) {
                ps[nt][j] += __shfl_xor_sync(0xffffffffu, ps[nt][j], o);
                pq[nt][j] += __shfl_xor_sync(0xffffffffu, pq[nt][j], o);
            }
        }
    if (lq == 0) {
#pragma unroll
        for (int nt = 0; nt < 4; nt++)
#pragma unroll
            for (int j = 0; j < 2; j++) {
                wsum[w * 32 + nt * 8 + 2 * lr + j] = ps[nt][j];
                wsq[w * 32 + nt * 8 + 2 * lr + j] = pq[nt][j];
            }
    }
    __syncthreads();
    if (t < 64) {
        int wcg = t >> 5, cl = t & 31;
        float sx = 0.f, sq2 = 0.f;
#pragma unroll
        for (int k = 0; k < 4; k++) {
            sx += wsum[(k * 2 + wcg) * 32 + cl];
            sq2 += wsq[(k * 2 + wcg) * 32 + cl];
        }
        csum[t] = sx;
        csq[t] = sq2;
    }
    __syncthreads();

    float mean[4][2], rs[4][2];
#pragma unroll
    for (int nt = 0; nt < 4; nt++)
#pragma unroll
        for (int j = 0; j < 2; j++) {
            int cg = wc * 32 + nt * 8 + 2 * lr + j;
            float mu = csum[cg] * (1.0f / 256.0f);
            float var = csq[cg] * (1.0f / 256.0f) - mu * mu;
            mean[nt][j] = mu;
            rs[nt][j] = rsqrtf(var + 1e-5f);
        }
#pragma unroll
    for (int mt = 0; mt < 4; mt++) {
        int r0 = wr * 64 + mt * 16 + lq;
        float g0 = gsm[r0], g1 = gsm[r0 + 8];
#pragma unroll
        for (int nt = 0; nt < 4; nt++) {
            int cc = n0 + wc * 32 + nt * 8 + 2 * lr;
            float2 o0, o1;
            o0.x = (acc[mt][nt][0] - mean[nt][0]) * rs[nt][0] * g0;
            o0.y = (acc[mt][nt][1] - mean[nt][1]) * rs[nt][1] * g0;
            o1.x = (acc[mt][nt][2] - mean[nt][0]) * rs[nt][0] * g1;
            o1.y = (acc[mt][nt][3] - mean[nt][1]) * rs[nt][1] * g1;
            *(float2*)&out[((size_t)(b * 256 + r0)) * NPOS + cc] = o0;
            *(float2*)&out[((size_t)(b * 256 + r0 + 8)) * NPOS + cc] = o1;
        }
    }
}

// ---------------- launch ----------------
extern "C" void kernel_launch(void* const* d_in, const int* in_sizes, int n_in,
                              void* d_out, int out_size) {
    (void)in_sizes; (void)n_in; (void)out_size;
    const float* x = (const float*)d_in[0];
    const float* cond = (const float*)d_in[1];
    const float* W_qkv = (const float*)d_in[2];
    const float* W_cond = (const float*)d_in[3];
    const float* b_cond = (const float*)d_in[4];
    const float* W_out = (const float*)d_in[5];
    const float* b_out = (const float*)d_in[6];
    const float* g = (const float*)d_in[7];
    float* out = (float*)d_out;

    film_kernel<<<NB, 512>>>(cond, W_cond, b_cond);
    wconv_kernel<<<96, 1024>>>(W_qkv);
    xpose_kernel<<<dim3(128, 8, NB), dim3(32, 8)>>>(x);
    qkv_mma<<<dim3(32, 3, NB), 256>>>();
    kmax_kernel<<<dim3(128, NB), 256>>>();
    ctx_kernel<<<dim3(NCHUNK, 4, NB), 256>>>();
    buildM_kernel<<<NB, 256>>>(W_out);
    qsm_kernel<<<dim3(64, NB), 256>>>();

    int smbytes = F_TOT * (int)sizeof(uint32_t);
    cudaFuncSetAttribute(final_mma, cudaFuncAttributeMaxDynamicSharedMemorySize, smbytes);
    final_mma<<<dim3(64, NB), 256, smbytes>>>(b_out, g, out);
}

// round 6
// speedup vs baseline: 2.3059x; 1.1927x over previous
#include <cuda_runtime.h>
#include <cuda_bf16.h>
#include <cstdint>

#define NB 16
#define NPOS 4096
#define SCALE 0.17677669529663687f   // 32^-0.5
#define INVN (1.0f / 4096.0f)
#define NCHUNK 8

// ---------------- scratch (device globals; no runtime allocation) ----------------
__device__ __nv_bfloat16 g_qkvh[(size_t)NB * 384 * NPOS]; // q(raw)/k(FiLM)/v(FiLM,/n) bf16
__device__ float g_film[NB * 512];
__device__ float g_kmax[NB * 128];
__device__ float g_Sp[NCHUNK * NB * 4 * 32 * 32];
__device__ float g_Zp[NCHUNK * NB * 128];
__device__ __nv_bfloat16 g_Mb[NB * 256 * 128];            // M_b bf16, k contiguous
__device__ __nv_bfloat16 g_wt[384 * 256];                 // W_qkv bf16, k contiguous

// ---------------- FiLM ----------------
__global__ void film_kernel(const float* __restrict__ cond,
                            const float* __restrict__ Wc,
                            const float* __restrict__ bc) {
    int b = blockIdx.x, t = threadIdx.x;
    __shared__ float sc[256];
    if (t < 256) {
        float xv = cond[b * 256 + t];
        sc[t] = xv / (1.0f + __expf(-xv));
    }
    __syncthreads();
    const float* wr = Wc + t * 256;
    float acc = bc[t];
#pragma unroll 8
    for (int j = 0; j < 256; j++) acc += wr[j] * sc[j];
    g_film[b * 512 + t] = acc;
}

__global__ void wconv_kernel(const float* __restrict__ W) {
    int i = blockIdx.x * 1024 + threadIdx.x;
    if (i < 384 * 256) g_wt[i] = __float2bfloat16(W[i]);
}

// ================= helpers =================
__device__ __forceinline__ uint32_t smem_u32(const void* p) {
    uint32_t a;
    asm("{ .reg .u64 t; cvta.to.shared.u64 t, %1; cvt.u32.u64 %0, t; }" : "=r"(a) : "l"(p));
    return a;
}
__device__ __forceinline__ void cpa16(uint32_t dst, const void* src) {
    asm volatile("cp.async.cg.shared.global [%0], [%1], 16;"
                 :: "r"(dst), "l"(__cvta_generic_to_global(src)));
}
#define CPA_COMMIT() asm volatile("cp.async.commit_group;" ::: "memory")
#define CPA_WAIT0()  asm volatile("cp.async.wait_group 0;" ::: "memory")

__device__ __forceinline__ void mma_bf16(float c[4], const uint32_t a[4], const uint32_t b[2]) {
    asm volatile(
        "mma.sync.aligned.m16n8k16.row.col.f32.bf16.bf16.f32 "
        "{%0,%1,%2,%3}, {%4,%5,%6,%7}, {%8,%9}, {%0,%1,%2,%3};\n"
        : "+f"(c[0]), "+f"(c[1]), "+f"(c[2]), "+f"(c[3])
        : "r"(a[0]), "r"(a[1]), "r"(a[2]), "r"(a[3]), "r"(b[0]), "r"(b[1]));
}
__device__ __forceinline__ void ldm_x4(uint32_t r[4], uint32_t addr) {
    asm volatile("ldmatrix.sync.aligned.m8n8.x4.shared.b16 {%0,%1,%2,%3}, [%4];"
                 : "=r"(r[0]), "=r"(r[1]), "=r"(r[2]), "=r"(r[3]) : "r"(addr));
}
__device__ __forceinline__ void ldm_x4t(uint32_t& r0, uint32_t& r1, uint32_t& r2, uint32_t& r3,
                                        uint32_t addr) {
    asm volatile("ldmatrix.sync.aligned.m8n8.x4.trans.shared.b16 {%0,%1,%2,%3}, [%4];"
                 : "=r"(r0), "=r"(r1), "=r"(r2), "=r"(r3) : "r"(addr));
}
__device__ __forceinline__ void filmAB(int m, const float* __restrict__ fb,
                                       float& alpha, float& beta) {
    alpha = 1.0f; beta = 0.0f;
    if (m >= 256) {
        int c = m - 256;
        alpha = (1.0f + fb[256 + c]) * INVN;
        beta = fb[384 + c] * INVN;
    } else if (m >= 128) {
        int c = m - 128;
        alpha = 1.0f + fb[c];
        beta = fb[128 + c];
    }
}

// ================= qkv GEMM: ldmatrix + cp.async(A) + fused X convert =================
// Block 128m x 128n x 32k/stage, 8 warps (2x4), warp 64x32, bf16 mma m16n8k16.
// A: [m][k] bf16 smem, 80B rows. B: [k][n] bf16 smem, 272B rows, fragments via ldmatrix.trans.
__global__ void __launch_bounds__(256, 2) qkv_mma(const float* __restrict__ X) {
    __shared__ uint8_t As[2][10240];   // 128 rows x 80B
    __shared__ uint8_t Bs[2][8704];    // 32 rows x 272B

    int b = blockIdx.z, grp = blockIdx.y;
    int m0 = grp * 128, n0 = blockIdx.x * 128;
    int t = threadIdx.x, lane = t & 31, w = t >> 5;
    int wr = w >> 2, wc = w & 3;
    int lq = lane >> 2, lr = lane & 3;

    float acc[4][4][4];
#pragma unroll
    for (int mt = 0; mt < 4; mt++)
#pragma unroll
        for (int nt = 0; nt < 4; nt++)
#pragma unroll
            for (int r = 0; r < 4; r++) acc[mt][nt][r] = 0.0f;

    // A cp.async mapping: 2x 16B chunks/thread (rows of 64B = 4 chunks)
    int c0 = 2 * t, c1 = c0 + 1;
    int aR0 = c0 >> 2, aS0 = c0 & 3;
    int aR1 = c1 >> 2, aS1 = c1 & 3;
    const __nv_bfloat16* gA0 = g_wt + (size_t)(m0 + aR0) * 256 + aS0 * 8;
    const __nv_bfloat16* gA1 = g_wt + (size_t)(m0 + aR1) * 256 + aS1 * 8;
    uint32_t sA0[2], sA1[2];
#pragma unroll
    for (int s = 0; s < 2; s++) {
        sA0[s] = smem_u32(&As[s][aR0 * 80 + aS0 * 16]);
        sA1[s] = smem_u32(&As[s][aR1 * 80 + aS1 * 16]);
    }

    // B: 4 float4 per thread per stage, convert->bf16 smem [k][n]
    const float* gB[4];
    uint8_t* pB[2][4];
#pragma unroll
    for (int j = 0; j < 4; j++) {
        int f = t + 256 * j;
        int bR = f >> 5, bC = f & 31;
        gB[j] = X + ((size_t)b * 256 + bR) * NPOS + n0 + bC * 4;
        pB[0][j] = &Bs[0][bR * 272 + bC * 8];
        pB[1][j] = &Bs[1][bR * 272 + bC * 8];
    }

    // fragment base offsets (bytes)
    uint32_t aOff = (uint32_t)(wr * 64 + (lane & 15)) * 80 + ((lane >> 4) << 3) * 2;
    uint32_t bOff = (uint32_t)(((lane >> 3) & 1) * 8 + (lane & 7)) * 272 +
                    (uint32_t)(wc * 32 + ((lane >> 4) << 3)) * 2;
    uint32_t Ab[2] = {smem_u32(As[0]), smem_u32(As[1])};
    uint32_t Bb[2] = {smem_u32(Bs[0]), smem_u32(Bs[1])};

#define BSTORE(stage, j)                                                        \
    {                                                                           \
        __nv_bfloat162 p0 = __floats2bfloat162_rn(xb[j].x, xb[j].y);            \
        __nv_bfloat162 p1 = __floats2bfloat162_rn(xb[j].z, xb[j].w);            \
        uint2 u;                                                                \
        u.x = *(uint32_t*)&p0; u.y = *(uint32_t*)&p1;                           \
        *(uint2*)(pB[stage][j]) = u;                                            \
    }

    // preload stage 0
    cpa16(sA0[0], gA0); cpa16(sA1[0], gA1); CPA_COMMIT();
    float4 xb[4];
#pragma unroll
    for (int j = 0; j < 4; j++) xb[j] = *(const float4*)gB[j];
#pragma unroll
    for (int j = 0; j < 4; j++) BSTORE(0, j);
    CPA_WAIT0();
    __syncthreads();

    for (int kk = 0; kk < 8; kk++) {
        int cur = kk & 1, nxt = cur ^ 1;
        if (kk < 7) {
            int ko = (kk + 1) * 32;
            cpa16(sA0[nxt], gA0 + ko); cpa16(sA1[nxt], gA1 + ko); CPA_COMMIT();
            size_t go = (size_t)ko * NPOS;
#pragma unroll
            for (int j = 0; j < 4; j++) xb[j] = *(const float4*)(gB[j] + go);
        }
#pragma unroll
        for (int kh = 0; kh < 2; kh++) {
            uint32_t af[4][4];
#pragma unroll
            for (int mt = 0; mt < 4; mt++)
                ldm_x4(af[mt], Ab[cur] + aOff + mt * 1280 + kh * 32);
            uint32_t bfr[4][2];
#pragma unroll
            for (int pr = 0; pr < 2; pr++) {
                uint32_t r0, r1, r2, r3;
                ldm_x4t(r0, r1, r2, r3, Bb[cur] + bOff + kh * 4352 + pr * 32);
                bfr[2 * pr][0] = r0; bfr[2 * pr][1] = r1;
                bfr[2 * pr + 1][0] = r2; bfr[2 * pr + 1][1] = r3;
            }
#pragma unroll
            for (int mt = 0; mt < 4; mt++)
#pragma unroll
                for (int nt = 0; nt < 4; nt++) mma_bf16(acc[mt][nt], af[mt], bfr[nt]);
        }
        if (kk < 7) {
#pragma unroll
            for (int j = 0; j < 4; j++) BSTORE(nxt, j);
            CPA_WAIT0();
            __syncthreads();
        }
    }

    // FiLM epilogue -> g_qkvh bf16
    const float* fb = g_film + b * 512;
    __nv_bfloat16* C = g_qkvh + (size_t)b * 384 * NPOS;
#pragma unroll
    for (int mt = 0; mt < 4; mt++) {
        int mA = m0 + wr * 64 + mt * 16 + lq;
        int mB = mA + 8;
        float aA, bA, aB, bB;
        filmAB(mA, fb, aA, bA);
        filmAB(mB, fb, aB, bB);
#pragma unroll
        for (int nt = 0; nt < 4; nt++) {
            int cc = n0 + wc * 32 + nt * 8 + 2 * lr;
            __nv_bfloat162 o0 = __floats2bfloat162_rn(fmaf(aA, acc[mt][nt][0], bA),
                                                      fmaf(aA, acc[mt][nt][1], bA));
            __nv_bfloat162 o1 = __floats2bfloat162_rn(fmaf(aB, acc[mt][nt][2], bB),
                                                      fmaf(aB, acc[mt][nt][3], bB));
            *(__nv_bfloat162*)&C[(size_t)mA * NPOS + cc] = o0;
            *(__nv_bfloat162*)&C[(size_t)mB * NPOS + cc] = o1;
        }
    }
}

// ---------------- per (b, k-channel) max over n (bf16 input) ----------------
__global__ void kmax_kernel() {
    int b = blockIdx.y, c = blockIdx.x, t = threadIdx.x;
    const uint4* row = (const uint4*)(g_qkvh + ((size_t)b * 384 + 128 + c) * NPOS);
    float m = -1e30f;
    for (int i = t; i < 512; i += 256) {
        uint4 vv = row[i];
        __nv_bfloat162* p = (__nv_bfloat162*)&vv;
#pragma unroll
        for (int j = 0; j < 4; j++) {
            float2 f = __bfloat1622float2(p[j]);
            m = fmaxf(m, fmaxf(f.x, f.y));
        }
    }
    __shared__ float red[8];
#pragma unroll
    for (int o = 16; o; o >>= 1) m = fmaxf(m, __shfl_xor_sync(0xffffffffu, m, o));
    if ((t & 31) == 0) red[t >> 5] = m;
    __syncthreads();
    if (t < 8) {
        m = red[t];
#pragma unroll
        for (int o = 4; o; o >>= 1) m = fmaxf(m, __shfl_xor_sync(0xffu, m, o));
        if (t == 0) g_kmax[b * 128 + c] = m;
    }
}

// ---------------- context partials (bf16 input) ----------------
__global__ void __launch_bounds__(256) ctx_kernel() {
    int b = blockIdx.z, h = blockIdx.y, chunk = blockIdx.x;
    int nbase = chunk * 512;
    int t = threadIdx.x;
    __shared__ float Et[32][65];
    __shared__ float Vt[32][65];
    int c = t & 31, e4 = t >> 5;
    int rF = t >> 3, cF = (t & 7) << 3;
    const __nv_bfloat16* Kb = g_qkvh + ((size_t)b * 384 + 128 + h * 32 + rF) * NPOS + nbase + cF;
    const __nv_bfloat16* Vb = g_qkvh + ((size_t)b * 384 + 256 + h * 32 + rF) * NPOS + nbase + cF;
    float km = g_kmax[b * 128 + h * 32 + rF];

    float a0 = 0.f, a1 = 0.f, a2 = 0.f, a3 = 0.f, z = 0.f;
    for (int sub = 0; sub < 8; sub++) {
        uint4 kraw = *(const uint4*)(Kb + sub * 64);
        uint4 vraw = *(const uint4*)(Vb + sub * 64);
        __syncthreads();
        __nv_bfloat162* kp = (__nv_bfloat162*)&kraw;
        __nv_bfloat162* vp = (__nv_bfloat162*)&vraw;
#pragma unroll
        for (int p = 0; p < 4; p++) {
            float2 kf = __bfloat1622float2(kp[p]);
            float2 vf = __bfloat1622float2(vp[p]);
            Et[rF][cF + 2 * p] = __expf(kf.x - km);
            Et[rF][cF + 2 * p + 1] = __expf(kf.y - km);
            Vt[rF][cF + 2 * p] = vf.x;
            Vt[rF][cF + 2 * p + 1] = vf.y;
        }
        __syncthreads();
#pragma unroll 16
        for (int n = 0; n < 64; n++) {
            float ec = Et[c][n];
            if (e4 == 0) z += ec;
            a0 += ec * Vt[(e4 << 2) + 0][n];
            a1 += ec * Vt[(e4 << 2) + 1][n];
            a2 += ec * Vt[(e4 << 2) + 2][n];
            a3 += ec * Vt[(e4 << 2) + 3][n];
        }
    }
    float* Sp = g_Sp + ((((size_t)chunk * NB + b) * 4 + h) * 32 + c) * 32 + (e4 << 2);
    Sp[0] = a0; Sp[1] = a1; Sp[2] = a2; Sp[3] = a3;
    if (e4 == 0) g_Zp[((size_t)chunk * NB + b) * 128 + h * 32 + c] = z;
}

// ---------------- build M_b (bf16 out) ----------------
__global__ void buildM_kernel(const float* __restrict__ Wout) {
    int b = blockIdx.x, t = threadIdx.x;
    __shared__ float ctxs[4096];
    __shared__ float zsm[128];
    if (t < 128) {
        float zz = 0.f;
#pragma unroll
        for (int ch = 0; ch < NCHUNK; ch++) zz += g_Zp[((size_t)ch * NB + b) * 128 + t];
        zsm[t] = zz;
    }
    __syncthreads();
    for (int i = t; i < 4096; i += 256) {
        int h = i >> 10, c = (i >> 5) & 31;
        float s = 0.f;
#pragma unroll
        for (int ch = 0; ch < NCHUNK; ch++) s += g_Sp[((size_t)ch * NB + b) * 4096 + i];
        ctxs[i] = s / zsm[h * 32 + c];
    }
    __syncthreads();
    const float* wr = Wout + t * 128;
    __nv_bfloat16* Mr = g_Mb + (size_t)b * 32768 + t * 128;
    for (int h = 0; h < 4; h++) {
        float w[32];
#pragma unroll
        for (int e = 0; e < 32; e++) w[e] = wr[h * 32 + e];
        for (int c2 = 0; c2 < 32; c2++) {
            float s = 0.f;
#pragma unroll
            for (int e = 0; e < 32; e++) s += w[e] * ctxs[h * 1024 + c2 * 32 + e];
            Mr[h * 32 + c2] = __float2bfloat16(s);
        }
    }
}

// ---------------- final: fused q-softmax + (M_b @ q)*.. + bias + LN via mma ----------------
// grid (64, NB), 256 threads. Block tile 256 rows x 64 cols, K=128.
#define KW2 72
#define FO_M  0           // 256*72 = 18432 words (M bf16x2 fragments)
#define FO_Q  18432       // 64*72 = 4608
#define FO_T  23040       // q raw bf16: 128*68 bf16 = 4352 words
#define FO_B  27392
#define FO_G  27648
#define FO_WS 27904
#define FO_WQ 28160
#define FO_CS 28416
#define FO_CQ 28480
#define F_TOT 28544       // words = 114176 bytes

__global__ void __launch_bounds__(256) final_mma(const float* __restrict__ bout,
                                                 const float* __restrict__ gam,
                                                 float* __restrict__ out) {
    extern __shared__ uint32_t fsm[];
    uint32_t* Msm = fsm + FO_M;
    uint32_t* Qsm = fsm + FO_Q;
    uint16_t* qh = (uint16_t*)(fsm + FO_T);
    float* bsm = (float*)(fsm + FO_B);
    float* gsm = (float*)(fsm + FO_G);
    float* wsum = (float*)(fsm + FO_WS);
    float* wsq = (float*)(fsm + FO_WQ);
    float* csum = (float*)(fsm + FO_CS);
    float* csq = (float*)(fsm + FO_CQ);

    int b = blockIdx.y, n0 = blockIdx.x * 64, t = threadIdx.x;
    int lane = t & 31, w = t >> 5;
    int wr = w >> 1, wc = w & 1;
    int lq = lane >> 2, lr = lane & 3;

    // kick off M load via cp.async (overlaps with q softmax)
    const __nv_bfloat16* Mg = g_Mb + (size_t)b * 32768;
#pragma unroll
    for (int j = 0; j < 16; j++) {
        int c = t + 256 * j;           // 4096 chunks of 16B
        int row = c >> 4, seg = c & 15;
        cpa16(smem_u32(&Msm[row * KW2 + seg * 4]), Mg + row * 128 + seg * 8);
    }
    CPA_COMMIT();

    // load q tile (128 chans x 64 cols bf16) into qh
    const __nv_bfloat16* Qg = g_qkvh + (size_t)b * 384 * NPOS + n0;
    for (int i = t; i < 2048; i += 256) {
        int row = i >> 4, c4 = i & 15;
        uint2 v = *(const uint2*)(Qg + (size_t)row * NPOS + c4 * 4);
        *(uint2*)&qh[row * 68 + c4 * 4] = v;
    }
    bsm[t] = bout[t];
    gsm[t] = gam[t];
    __syncthreads();

    // per-(head, col) softmax over 32 channels, pack bf16 fragments into Qsm
    {
        int h = t >> 6, col = t & 63;
        float v[32];
        float mx = -1e30f;
#pragma unroll
        for (int i = 0; i < 32; i++) {
            uint16_t raw = qh[(h * 32 + i) * 68 + col];
            v[i] = __bfloat162float(*(__nv_bfloat16*)&raw);
            mx = fmaxf(mx, v[i]);
        }
        float ssum = 0.f;
#pragma unroll
        for (int i = 0; i < 32; i++) {
            v[i] = __expf(v[i] - mx);
            ssum += v[i];
        }
        float inv = SCALE / ssum;
#pragma unroll
        for (int i2 = 0; i2 < 16; i2++) {
            __nv_bfloat162 p = __floats2bfloat162_rn(v[2 * i2] * inv, v[2 * i2 + 1] * inv);
            Qsm[col * KW2 + h * 16 + i2] = *(uint32_t*)&p;
        }
    }
    CPA_WAIT0();
    __syncthreads();

    float acc[4][4][4];
#pragma unroll
    for (int mt = 0; mt < 4; mt++)
#pragma unroll
        for (int nt = 0; nt < 4; nt++)
#pragma unroll
            for (int r = 0; r < 4; r++) acc[mt][nt][r] = 0.0f;

#pragma unroll
    for (int ks = 0; ks < 8; ks++) {
        int ksw = ks * 8;
        uint32_t af[4][4], bfr[4][2];
#pragma unroll
        for (int mt = 0; mt < 4; mt++) {
            int r0 = wr * 64 + mt * 16 + lq;
            af[mt][0] = Msm[r0 * KW2 + ksw + lr];
            af[mt][1] = Msm[(r0 + 8) * KW2 + ksw + lr];
            af[mt][2] = Msm[r0 * KW2 + ksw + lr + 4];
            af[mt][3] = Msm[(r0 + 8) * KW2 + ksw + lr + 4];
        }
#pragma unroll
        for (int nt = 0; nt < 4; nt++) {
            int n = wc * 32 + nt * 8 + lq;
            bfr[nt][0] = Qsm[n * KW2 + ksw + lr];
            bfr[nt][1] = Qsm[n * KW2 + ksw + lr + 4];
        }
#pragma unroll
        for (int mt = 0; mt < 4; mt++)
#pragma unroll
            for (int nt = 0; nt < 4; nt++) mma_bf16(acc[mt][nt], af[mt], bfr[nt]);
    }

    // + bias, per-column stats
    float ps[4][2], pq[4][2];
#pragma unroll
    for (int nt = 0; nt < 4; nt++)
#pragma unroll
        for (int j = 0; j < 2; j++) { ps[nt][j] = 0.f; pq[nt][j] = 0.f; }
#pragma unroll
    for (int mt = 0; mt < 4; mt++) {
        float b0v = bsm[wr * 64 + mt * 16 + lq];
        float b1v = bsm[wr * 64 + mt * 16 + lq + 8];
#pragma unroll
        for (int nt = 0; nt < 4; nt++) {
            acc[mt][nt][0] += b0v; acc[mt][nt][1] += b0v;
            acc[mt][nt][2] += b1v; acc[mt][nt][3] += b1v;
#pragma unroll
            for (int j = 0; j < 2; j++) {
                float v0 = acc[mt][nt][j], v1 = acc[mt][nt][2 + j];
                ps[nt][j] += v0 + v1;
                pq[nt][j] += v0 * v0 + v1 * v1;
            }
        }
    }
#pragma unroll
    for (int nt = 0; nt < 4; nt++)
#pragma unroll
        for (int j = 0; j < 2; j++) {
#pragma unroll
            for (int o = 4; o <= 16; o <<= 1) {
                ps[nt][j] += __shfl_xor_sync(0xffffffffu, ps[nt][j], o);
                pq[nt][j] += __shfl_xor_sync(0xffffffffu, pq[nt][j], o);
            }
        }
    if (lq == 0) {
#pragma unroll
        for (int nt = 0; nt < 4; nt++)
#pragma unroll
            for (int j = 0; j < 2; j++) {
                wsum[w * 32 + nt * 8 + 2 * lr + j] = ps[nt][j];
                wsq[w * 32 + nt * 8 + 2 * lr + j] = pq[nt][j];
            }
    }
    __syncthreads();
    if (t < 64) {
        int wcg = t >> 5, cl = t & 31;
        float sx = 0.f, sq2 = 0.f;
#pragma unroll
        for (int k = 0; k < 4; k++) {
            sx += wsum[(k * 2 + wcg) * 32 + cl];
            sq2 += wsq[(k * 2 + wcg) * 32 + cl];
        }
        csum[t] = sx;
        csq[t] = sq2;
    }
    __syncthreads();

    float mean[4][2], rs[4][2];
#pragma unroll
    for (int nt = 0; nt < 4; nt++)
#pragma unroll
        for (int j = 0; j < 2; j++) {
            int cg = wc * 32 + nt * 8 + 2 * lr + j;
            float mu = csum[cg] * (1.0f / 256.0f);
            float var = csq[cg] * (1.0f / 256.0f) - mu * mu;
            mean[nt][j] = mu;
            rs[nt][j] = rsqrtf(var + 1e-5f);
        }
#pragma unroll
    for (int mt = 0; mt < 4; mt++) {
        int r0 = wr * 64 + mt * 16 + lq;
        float g0 = gsm[r0], g1 = gsm[r0 + 8];
#pragma unroll
        for (int nt = 0; nt < 4; nt++) {
            int cc = n0 + wc * 32 + nt * 8 + 2 * lr;
            float2 o0, o1;
            o0.x = (acc[mt][nt][0] - mean[nt][0]) * rs[nt][0] * g0;
            o0.y = (acc[mt][nt][1] - mean[nt][1]) * rs[nt][1] * g0;
            o1.x = (acc[mt][nt][2] - mean[nt][0]) * rs[nt][0] * g1;
            o1.y = (acc[mt][nt][3] - mean[nt][1]) * rs[nt][1] * g1;
            *(float2*)&out[((size_t)(b * 256 + r0)) * NPOS + cc] = o0;
            *(float2*)&out[((size_t)(b * 256 + r0 + 8)) * NPOS + cc] = o1;
        }
    }
}

// ---------------- launch ----------------
extern "C" void kernel_launch(void* const* d_in, const int* in_sizes, int n_in,
                              void* d_out, int out_size) {
    (void)in_sizes; (void)n_in; (void)out_size;
    const float* x = (const float*)d_in[0];
    const float* cond = (const float*)d_in[1];
    const float* W_qkv = (const float*)d_in[2];
    const float* W_cond = (const float*)d_in[3];
    const float* b_cond = (const float*)d_in[4];
    const float* W_out = (const float*)d_in[5];
    const float* b_out = (const float*)d_in[6];
    const float* g = (const float*)d_in[7];
    float* out = (float*)d_out;

    film_kernel<<<NB, 512>>>(cond, W_cond, b_cond);
    wconv_kernel<<<96, 1024>>>(W_qkv);
    qkv_mma<<<dim3(32, 3, NB), 256>>>(x);
    kmax_kernel<<<dim3(128, NB), 256>>>();
    ctx_kernel<<<dim3(NCHUNK, 4, NB), 256>>>();
    buildM_kernel<<<NB, 256>>>(W_out);

    int smbytes = F_TOT * (int)sizeof(uint32_t);
    cudaFuncSetAttribute(final_mma, cudaFuncAttributeMaxDynamicSharedMemorySize, smbytes);
    final_mma<<<dim3(64, NB), 256, smbytes>>>(b_out, g, out);
}

// round 7
// speedup vs baseline: 2.4351x; 1.0561x over previous
#include <cuda_runtime.h>
#include <cuda_bf16.h>
#include <cstdint>

#define NB 16
#define NPOS 4096
#define SCALE 0.17677669529663687f   // 32^-0.5
#define INVN (1.0f / 4096.0f)
#define NCHUNK 8

// ---------------- scratch (device globals; no runtime allocation) ----------------
__device__ __nv_bfloat16 g_qkvh[(size_t)NB * 384 * NPOS]; // q(raw)/k(FiLM)/v(FiLM,/n) bf16
__device__ float g_film[NB * 512];
__device__ float g_Sp[NCHUNK * NB * 4 * 32 * 32];
__device__ float g_Zp[NCHUNK * NB * 128];
__device__ float g_Mx[NCHUNK * NB * 128];
__device__ __nv_bfloat16 g_Mb[NB * 256 * 128];            // M_b bf16, k contiguous
__device__ __nv_bfloat16 g_wt[384 * 256];                 // W_qkv bf16, k contiguous

// ---------------- FiLM ----------------
__global__ void film_kernel(const float* __restrict__ cond,
                            const float* __restrict__ Wc,
                            const float* __restrict__ bc) {
    int b = blockIdx.x, t = threadIdx.x;
    __shared__ float sc[256];
    if (t < 256) {
        float xv = cond[b * 256 + t];
        sc[t] = xv / (1.0f + __expf(-xv));
    }
    __syncthreads();
    const float* wr = Wc + t * 256;
    float acc = bc[t];
#pragma unroll 8
    for (int j = 0; j < 256; j++) acc += wr[j] * sc[j];
    g_film[b * 512 + t] = acc;
}

__global__ void wconv_kernel(const float* __restrict__ W) {
    int i = blockIdx.x * 1024 + threadIdx.x;
    if (i < 384 * 256) g_wt[i] = __float2bfloat16(W[i]);
}

// ================= helpers =================
__device__ __forceinline__ uint32_t smem_u32(const void* p) {
    uint32_t a;
    asm("{ .reg .u64 t; cvta.to.shared.u64 t, %1; cvt.u32.u64 %0, t; }" : "=r"(a) : "l"(p));
    return a;
}
__device__ __forceinline__ void cpa16(uint32_t dst, const void* src) {
    asm volatile("cp.async.cg.shared.global [%0], [%1], 16;"
                 :: "r"(dst), "l"(__cvta_generic_to_global(src)));
}
#define CPA_COMMIT() asm volatile("cp.async.commit_group;" ::: "memory")
#define CPA_WAIT0()  asm volatile("cp.async.wait_group 0;" ::: "memory")

__device__ __forceinline__ void mma_bf16(float c[4], const uint32_t a[4], const uint32_t b[2]) {
    asm volatile(
        "mma.sync.aligned.m16n8k16.row.col.f32.bf16.bf16.f32 "
        "{%0,%1,%2,%3}, {%4,%5,%6,%7}, {%8,%9}, {%0,%1,%2,%3};\n"
        : "+f"(c[0]), "+f"(c[1]), "+f"(c[2]), "+f"(c[3])
        : "r"(a[0]), "r"(a[1]), "r"(a[2]), "r"(a[3]), "r"(b[0]), "r"(b[1]));
}
__device__ __forceinline__ void ldm_x4(uint32_t r[4], uint32_t addr) {
    asm volatile("ldmatrix.sync.aligned.m8n8.x4.shared.b16 {%0,%1,%2,%3}, [%4];"
                 : "=r"(r[0]), "=r"(r[1]), "=r"(r[2]), "=r"(r[3]) : "r"(addr));
}
__device__ __forceinline__ void ldm_x2(uint32_t r[2], uint32_t addr) {
    asm volatile("ldmatrix.sync.aligned.m8n8.x2.shared.b16 {%0,%1}, [%2];"
                 : "=r"(r[0]), "=r"(r[1]) : "r"(addr));
}
__device__ __forceinline__ void ldm_x4t(uint32_t& r0, uint32_t& r1, uint32_t& r2, uint32_t& r3,
                                        uint32_t addr) {
    asm volatile("ldmatrix.sync.aligned.m8n8.x4.trans.shared.b16 {%0,%1,%2,%3}, [%4];"
                 : "=r"(r0), "=r"(r1), "=r"(r2), "=r"(r3) : "r"(addr));
}
__device__ __forceinline__ void filmAB(int m, const float* __restrict__ fb,
                                       float& alpha, float& beta) {
    alpha = 1.0f; beta = 0.0f;
    if (m >= 256) {
        int c = m - 256;
        alpha = (1.0f + fb[256 + c]) * INVN;
        beta = fb[384 + c] * INVN;
    } else if (m >= 128) {
        int c = m - 128;
        alpha = 1.0f + fb[c];
        beta = fb[128 + c];
    }
}

// ================= qkv GEMM: ldmatrix + cp.async(A) + fused X convert =================
// grid (3 grp, 32 n-tiles, NB) — grp innermost so the 3 CTAs sharing an X tile hit L2.
__global__ void __launch_bounds__(256, 2) qkv_mma(const float* __restrict__ X) {
    __shared__ uint8_t As[2][10240];   // 128 rows x 80B
    __shared__ uint8_t Bs[2][8704];    // 32 rows x 272B

    int b = blockIdx.z, grp = blockIdx.x;
    int m0 = grp * 128, n0 = blockIdx.y * 128;
    int t = threadIdx.x, lane = t & 31, w = t >> 5;
    int wr = w >> 2, wc = w & 3;
    int lq = lane >> 2, lr = lane & 3;

    float acc[4][4][4];
#pragma unroll
    for (int mt = 0; mt < 4; mt++)
#pragma unroll
        for (int nt = 0; nt < 4; nt++)
#pragma unroll
            for (int r = 0; r < 4; r++) acc[mt][nt][r] = 0.0f;

    int c0 = 2 * t, c1 = c0 + 1;
    int aR0 = c0 >> 2, aS0 = c0 & 3;
    int aR1 = c1 >> 2, aS1 = c1 & 3;
    const __nv_bfloat16* gA0 = g_wt + (size_t)(m0 + aR0) * 256 + aS0 * 8;
    const __nv_bfloat16* gA1 = g_wt + (size_t)(m0 + aR1) * 256 + aS1 * 8;
    uint32_t sA0[2], sA1[2];
#pragma unroll
    for (int s = 0; s < 2; s++) {
        sA0[s] = smem_u32(&As[s][aR0 * 80 + aS0 * 16]);
        sA1[s] = smem_u32(&As[s][aR1 * 80 + aS1 * 16]);
    }

    const float* gB[4];
    uint8_t* pB[2][4];
#pragma unroll
    for (int j = 0; j < 4; j++) {
        int f = t + 256 * j;
        int bR = f >> 5, bC = f & 31;
        gB[j] = X + ((size_t)b * 256 + bR) * NPOS + n0 + bC * 4;
        pB[0][j] = &Bs[0][bR * 272 + bC * 8];
        pB[1][j] = &Bs[1][bR * 272 + bC * 8];
    }

    uint32_t aOff = (uint32_t)(wr * 64 + (lane & 15)) * 80 + ((lane >> 4) << 3) * 2;
    uint32_t bOff = (uint32_t)(((lane >> 3) & 1) * 8 + (lane & 7)) * 272 +
                    (uint32_t)(wc * 32 + ((lane >> 4) << 3)) * 2;
    uint32_t Ab[2] = {smem_u32(As[0]), smem_u32(As[1])};
    uint32_t Bb[2] = {smem_u32(Bs[0]), smem_u32(Bs[1])};

#define BSTORE(stage, j)                                                        \
    {                                                                           \
        __nv_bfloat162 p0 = __floats2bfloat162_rn(xb[j].x, xb[j].y);            \
        __nv_bfloat162 p1 = __floats2bfloat162_rn(xb[j].z, xb[j].w);            \
        uint2 u;                                                                \
        u.x = *(uint32_t*)&p0; u.y = *(uint32_t*)&p1;                           \
        *(uint2*)(pB[stage][j]) = u;                                            \
    }

    cpa16(sA0[0], gA0); cpa16(sA1[0], gA1); CPA_COMMIT();
    float4 xb[4];
#pragma unroll
    for (int j = 0; j < 4; j++) xb[j] = *(const float4*)gB[j];
#pragma unroll
    for (int j = 0; j < 4; j++) BSTORE(0, j);
    CPA_WAIT0();
    __syncthreads();

    for (int kk = 0; kk < 8; kk++) {
        int cur = kk & 1, nxt = cur ^ 1;
        if (kk < 7) {
            int ko = (kk + 1) * 32;
            cpa16(sA0[nxt], gA0 + ko); cpa16(sA1[nxt], gA1 + ko); CPA_COMMIT();
            size_t go = (size_t)ko * NPOS;
#pragma unroll
            for (int j = 0; j < 4; j++) xb[j] = *(const float4*)(gB[j] + go);
        }
#pragma unroll
        for (int kh = 0; kh < 2; kh++) {
            uint32_t af[4][4];
#pragma unroll
            for (int mt = 0; mt < 4; mt++)
                ldm_x4(af[mt], Ab[cur] + aOff + mt * 1280 + kh * 32);
            uint32_t bfr[4][2];
#pragma unroll
            for (int pr = 0; pr < 2; pr++) {
                uint32_t r0, r1, r2, r3;
                ldm_x4t(r0, r1, r2, r3, Bb[cur] + bOff + kh * 4352 + pr * 32);
                bfr[2 * pr][0] = r0; bfr[2 * pr][1] = r1;
                bfr[2 * pr + 1][0] = r2; bfr[2 * pr + 1][1] = r3;
            }
#pragma unroll
            for (int mt = 0; mt < 4; mt++)
#pragma unroll
                for (int nt = 0; nt < 4; nt++) mma_bf16(acc[mt][nt], af[mt], bfr[nt]);
        }
        if (kk < 7) {
#pragma unroll
            for (int j = 0; j < 4; j++) BSTORE(nxt, j);
            CPA_WAIT0();
            __syncthreads();
        }
    }

    const float* fb = g_film + b * 512;
    __nv_bfloat16* C = g_qkvh + (size_t)b * 384 * NPOS;
#pragma unroll
    for (int mt = 0; mt < 4; mt++) {
        int mA = m0 + wr * 64 + mt * 16 + lq;
        int mB = mA + 8;
        float aA, bA, aB, bB;
        filmAB(mA, fb, aA, bA);
        filmAB(mB, fb, aB, bB);
#pragma unroll
        for (int nt = 0; nt < 4; nt++) {
            int cc = n0 + wc * 32 + nt * 8 + 2 * lr;
            __nv_bfloat162 o0 = __floats2bfloat162_rn(fmaf(aA, acc[mt][nt][0], bA),
                                                      fmaf(aA, acc[mt][nt][1], bA));
            __nv_bfloat162 o1 = __floats2bfloat162_rn(fmaf(aB, acc[mt][nt][2], bB),
                                                      fmaf(aB, acc[mt][nt][3], bB));
            *(__nv_bfloat162*)&C[(size_t)mA * NPOS + cc] = o0;
            *(__nv_bfloat162*)&C[(size_t)mB * NPOS + cc] = o1;
        }
    }
}

// ================= ctx via mma: flash-style local max, S = E @ V^T =================
// grid (NCHUNK, 4 heads, NB), 256 threads. K,V tiles 32x512 bf16 in smem (stride 520).
#define KSE 520
__global__ void __launch_bounds__(256) ctx_mma() {
    extern __shared__ __nv_bfloat16 cs[];
    __nv_bfloat16* Ks = cs;                 // 32 x KSE (E overwrites in place)
    __nv_bfloat16* Vs = cs + 32 * KSE;

    int b = blockIdx.z, h = blockIdx.y, chunk = blockIdx.x;
    int t = threadIdx.x;

    const __nv_bfloat16* Kg = g_qkvh + ((size_t)b * 384 + 128 + h * 32) * NPOS + chunk * 512;
    const __nv_bfloat16* Vg = Kg + (size_t)128 * NPOS;
    for (int i = t; i < 2048; i += 256) {
        int row = i >> 6, col = i & 63;
        *(uint4*)&Ks[row * KSE + col * 8] = *(const uint4*)(Kg + (size_t)row * NPOS + col * 8);
        *(uint4*)&Vs[row * KSE + col * 8] = *(const uint4*)(Vg + (size_t)row * NPOS + col * 8);
    }
    __syncthreads();

    // local max over this chunk for channel c (8 threads per channel)
    int c = t >> 3, sub = t & 7;
    __nv_bfloat16* Kr = Ks + c * KSE + sub * 64;
    float m = -1e30f;
#pragma unroll
    for (int j4 = 0; j4 < 8; j4++) {
        uint4 kv = *(uint4*)&Kr[j4 * 8];
        __nv_bfloat162* kp = (__nv_bfloat162*)&kv;
#pragma unroll
        for (int p = 0; p < 4; p++) {
            float2 f = __bfloat1622float2(kp[p]);
            m = fmaxf(m, fmaxf(f.x, f.y));
        }
    }
#pragma unroll
    for (int o = 1; o < 8; o <<= 1) m = fmaxf(m, __shfl_xor_sync(0xffffffffu, m, o));

    // exponentiate in place (bf16), accumulate z over bf16 E
    float z = 0.f;
#pragma unroll
    for (int j4 = 0; j4 < 8; j4++) {
        uint4 kv = *(uint4*)&Kr[j4 * 8];
        __nv_bfloat162* kp = (__nv_bfloat162*)&kv;
        uint4 ev;
        __nv_bfloat162* ep = (__nv_bfloat162*)&ev;
#pragma unroll
        for (int p = 0; p < 4; p++) {
            float2 f = __bfloat1622float2(kp[p]);
            __nv_bfloat162 e2 = __floats2bfloat162_rn(__expf(f.x - m), __expf(f.y - m));
            ep[p] = e2;
            float2 ef = __bfloat1622float2(e2);
            z += ef.x + ef.y;
        }
        *(uint4*)&Kr[j4 * 8] = ev;
    }
#pragma unroll
    for (int o = 1; o < 8; o <<= 1) z += __shfl_xor_sync(0xffffffffu, z, o);
    if (sub == 0) g_Zp[((size_t)chunk * NB + b) * 128 + h * 32 + c] = z;
    if (sub == 1) g_Mx[((size_t)chunk * NB + b) * 128 + h * 32 + c] = m;
    __syncthreads();

    // S(32x32) = E(32x512) @ V^T : 8 warps in 2(M) x 4(N), each m16n8, K=512
    int w = t >> 5, lane = t & 31;
    int mrow = (w & 1) * 16, ncol = (w >> 1) * 8;
    uint32_t Eb = smem_u32(Ks), Vb = smem_u32(Vs);
    uint32_t aAddr = Eb + ((mrow + (lane & 15)) * KSE + ((lane >> 4) << 3)) * 2;
    uint32_t bAddr = Vb + ((ncol + (lane & 7)) * KSE + (((lane >> 3) & 3) << 3)) * 2;
    float acc[4] = {0.f, 0.f, 0.f, 0.f};
#pragma unroll 8
    for (int ks = 0; ks < 32; ks++) {
        uint32_t a[4], bb[2];
        ldm_x4(a, aAddr + ks * 32);
        ldm_x2(bb, bAddr + ks * 32);
        mma_bf16(acc, a, bb);
    }
    int lq = lane >> 2, lr = lane & 3;
    float* Sp = g_Sp + (((size_t)chunk * NB + b) * 4 + h) * 1024;
    Sp[(mrow + lq) * 32 + ncol + 2 * lr] = acc[0];
    Sp[(mrow + lq) * 32 + ncol + 2 * lr + 1] = acc[1];
    Sp[(mrow + lq + 8) * 32 + ncol + 2 * lr] = acc[2];
    Sp[(mrow + lq + 8) * 32 + ncol + 2 * lr + 1] = acc[3];
}

// ---------------- build M_b (bf16 out), flash-style chunk combine ----------------
__global__ void buildM_kernel(const float* __restrict__ Wout) {
    int b = blockIdx.x, t = threadIdx.x;
    __shared__ float ctxs[4096];
    __shared__ float zsm[128];
    __shared__ float scl[NCHUNK * 128];
    if (t < 128) {
        float mloc[NCHUNK];
        float mg = -1e30f;
#pragma unroll
        for (int ch = 0; ch < NCHUNK; ch++) {
            mloc[ch] = g_Mx[((size_t)ch * NB + b) * 128 + t];
            mg = fmaxf(mg, mloc[ch]);
        }
        float zz = 0.f;
#pragma unroll
        for (int ch = 0; ch < NCHUNK; ch++) {
            float s = __expf(mloc[ch] - mg);
            scl[ch * 128 + t] = s;
            zz += g_Zp[((size_t)ch * NB + b) * 128 + t] * s;
        }
        zsm[t] = zz;
    }
    __syncthreads();
    for (int i = t; i < 4096; i += 256) {
        int h = i >> 10, c = (i >> 5) & 31;
        int chan = h * 32 + c;
        float s = 0.f;
#pragma unroll
        for (int ch = 0; ch < NCHUNK; ch++)
            s += g_Sp[((size_t)ch * NB + b) * 4096 + i] * scl[ch * 128 + chan];
        ctxs[i] = s / zsm[chan];
    }
    __syncthreads();
    const float* wr = Wout + t * 128;
    __nv_bfloat16* Mr = g_Mb + (size_t)b * 32768 + t * 128;
    for (int h = 0; h < 4; h++) {
        float w[32];
#pragma unroll
        for (int e = 0; e < 32; e++) w[e] = wr[h * 32 + e];
        for (int c2 = 0; c2 < 32; c2++) {
            float s = 0.f;
#pragma unroll
            for (int e = 0; e < 32; e++) s += w[e] * ctxs[h * 1024 + c2 * 32 + e];
            Mr[h * 32 + c2] = __float2bfloat16(s);
        }
    }
}

// ---------------- final: fused q-softmax + (M_b @ q) + bias + LN via mma ----------------
#define KW2 72
#define FO_M  0
#define FO_Q  18432
#define FO_T  23040
#define FO_B  27392
#define FO_G  27648
#define FO_WS 27904
#define FO_WQ 28160
#define FO_CS 28416
#define FO_CQ 28480
#define F_TOT 28544

__global__ void __launch_bounds__(256) final_mma(const float* __restrict__ bout,
                                                 const float* __restrict__ gam,
                                                 float* __restrict__ out) {
    extern __shared__ uint32_t fsm[];
    uint32_t* Msm = fsm + FO_M;
    uint32_t* Qsm = fsm + FO_Q;
    uint16_t* qh = (uint16_t*)(fsm + FO_T);
    float* bsm = (float*)(fsm + FO_B);
    float* gsm = (float*)(fsm + FO_G);
    float* wsum = (float*)(fsm + FO_WS);
    float* wsq = (float*)(fsm + FO_WQ);
    float* csum = (float*)(fsm + FO_CS);
    float* csq = (float*)(fsm + FO_CQ);

    int b = blockIdx.y, n0 = blockIdx.x * 64, t = threadIdx.x;
    int lane = t & 31, w = t >> 5;
    int wr = w >> 1, wc = w & 1;
    int lq = lane >> 2, lr = lane & 3;

    const __nv_bfloat16* Mg = g_Mb + (size_t)b * 32768;
#pragma unroll
    for (int j = 0; j < 16; j++) {
        int c = t + 256 * j;
        int row = c >> 4, seg = c & 15;
        cpa16(smem_u32(&Msm[row * KW2 + seg * 4]), Mg + row * 128 + seg * 8);
    }
    CPA_COMMIT();

    const __nv_bfloat16* Qg = g_qkvh + (size_t)b * 384 * NPOS + n0;
    for (int i = t; i < 2048; i += 256) {
        int row = i >> 4, c4 = i & 15;
        uint2 v = *(const uint2*)(Qg + (size_t)row * NPOS + c4 * 4);
        *(uint2*)&qh[row * 68 + c4 * 4] = v;
    }
    bsm[t] = bout[t];
    gsm[t] = gam[t];
    __syncthreads();

    {
        int h = t >> 6, col = t & 63;
        float v[32];
        float mx = -1e30f;
#pragma unroll
        for (int i = 0; i < 32; i++) {
            uint16_t raw = qh[(h * 32 + i) * 68 + col];
            v[i] = __bfloat162float(*(__nv_bfloat16*)&raw);
            mx = fmaxf(mx, v[i]);
        }
        float ssum = 0.f;
#pragma unroll
        for (int i = 0; i < 32; i++) {
            v[i] = __expf(v[i] - mx);
            ssum += v[i];
        }
        float inv = SCALE / ssum;
#pragma unroll
        for (int i2 = 0; i2 < 16; i2++) {
            __nv_bfloat162 p = __floats2bfloat162_rn(v[2 * i2] * inv, v[2 * i2 + 1] * inv);
            Qsm[col * KW2 + h * 16 + i2] = *(uint32_t*)&p;
        }
    }
    CPA_WAIT0();
    __syncthreads();

    float acc[4][4][4];
#pragma unroll
    for (int mt = 0; mt < 4; mt++)
#pragma unroll
        for (int nt = 0; nt < 4; nt++)
#pragma unroll
            for (int r = 0; r < 4; r++) acc[mt][nt][r] = 0.0f;

#pragma unroll
    for (int ks = 0; ks < 8; ks++) {
        int ksw = ks * 8;
        uint32_t af[4][4], bfr[4][2];
#pragma unroll
        for (int mt = 0; mt < 4; mt++) {
            int r0 = wr * 64 + mt * 16 + lq;
            af[mt][0] = Msm[r0 * KW2 + ksw + lr];
            af[mt][1] = Msm[(r0 + 8) * KW2 + ksw + lr];
            af[mt][2] = Msm[r0 * KW2 + ksw + lr + 4];
            af[mt][3] = Msm[(r0 + 8) * KW2 + ksw + lr + 4];
        }
#pragma unroll
        for (int nt = 0; nt < 4; nt++) {
            int n = wc * 32 + nt * 8 + lq;
            bfr[nt][0] = Qsm[n * KW2 + ksw + lr];
            bfr[nt][1] = Qsm[n * KW2 + ksw + lr + 4];
        }
#pragma unroll
        for (int mt = 0; mt < 4; mt++)
#pragma unroll
            for (int nt = 0; nt < 4; nt++) mma_bf16(acc[mt][nt], af[mt], bfr[nt]);
    }

    float ps[4][2], pq[4][2];
#pragma unroll
    for (int nt = 0; nt < 4; nt++)
#pragma unroll
        for (int j = 0; j < 2; j++) { ps[nt][j] = 0.f; pq[nt][j] = 0.f; }
#pragma unroll
    for (int mt = 0; mt < 4; mt++) {
        float b0v = bsm[wr * 64 + mt * 16 + lq];
        float b1v = bsm[wr * 64 + mt * 16 + lq + 8];
#pragma unroll
        for (int nt = 0; nt < 4; nt++) {
            acc[mt][nt][0] += b0v; acc[mt][nt][1] += b0v;
            acc[mt][nt][2] += b1v; acc[mt][nt][3] += b1v;
#pragma unroll
            for (int j = 0; j < 2; j++) {
                float v0 = acc[mt][nt][j], v1 = acc[mt][nt][2 + j];
                ps[nt][j] += v0 + v1;
                pq[nt][j] += v0 * v0 + v1 * v1;
            }
        }
    }
#pragma unroll
    for (int nt = 0; nt < 4; nt++)
#pragma unroll
        for (int j = 0; j < 2; j++) {
#pragma unroll
            for (int o = 4; o <= 16; o <<= 1) {
                ps[nt][j] += __shfl_xor_sync(0xffffffffu, ps[nt][j], o);
                pq[nt][j] += __shfl_xor_sync(0xffffffffu, pq[nt][j], o);
            }
        }
    if (lq == 0) {
#pragma unroll
        for (int nt = 0; nt < 4; nt++)
#pragma unroll
            for (int j = 0; j < 2; j++) {
                wsum[w * 32 + nt * 8 + 2 * lr + j] = ps[nt][j];
                wsq[w * 32 + nt * 8 + 2 * lr + j] = pq[nt][j];
            }
    }
    __syncthreads();
    if (t < 64) {
        int wcg = t >> 5, cl = t & 31;
        float sx = 0.f, sq2 = 0.f;
#pragma unroll
        for (int k = 0; k < 4; k++) {
            sx += wsum[(k * 2 + wcg) * 32 + cl];
            sq2 += wsq[(k * 2 + wcg) * 32 + cl];
        }
        csum[t] = sx;
        csq[t] = sq2;
    }
    __syncthreads();

    float mean[4][2], rs[4][2];
#pragma unroll
    for (int nt = 0; nt < 4; nt++)
#pragma unroll
        for (int j = 0; j < 2; j++) {
            int cg = wc * 32 + nt * 8 + 2 * lr + j;
            float mu = csum[cg] * (1.0f / 256.0f);
            float var = csq[cg] * (1.0f / 256.0f) - mu * mu;
            mean[nt][j] = mu;
            rs[nt][j] = rsqrtf(var + 1e-5f);
        }
#pragma unroll
    for (int mt = 0; mt < 4; mt++) {
        int r0 = wr * 64 + mt * 16 + lq;
        float g0 = gsm[r0], g1 = gsm[r0 + 8];
#pragma unroll
        for (int nt = 0; nt < 4; nt++) {
            int cc = n0 + wc * 32 + nt * 8 + 2 * lr;
            float2 o0, o1;
            o0.x = (acc[mt][nt][0] - mean[nt][0]) * rs[nt][0] * g0;
            o0.y = (acc[mt][nt][1] - mean[nt][1]) * rs[nt][1] * g0;
            o1.x = (acc[mt][nt][2] - mean[nt][0]) * rs[nt][0] * g1;
            o1.y = (acc[mt][nt][3] - mean[nt][1]) * rs[nt][1] * g1;
            *(float2*)&out[((size_t)(b * 256 + r0)) * NPOS + cc] = o0;
            *(float2*)&out[((size_t)(b * 256 + r0 + 8)) * NPOS + cc] = o1;
        }
    }
}

// ---------------- launch ----------------
extern "C" void kernel_launch(void* const* d_in, const int* in_sizes, int n_in,
                              void* d_out, int out_size) {
    (void)in_sizes; (void)n_in; (void)out_size;
    const float* x = (const float*)d_in[0];
    const float* cond = (const float*)d_in[1];
    const float* W_qkv = (const float*)d_in[2];
    const float* W_cond = (const float*)d_in[3];
    const float* b_cond = (const float*)d_in[4];
    const float* W_out = (const float*)d_in[5];
    const float* b_out = (const float*)d_in[6];
    const float* g = (const float*)d_in[7];
    float* out = (float*)d_out;

    film_kernel<<<NB, 512>>>(cond, W_cond, b_cond);
    wconv_kernel<<<96, 1024>>>(W_qkv);
    qkv_mma<<<dim3(3, 32, NB), 256>>>(x);

    int ctx_smem = 2 * 32 * KSE * (int)sizeof(__nv_bfloat16);
    cudaFuncSetAttribute(ctx_mma, cudaFuncAttributeMaxDynamicSharedMemorySize, ctx_smem);
    ctx_mma<<<dim3(NCHUNK, 4, NB), 256, ctx_smem>>>();

    buildM_kernel<<<NB, 256>>>(W_out);

    int smbytes = F_TOT * (int)sizeof(uint32_t);
    cudaFuncSetAttribute(final_mma, cudaFuncAttributeMaxDynamicSharedMemorySize, smbytes);
    final_mma<<<dim3(64, NB), 256, smbytes>>>(b_out, g, out);
}

// round 8
// speedup vs baseline: 2.5038x; 1.0282x over previous
#include <cuda_runtime.h>
#include <cuda_bf16.h>
#include <cstdint>

#define NB 16
#define NPOS 4096
#define SCALE 0.17677669529663687f   // 32^-0.5
#define INVN (1.0f / 4096.0f)
#define NCHUNK 8

// ---------------- scratch (device globals; no runtime allocation) ----------------
__device__ __nv_bfloat16 g_qkvh[(size_t)NB * 384 * NPOS]; // q(raw)/k(FiLM)/v(FiLM,/n) bf16
__device__ float g_film[NB * 512];
__device__ float g_Sp[NCHUNK * NB * 4 * 32 * 32];
__device__ float g_Zp[NCHUNK * NB * 128];
__device__ float g_Mx[NCHUNK * NB * 128];
__device__ __nv_bfloat16 g_Mb[NB * 256 * 128];            // M_b bf16, k contiguous
__device__ __nv_bfloat16 g_wt[384 * 256];                 // W_qkv bf16, k contiguous

// ---------------- FiLM ----------------
__global__ void film_kernel(const float* __restrict__ cond,
                            const float* __restrict__ Wc,
                            const float* __restrict__ bc) {
    int b = blockIdx.x, t = threadIdx.x;
    __shared__ float sc[256];
    if (t < 256) {
        float xv = cond[b * 256 + t];
        sc[t] = xv / (1.0f + __expf(-xv));
    }
    __syncthreads();
    const float* wr = Wc + t * 256;
    float acc = bc[t];
#pragma unroll 8
    for (int j = 0; j < 256; j++) acc += wr[j] * sc[j];
    g_film[b * 512 + t] = acc;
}

__global__ void wconv_kernel(const float* __restrict__ W) {
    int i = blockIdx.x * 1024 + threadIdx.x;
    if (i < 384 * 256) g_wt[i] = __float2bfloat16(W[i]);
}

// ================= helpers =================
__device__ __forceinline__ uint32_t smem_u32(const void* p) {
    uint32_t a;
    asm("{ .reg .u64 t; cvta.to.shared.u64 t, %1; cvt.u32.u64 %0, t; }" : "=r"(a) : "l"(p));
    return a;
}
__device__ __forceinline__ void cpa16(uint32_t dst, const void* src) {
    asm volatile("cp.async.cg.shared.global [%0], [%1], 16;"
                 :: "r"(dst), "l"(__cvta_generic_to_global(src)));
}
#define CPA_COMMIT() asm volatile("cp.async.commit_group;" ::: "memory")
#define CPA_WAIT0()  asm volatile("cp.async.wait_group 0;" ::: "memory")
#define CPA_WAIT1()  asm volatile("cp.async.wait_group 1;" ::: "memory")

__device__ __forceinline__ void mma_bf16(float c[4], const uint32_t a[4], const uint32_t b[2]) {
    asm volatile(
        "mma.sync.aligned.m16n8k16.row.col.f32.bf16.bf16.f32 "
        "{%0,%1,%2,%3}, {%4,%5,%6,%7}, {%8,%9}, {%0,%1,%2,%3};\n"
        : "+f"(c[0]), "+f"(c[1]), "+f"(c[2]), "+f"(c[3])
        : "r"(a[0]), "r"(a[1]), "r"(a[2]), "r"(a[3]), "r"(b[0]), "r"(b[1]));
}
__device__ __forceinline__ void ldm_x4(uint32_t r[4], uint32_t addr) {
    asm volatile("ldmatrix.sync.aligned.m8n8.x4.shared.b16 {%0,%1,%2,%3}, [%4];"
                 : "=r"(r[0]), "=r"(r[1]), "=r"(r[2]), "=r"(r[3]) : "r"(addr));
}
__device__ __forceinline__ void ldm_x2(uint32_t r[2], uint32_t addr) {
    asm volatile("ldmatrix.sync.aligned.m8n8.x2.shared.b16 {%0,%1}, [%2];"
                 : "=r"(r[0]), "=r"(r[1]) : "r"(addr));
}
__device__ __forceinline__ void ldm_x4t(uint32_t& r0, uint32_t& r1, uint32_t& r2, uint32_t& r3,
                                        uint32_t addr) {
    asm volatile("ldmatrix.sync.aligned.m8n8.x4.trans.shared.b16 {%0,%1,%2,%3}, [%4];"
                 : "=r"(r0), "=r"(r1), "=r"(r2), "=r"(r3) : "r"(addr));
}
__device__ __forceinline__ void filmAB(int m, const float* __restrict__ fb,
                                       float& alpha, float& beta) {
    alpha = 1.0f; beta = 0.0f;
    if (m >= 256) {
        int c = m - 256;
        alpha = (1.0f + fb[256 + c]) * INVN;
        beta = fb[384 + c] * INVN;
    } else if (m >= 128) {
        int c = m - 128;
        alpha = 1.0f + fb[c];
        beta = fb[128 + c];
    }
}

// ================= qkv GEMM (unchanged from R7) =================
__global__ void __launch_bounds__(256, 2) qkv_mma(const float* __restrict__ X) {
    __shared__ uint8_t As[2][10240];
    __shared__ uint8_t Bs[2][8704];

    int b = blockIdx.z, grp = blockIdx.x;
    int m0 = grp * 128, n0 = blockIdx.y * 128;
    int t = threadIdx.x, lane = t & 31, w = t >> 5;
    int wr = w >> 2, wc = w & 3;
    int lq = lane >> 2, lr = lane & 3;

    float acc[4][4][4];
#pragma unroll
    for (int mt = 0; mt < 4; mt++)
#pragma unroll
        for (int nt = 0; nt < 4; nt++)
#pragma unroll
            for (int r = 0; r < 4; r++) acc[mt][nt][r] = 0.0f;

    int c0 = 2 * t, c1 = c0 + 1;
    int aR0 = c0 >> 2, aS0 = c0 & 3;
    int aR1 = c1 >> 2, aS1 = c1 & 3;
    const __nv_bfloat16* gA0 = g_wt + (size_t)(m0 + aR0) * 256 + aS0 * 8;
    const __nv_bfloat16* gA1 = g_wt + (size_t)(m0 + aR1) * 256 + aS1 * 8;
    uint32_t sA0[2], sA1[2];
#pragma unroll
    for (int s = 0; s < 2; s++) {
        sA0[s] = smem_u32(&As[s][aR0 * 80 + aS0 * 16]);
        sA1[s] = smem_u32(&As[s][aR1 * 80 + aS1 * 16]);
    }

    const float* gB[4];
    uint8_t* pB[2][4];
#pragma unroll
    for (int j = 0; j < 4; j++) {
        int f = t + 256 * j;
        int bR = f >> 5, bC = f & 31;
        gB[j] = X + ((size_t)b * 256 + bR) * NPOS + n0 + bC * 4;
        pB[0][j] = &Bs[0][bR * 272 + bC * 8];
        pB[1][j] = &Bs[1][bR * 272 + bC * 8];
    }

    uint32_t aOff = (uint32_t)(wr * 64 + (lane & 15)) * 80 + ((lane >> 4) << 3) * 2;
    uint32_t bOff = (uint32_t)(((lane >> 3) & 1) * 8 + (lane & 7)) * 272 +
                    (uint32_t)(wc * 32 + ((lane >> 4) << 3)) * 2;
    uint32_t Ab[2] = {smem_u32(As[0]), smem_u32(As[1])};
    uint32_t Bb[2] = {smem_u32(Bs[0]), smem_u32(Bs[1])};

#define BSTORE(stage, j)                                                        \
    {                                                                           \
        __nv_bfloat162 p0 = __floats2bfloat162_rn(xb[j].x, xb[j].y);            \
        __nv_bfloat162 p1 = __floats2bfloat162_rn(xb[j].z, xb[j].w);            \
        uint2 u;                                                                \
        u.x = *(uint32_t*)&p0; u.y = *(uint32_t*)&p1;                           \
        *(uint2*)(pB[stage][j]) = u;                                            \
    }

    cpa16(sA0[0], gA0); cpa16(sA1[0], gA1); CPA_COMMIT();
    float4 xb[4];
#pragma unroll
    for (int j = 0; j < 4; j++) xb[j] = *(const float4*)gB[j];
#pragma unroll
    for (int j = 0; j < 4; j++) BSTORE(0, j);
    CPA_WAIT0();
    __syncthreads();

    for (int kk = 0; kk < 8; kk++) {
        int cur = kk & 1, nxt = cur ^ 1;
        if (kk < 7) {
            int ko = (kk + 1) * 32;
            cpa16(sA0[nxt], gA0 + ko); cpa16(sA1[nxt], gA1 + ko); CPA_COMMIT();
            size_t go = (size_t)ko * NPOS;
#pragma unroll
            for (int j = 0; j < 4; j++) xb[j] = *(const float4*)(gB[j] + go);
        }
#pragma unroll
        for (int kh = 0; kh < 2; kh++) {
            uint32_t af[4][4];
#pragma unroll
            for (int mt = 0; mt < 4; mt++)
                ldm_x4(af[mt], Ab[cur] + aOff + mt * 1280 + kh * 32);
            uint32_t bfr[4][2];
#pragma unroll
            for (int pr = 0; pr < 2; pr++) {
                uint32_t r0, r1, r2, r3;
                ldm_x4t(r0, r1, r2, r3, Bb[cur] + bOff + kh * 4352 + pr * 32);
                bfr[2 * pr][0] = r0; bfr[2 * pr][1] = r1;
                bfr[2 * pr + 1][0] = r2; bfr[2 * pr + 1][1] = r3;
            }
#pragma unroll
            for (int mt = 0; mt < 4; mt++)
#pragma unroll
                for (int nt = 0; nt < 4; nt++) mma_bf16(acc[mt][nt], af[mt], bfr[nt]);
        }
        if (kk < 7) {
#pragma unroll
            for (int j = 0; j < 4; j++) BSTORE(nxt, j);
            CPA_WAIT0();
            __syncthreads();
        }
    }

    const float* fb = g_film + b * 512;
    __nv_bfloat16* C = g_qkvh + (size_t)b * 384 * NPOS;
#pragma unroll
    for (int mt = 0; mt < 4; mt++) {
        int mA = m0 + wr * 64 + mt * 16 + lq;
        int mB = mA + 8;
        float aA, bA, aB, bB;
        filmAB(mA, fb, aA, bA);
        filmAB(mB, fb, aB, bB);
#pragma unroll
        for (int nt = 0; nt < 4; nt++) {
            int cc = n0 + wc * 32 + nt * 8 + 2 * lr;
            __nv_bfloat162 o0 = __floats2bfloat162_rn(fmaf(aA, acc[mt][nt][0], bA),
                                                      fmaf(aA, acc[mt][nt][1], bA));
            __nv_bfloat162 o1 = __floats2bfloat162_rn(fmaf(aB, acc[mt][nt][2], bB),
                                                      fmaf(aB, acc[mt][nt][3], bB));
            *(__nv_bfloat162*)&C[(size_t)mA * NPOS + cc] = o0;
            *(__nv_bfloat162*)&C[(size_t)mB * NPOS + cc] = o1;
        }
    }
}

// ================= ctx via mma (unchanged from R7) =================
#define KSE 520
__global__ void __launch_bounds__(256) ctx_mma() {
    extern __shared__ __nv_bfloat16 cs[];
    __nv_bfloat16* Ks = cs;
    __nv_bfloat16* Vs = cs + 32 * KSE;

    int b = blockIdx.z, h = blockIdx.y, chunk = blockIdx.x;
    int t = threadIdx.x;

    const __nv_bfloat16* Kg = g_qkvh + ((size_t)b * 384 + 128 + h * 32) * NPOS + chunk * 512;
    const __nv_bfloat16* Vg = Kg + (size_t)128 * NPOS;
    for (int i = t; i < 2048; i += 256) {
        int row = i >> 6, col = i & 63;
        *(uint4*)&Ks[row * KSE + col * 8] = *(const uint4*)(Kg + (size_t)row * NPOS + col * 8);
        *(uint4*)&Vs[row * KSE + col * 8] = *(const uint4*)(Vg + (size_t)row * NPOS + col * 8);
    }
    __syncthreads();

    int c = t >> 3, sub = t & 7;
    __nv_bfloat16* Kr = Ks + c * KSE + sub * 64;
    float m = -1e30f;
#pragma unroll
    for (int j4 = 0; j4 < 8; j4++) {
        uint4 kv = *(uint4*)&Kr[j4 * 8];
        __nv_bfloat162* kp = (__nv_bfloat162*)&kv;
#pragma unroll
        for (int p = 0; p < 4; p++) {
            float2 f = __bfloat1622float2(kp[p]);
            m = fmaxf(m, fmaxf(f.x, f.y));
        }
    }
#pragma unroll
    for (int o = 1; o < 8; o <<= 1) m = fmaxf(m, __shfl_xor_sync(0xffffffffu, m, o));

    float z = 0.f;
#pragma unroll
    for (int j4 = 0; j4 < 8; j4++) {
        uint4 kv = *(uint4*)&Kr[j4 * 8];
        __nv_bfloat162* kp = (__nv_bfloat162*)&kv;
        uint4 ev;
        __nv_bfloat162* ep = (__nv_bfloat162*)&ev;
#pragma unroll
        for (int p = 0; p < 4; p++) {
            float2 f = __bfloat1622float2(kp[p]);
            __nv_bfloat162 e2 = __floats2bfloat162_rn(__expf(f.x - m), __expf(f.y - m));
            ep[p] = e2;
            float2 ef = __bfloat1622float2(e2);
            z += ef.x + ef.y;
        }
        *(uint4*)&Kr[j4 * 8] = ev;
    }
#pragma unroll
    for (int o = 1; o < 8; o <<= 1) z += __shfl_xor_sync(0xffffffffu, z, o);
    if (sub == 0) g_Zp[((size_t)chunk * NB + b) * 128 + h * 32 + c] = z;
    if (sub == 1) g_Mx[((size_t)chunk * NB + b) * 128 + h * 32 + c] = m;
    __syncthreads();

    int w = t >> 5, lane = t & 31;
    int mrow = (w & 1) * 16, ncol = (w >> 1) * 8;
    uint32_t Eb = smem_u32(Ks), Vb = smem_u32(Vs);
    uint32_t aAddr = Eb + ((mrow + (lane & 15)) * KSE + ((lane >> 4) << 3)) * 2;
    uint32_t bAddr = Vb + ((ncol + (lane & 7)) * KSE + (((lane >> 3) & 3) << 3)) * 2;
    float acc[4] = {0.f, 0.f, 0.f, 0.f};
#pragma unroll 8
    for (int ks = 0; ks < 32; ks++) {
        uint32_t a[4], bb[2];
        ldm_x4(a, aAddr + ks * 32);
        ldm_x2(bb, bAddr + ks * 32);
        mma_bf16(acc, a, bb);
    }
    int lq = lane >> 2, lr = lane & 3;
    float* Sp = g_Sp + (((size_t)chunk * NB + b) * 4 + h) * 1024;
    Sp[(mrow + lq) * 32 + ncol + 2 * lr] = acc[0];
    Sp[(mrow + lq) * 32 + ncol + 2 * lr + 1] = acc[1];
    Sp[(mrow + lq + 8) * 32 + ncol + 2 * lr] = acc[2];
    Sp[(mrow + lq + 8) * 32 + ncol + 2 * lr + 1] = acc[3];
}

// ---------------- build M_b (unchanged from R7) ----------------
__global__ void buildM_kernel(const float* __restrict__ Wout) {
    int b = blockIdx.x, t = threadIdx.x;
    __shared__ float ctxs[4096];
    __shared__ float zsm[128];
    __shared__ float scl[NCHUNK * 128];
    if (t < 128) {
        float mloc[NCHUNK];
        float mg = -1e30f;
#pragma unroll
        for (int ch = 0; ch < NCHUNK; ch++) {
            mloc[ch] = g_Mx[((size_t)ch * NB + b) * 128 + t];
            mg = fmaxf(mg, mloc[ch]);
        }
        float zz = 0.f;
#pragma unroll
        for (int ch = 0; ch < NCHUNK; ch++) {
            float s = __expf(mloc[ch] - mg);
            scl[ch * 128 + t] = s;
            zz += g_Zp[((size_t)ch * NB + b) * 128 + t] * s;
        }
        zsm[t] = zz;
    }
    __syncthreads();
    for (int i = t; i < 4096; i += 256) {
        int h = i >> 10, c = (i >> 5) & 31;
        int chan = h * 32 + c;
        float s = 0.f;
#pragma unroll
        for (int ch = 0; ch < NCHUNK; ch++)
            s += g_Sp[((size_t)ch * NB + b) * 4096 + i] * scl[ch * 128 + chan];
        ctxs[i] = s / zsm[chan];
    }
    __syncthreads();
    const float* wr = Wout + t * 128;
    __nv_bfloat16* Mr = g_Mb + (size_t)b * 32768 + t * 128;
    for (int h = 0; h < 4; h++) {
        float w[32];
#pragma unroll
        for (int e = 0; e < 32; e++) w[e] = wr[h * 32 + e];
        for (int c2 = 0; c2 < 32; c2++) {
            float s = 0.f;
#pragma unroll
            for (int e = 0; e < 32; e++) s += w[e] * ctxs[h * 1024 + c2 * 32 + e];
            Mr[h * 32 + c2] = __float2bfloat16(s);
        }
    }
}

// ---------------- final v2: 512 threads, 128 cols/CTA, cp.async q+M, fused softmax+LN ----------------
// grid (32, NB). 16 warps in 4(m) x 4(n); warp tile 64 rows x 32 cols; K=128.
#define KW2 72                 // M row stride in words (64 data + 8 pad)
#define QHW 68                 // q raw row stride in words (64 data + 4 pad) -> 272B, 16B-aligned
#define FO_M   0               // 256*72 = 18432 words
#define FO_Q   18432           // Qsm: 128 cols * 72 = 9216 words
#define FO_T   27648           // qh raw: 128 rows * 68 = 8704 words
#define FO_B   36352           // 256
#define FO_G   36608           // 256
#define FO_WS  36864           // 16*32 = 512
#define FO_WQ  37376           // 512
#define FO_CS  37888           // 128
#define FO_CQ  38016           // 128
#define F_TOT  38144           // words = 152576 bytes

__global__ void __launch_bounds__(512) final_mma(const float* __restrict__ bout,
                                                 const float* __restrict__ gam,
                                                 float* __restrict__ out) {
    extern __shared__ uint32_t fsm[];
    uint32_t* Msm = fsm + FO_M;
    uint32_t* Qsm = fsm + FO_Q;
    uint16_t* qh = (uint16_t*)(fsm + FO_T);
    float* bsm = (float*)(fsm + FO_B);
    float* gsm = (float*)(fsm + FO_G);
    float* wsum = (float*)(fsm + FO_WS);
    float* wsq = (float*)(fsm + FO_WQ);
    float* csum = (float*)(fsm + FO_CS);
    float* csq = (float*)(fsm + FO_CQ);

    int b = blockIdx.y, n0 = blockIdx.x * 128, t = threadIdx.x;
    int lane = t & 31, w = t >> 5;
    int wm = w >> 2, wn = w & 3;
    int lq = lane >> 2, lr = lane & 3;

    // group 1: q raw tile (128 chans x 128 cols bf16) via cp.async
    const __nv_bfloat16* Qg = g_qkvh + (size_t)b * 384 * NPOS + n0;
#pragma unroll
    for (int j = 0; j < 4; j++) {
        int c = t + 512 * j;           // 2048 chunks of 16B
        int row = c >> 4, seg = c & 15;
        cpa16(smem_u32(&qh[row * 136 + seg * 8]), Qg + (size_t)row * NPOS + seg * 8);
    }
    CPA_COMMIT();
    // group 2: M tile (256 x 128 bf16)
    const __nv_bfloat16* Mg = g_Mb + (size_t)b * 32768;
#pragma unroll
    for (int j = 0; j < 8; j++) {
        int c = t + 512 * j;           // 4096 chunks of 16B
        int row = c >> 4, seg = c & 15;
        cpa16(smem_u32(&Msm[row * KW2 + seg * 4]), Mg + row * 128 + seg * 8);
    }
    CPA_COMMIT();

    if (t < 256) {
        bsm[t] = bout[t];
        gsm[t] = gam[t];
    }
    CPA_WAIT1();       // q ready (M may still be in flight)
    __syncthreads();

    // per-(head, col) softmax over 32 channels -> Qsm bf16 fragments
    {
        int h = t >> 7, col = t & 127;   // 4 heads x 128 cols = 512 threads
        float v[32];
        float mx = -1e30f;
#pragma unroll
        for (int i = 0; i < 32; i++) {
            uint16_t raw = qh[(h * 32 + i) * 136 + col];
            v[i] = __bfloat162float(*(__nv_bfloat16*)&raw);
            mx = fmaxf(mx, v[i]);
        }
        float ssum = 0.f;
#pragma unroll
        for (int i = 0; i < 32; i++) {
            v[i] = __expf(v[i] - mx);
            ssum += v[i];
        }
        float inv = SCALE / ssum;
#pragma unroll
        for (int i2 = 0; i2 < 16; i2++) {
            __nv_bfloat162 p = __floats2bfloat162_rn(v[2 * i2] * inv, v[2 * i2 + 1] * inv);
            Qsm[col * KW2 + h * 16 + i2] = *(uint32_t*)&p;
        }
    }
    CPA_WAIT0();       // M ready
    __syncthreads();

    float acc[4][4][4];
#pragma unroll
    for (int mt = 0; mt < 4; mt++)
#pragma unroll
        for (int nt = 0; nt < 4; nt++)
#pragma unroll
            for (int r = 0; r < 4; r++) acc[mt][nt][r] = 0.0f;

#pragma unroll
    for (int ks = 0; ks < 8; ks++) {
        int ksw = ks * 8;
        uint32_t af[4][4], bfr[4][2];
#pragma unroll
        for (int mt = 0; mt < 4; mt++) {
            int r0 = wm * 64 + mt * 16 + lq;
            af[mt][0] = Msm[r0 * KW2 + ksw + lr];
            af[mt][1] = Msm[(r0 + 8) * KW2 + ksw + lr];
            af[mt][2] = Msm[r0 * KW2 + ksw + lr + 4];
            af[mt][3] = Msm[(r0 + 8) * KW2 + ksw + lr + 4];
        }
#pragma unroll
        for (int nt = 0; nt < 4; nt++) {
            int n = wn * 32 + nt * 8 + lq;
            bfr[nt][0] = Qsm[n * KW2 + ksw + lr];
            bfr[nt][1] = Qsm[n * KW2 + ksw + lr + 4];
        }
#pragma unroll
        for (int mt = 0; mt < 4; mt++)
#pragma unroll
            for (int nt = 0; nt < 4; nt++) mma_bf16(acc[mt][nt], af[mt], bfr[nt]);
    }

    // + bias, per-column partial stats (thread covers 8 rows of its warp's 64)
    float ps[4][2], pq[4][2];
#pragma unroll
    for (int nt = 0; nt < 4; nt++)
#pragma unroll
        for (int j = 0; j < 2; j++) { ps[nt][j] = 0.f; pq[nt][j] = 0.f; }
#pragma unroll
    for (int mt = 0; mt < 4; mt++) {
        float b0v = bsm[wm * 64 + mt * 16 + lq];
        float b1v = bsm[wm * 64 + mt * 16 + lq + 8];
#pragma unroll
        for (int nt = 0; nt < 4; nt++) {
            acc[mt][nt][0] += b0v; acc[mt][nt][1] += b0v;
            acc[mt][nt][2] += b1v; acc[mt][nt][3] += b1v;
#pragma unroll
            for (int j = 0; j < 2; j++) {
                float v0 = acc[mt][nt][j], v1 = acc[mt][nt][2 + j];
                ps[nt][j] += v0 + v1;
                pq[nt][j] += v0 * v0 + v1 * v1;
            }
        }
    }
    // reduce over lq (lanes differing in bits 2..4, same lr)
#pragma unroll
    for (int nt = 0; nt < 4; nt++)
#pragma unroll
        for (int j = 0; j < 2; j++) {
#pragma unroll
            for (int o = 4; o <= 16; o <<= 1) {
                ps[nt][j] += __shfl_xor_sync(0xffffffffu, ps[nt][j], o);
                pq[nt][j] += __shfl_xor_sync(0xffffffffu, pq[nt][j], o);
            }
        }
    if (lq == 0) {
#pragma unroll
        for (int nt = 0; nt < 4; nt++)
#pragma unroll
            for (int j = 0; j < 2; j++) {
                wsum[w * 32 + nt * 8 + 2 * lr + j] = ps[nt][j];
                wsq[w * 32 + nt * 8 + 2 * lr + j] = pq[nt][j];
            }
    }
    __syncthreads();
    // combine the 4 m-warps per column group (deterministic fixed order)
    if (t < 128) {
        int wnc = t >> 5, cl = t & 31;
        float sx = 0.f, sq2 = 0.f;
#pragma unroll
        for (int k = 0; k < 4; k++) {
            sx += wsum[(k * 4 + wnc) * 32 + cl];
            sq2 += wsq[(k * 4 + wnc) * 32 + cl];
        }
        csum[t] = sx;
        csq[t] = sq2;
    }
    __syncthreads();

    float mean[4][2], rs[4][2];
#pragma unroll
    for (int nt = 0; nt < 4; nt++)
#pragma unroll
        for (int j = 0; j < 2; j++) {
            int cg = wn * 32 + nt * 8 + 2 * lr + j;
            float mu = csum[cg] * (1.0f / 256.0f);
            float var = csq[cg] * (1.0f / 256.0f) - mu * mu;
            mean[nt][j] = mu;
            rs[nt][j] = rsqrtf(var + 1e-5f);
        }
#pragma unroll
    for (int mt = 0; mt < 4; mt++) {
        int r0 = wm * 64 + mt * 16 + lq;
        float g0 = gsm[r0], g1 = gsm[r0 + 8];
#pragma unroll
        for (int nt = 0; nt < 4; nt++) {
            int cc = n0 + wn * 32 + nt * 8 + 2 * lr;
            float2 o0, o1;
            o0.x = (acc[mt][nt][0] - mean[nt][0]) * rs[nt][0] * g0;
            o0.y = (acc[mt][nt][1] - mean[nt][1]) * rs[nt][1] * g0;
            o1.x = (acc[mt][nt][2] - mean[nt][0]) * rs[nt][0] * g1;
            o1.y = (acc[mt][nt][3] - mean[nt][1]) * rs[nt][1] * g1;
            *(float2*)&out[((size_t)(b * 256 + r0)) * NPOS + cc] = o0;
            *(float2*)&out[((size_t)(b * 256 + r0 + 8)) * NPOS + cc] = o1;
        }
    }
}

// ---------------- launch ----------------
extern "C" void kernel_launch(void* const* d_in, const int* in_sizes, int n_in,
                              void* d_out, int out_size) {
    (void)in_sizes; (void)n_in; (void)out_size;
    const float* x = (const float*)d_in[0];
    const float* cond = (const float*)d_in[1];
    const float* W_qkv = (const float*)d_in[2];
    const float* W_cond = (const float*)d_in[3];
    const float* b_cond = (const float*)d_in[4];
    const float* W_out = (const float*)d_in[5];
    const float* b_out = (const float*)d_in[6];
    const float* g = (const float*)d_in[7];
    float* out = (float*)d_out;

    film_kernel<<<NB, 512>>>(cond, W_cond, b_cond);
    wconv_kernel<<<96, 1024>>>(W_qkv);
    qkv_mma<<<dim3(3, 32, NB), 256>>>(x);

    int ctx_smem = 2 * 32 * KSE * (int)sizeof(__nv_bfloat16);
    cudaFuncSetAttribute(ctx_mma, cudaFuncAttributeMaxDynamicSharedMemorySize, ctx_smem);
    ctx_mma<<<dim3(NCHUNK, 4, NB), 256, ctx_smem>>>();

    buildM_kernel<<<NB, 256>>>(W_out);

    int smbytes = F_TOT * (int)sizeof(uint32_t);
    cudaFuncSetAttribute(final_mma, cudaFuncAttributeMaxDynamicSharedMemorySize, smbytes);
    final_mma<<<dim3(32, NB), 512, smbytes>>>(b_out, g, out);
}

// round 9
// speedup vs baseline: 2.8544x; 1.1400x over previous
#include <cuda_runtime.h>
#include <cuda_bf16.h>
#include <cstdint>

#define NB 16
#define NPOS 4096
#define SCALE 0.17677669529663687f   // 32^-0.5
#define INVN (1.0f / 4096.0f)
#define NCHUNK 8

// ---------------- scratch (device globals; no runtime allocation) ----------------
__device__ __nv_bfloat16 g_qkvh[(size_t)NB * 384 * NPOS]; // q(raw)/k(FiLM)/v(FiLM,/n) bf16
__device__ __nv_bfloat16 g_xh[(size_t)NB * 256 * NPOS];   // X bf16, same [b][k][n] layout
__device__ float g_film[NB * 512];
__device__ float g_Sp[NCHUNK * NB * 4 * 32 * 32];
__device__ float g_Zp[NCHUNK * NB * 128];
__device__ float g_Mx[NCHUNK * NB * 128];
__device__ __nv_bfloat16 g_Mb[NB * 256 * 128];            // M_b bf16, k contiguous
__device__ __nv_bfloat16 g_wt[384 * 256];                 // W_qkv bf16, k contiguous

// ---------------- FiLM ----------------
__global__ void film_kernel(const float* __restrict__ cond,
                            const float* __restrict__ Wc,
                            const float* __restrict__ bc) {
    int b = blockIdx.x, t = threadIdx.x;
    __shared__ float sc[256];
    if (t < 256) {
        float xv = cond[b * 256 + t];
        sc[t] = xv / (1.0f + __expf(-xv));
    }
    __syncthreads();
    const float* wr = Wc + t * 256;
    float acc = bc[t];
#pragma unroll 8
    for (int j = 0; j < 256; j++) acc += wr[j] * sc[j];
    g_film[b * 512 + t] = acc;
}

__global__ void wconv_kernel(const float* __restrict__ W) {
    int i = blockIdx.x * 1024 + threadIdx.x;
    if (i < 384 * 256) g_wt[i] = __float2bfloat16(W[i]);
}

// X fp32 -> bf16, identity layout, vectorized
__global__ void xconv_kernel(const float* __restrict__ X) {
    size_t i = ((size_t)blockIdx.x * 256 + threadIdx.x) * 4;
    float4 v = *(const float4*)(X + i);
    __nv_bfloat162 p0 = __floats2bfloat162_rn(v.x, v.y);
    __nv_bfloat162 p1 = __floats2bfloat162_rn(v.z, v.w);
    uint2 u;
    u.x = *(uint32_t*)&p0;
    u.y = *(uint32_t*)&p1;
    *(uint2*)(g_xh + i) = u;
}

// ================= helpers =================
__device__ __forceinline__ uint32_t smem_u32(const void* p) {
    uint32_t a;
    asm("{ .reg .u64 t; cvta.to.shared.u64 t, %1; cvt.u32.u64 %0, t; }" : "=r"(a) : "l"(p));
    return a;
}
__device__ __forceinline__ void cpa16(uint32_t dst, const void* src) {
    asm volatile("cp.async.cg.shared.global [%0], [%1], 16;"
                 :: "r"(dst), "l"(__cvta_generic_to_global(src)));
}
#define CPA_COMMIT() asm volatile("cp.async.commit_group;" ::: "memory")
#define CPA_WAIT0()  asm volatile("cp.async.wait_group 0;" ::: "memory")
#define CPA_WAIT1()  asm volatile("cp.async.wait_group 1;" ::: "memory")

__device__ __forceinline__ void mma_bf16(float c[4], const uint32_t a[4], const uint32_t b[2]) {
    asm volatile(
        "mma.sync.aligned.m16n8k16.row.col.f32.bf16.bf16.f32 "
        "{%0,%1,%2,%3}, {%4,%5,%6,%7}, {%8,%9}, {%0,%1,%2,%3};\n"
        : "+f"(c[0]), "+f"(c[1]), "+f"(c[2]), "+f"(c[3])
        : "r"(a[0]), "r"(a[1]), "r"(a[2]), "r"(a[3]), "r"(b[0]), "r"(b[1]));
}
__device__ __forceinline__ void ldm_x4(uint32_t r[4], uint32_t addr) {
    asm volatile("ldmatrix.sync.aligned.m8n8.x4.shared.b16 {%0,%1,%2,%3}, [%4];"
                 : "=r"(r[0]), "=r"(r[1]), "=r"(r[2]), "=r"(r[3]) : "r"(addr));
}
__device__ __forceinline__ void ldm_x2(uint32_t r[2], uint32_t addr) {
    asm volatile("ldmatrix.sync.aligned.m8n8.x2.shared.b16 {%0,%1}, [%2];"
                 : "=r"(r[0]), "=r"(r[1]) : "r"(addr));
}
__device__ __forceinline__ void ldm_x4t(uint32_t& r0, uint32_t& r1, uint32_t& r2, uint32_t& r3,
                                        uint32_t addr) {
    asm volatile("ldmatrix.sync.aligned.m8n8.x4.trans.shared.b16 {%0,%1,%2,%3}, [%4];"
                 : "=r"(r0), "=r"(r1), "=r"(r2), "=r"(r3) : "r"(addr));
}
__device__ __forceinline__ void filmAB(int m, const float* __restrict__ fb,
                                       float& alpha, float& beta) {
    alpha = 1.0f; beta = 0.0f;
    if (m >= 256) {
        int c = m - 256;
        alpha = (1.0f + fb[256 + c]) * INVN;
        beta = fb[384 + c] * INVN;
    } else if (m >= 128) {
        int c = m - 128;
        alpha = 1.0f + fb[c];
        beta = fb[128 + c];
    }
}

// ================= qkv GEMM: 3-stage cp.async, all-bf16 operands =================
// Block 128m x 128n x 32k/stage. A smem rows 80B; B smem rows 272B. One commit group/stage.
#define QST 18944   // stage stride bytes = 10240 (A) + 8704 (B)
#define QKV_SMEM (3 * QST)

__global__ void __launch_bounds__(256, 2) qkv_mma(void) {
    extern __shared__ uint8_t qs[];
    uint32_t sb = smem_u32(qs);

    int b = blockIdx.z, grp = blockIdx.x;
    int m0 = grp * 128, n0 = blockIdx.y * 128;
    int t = threadIdx.x, lane = t & 31, w = t >> 5;
    int wr = w >> 2, wc = w & 3;
    int lq = lane >> 2, lr = lane & 3;

    float acc[4][4][4];
#pragma unroll
    for (int mt = 0; mt < 4; mt++)
#pragma unroll
        for (int nt = 0; nt < 4; nt++)
#pragma unroll
            for (int r = 0; r < 4; r++) acc[mt][nt][r] = 0.0f;

    // per-thread chunk mappings (2 A-chunks + 2 B-chunks of 16B per stage)
    int cA0 = 2 * t, cA1 = 2 * t + 1;
    int aR0 = cA0 >> 2, aS0 = cA0 & 3;     // A: 128 rows x 4 chunks
    int aR1 = cA1 >> 2, aS1 = cA1 & 3;
    int bR0 = cA0 >> 4, bS0 = cA0 & 15;    // B: 32 rows x 16 chunks
    int bR1 = cA1 >> 4, bS1 = cA1 & 15;
    const __nv_bfloat16* gA0 = g_wt + (size_t)(m0 + aR0) * 256 + aS0 * 8;
    const __nv_bfloat16* gA1 = g_wt + (size_t)(m0 + aR1) * 256 + aS1 * 8;
    const __nv_bfloat16* gB0 = g_xh + ((size_t)b * 256 + bR0) * NPOS + n0 + bS0 * 8;
    const __nv_bfloat16* gB1 = g_xh + ((size_t)b * 256 + bR1) * NPOS + n0 + bS1 * 8;
    uint32_t dA0 = aR0 * 80 + aS0 * 16, dA1 = aR1 * 80 + aS1 * 16;
    uint32_t dB0 = 10240 + bR0 * 272 + bS0 * 16, dB1 = 10240 + bR1 * 272 + bS1 * 16;

#define LOADSTAGE(s, k0)                                                   \
    {                                                                      \
        uint32_t stb = sb + (s) * QST;                                     \
        cpa16(stb + dA0, gA0 + (k0));                                      \
        cpa16(stb + dA1, gA1 + (k0));                                      \
        cpa16(stb + dB0, gB0 + (size_t)(k0) * NPOS);                       \
        cpa16(stb + dB1, gB1 + (size_t)(k0) * NPOS);                       \
        CPA_COMMIT();                                                      \
    }

    // fragment base offsets (bytes), same geometry as R6
    uint32_t aOff = (uint32_t)(wr * 64 + (lane & 15)) * 80 + ((lane >> 4) << 3) * 2;
    uint32_t bOff = 10240 + (uint32_t)(((lane >> 3) & 1) * 8 + (lane & 7)) * 272 +
                    (uint32_t)(wc * 32 + ((lane >> 4) << 3)) * 2;

    LOADSTAGE(0, 0);
    LOADSTAGE(1, 32);

    for (int kk = 0; kk < 8; kk++) {
        int st = kk % 3;
        if (kk < 7) { CPA_WAIT1(); } else { CPA_WAIT0(); }
        __syncthreads();
        if (kk + 2 < 8) LOADSTAGE((kk + 2) % 3, (kk + 2) * 32);
        uint32_t stb = sb + st * QST;
#pragma unroll
        for (int kh = 0; kh < 2; kh++) {
            uint32_t af[4][4];
#pragma unroll
            for (int mt = 0; mt < 4; mt++)
                ldm_x4(af[mt], stb + aOff + mt * 1280 + kh * 32);
            uint32_t bfr[4][2];
#pragma unroll
            for (int pr = 0; pr < 2; pr++) {
                uint32_t r0, r1, r2, r3;
                ldm_x4t(r0, r1, r2, r3, stb + bOff + kh * 4352 + pr * 32);
                bfr[2 * pr][0] = r0; bfr[2 * pr][1] = r1;
                bfr[2 * pr + 1][0] = r2; bfr[2 * pr + 1][1] = r3;
            }
#pragma unroll
            for (int mt = 0; mt < 4; mt++)
#pragma unroll
                for (int nt = 0; nt < 4; nt++) mma_bf16(acc[mt][nt], af[mt], bfr[nt]);
        }
    }

    // FiLM epilogue -> g_qkvh bf16
    const float* fb = g_film + b * 512;
    __nv_bfloat16* C = g_qkvh + (size_t)b * 384 * NPOS;
#pragma unroll
    for (int mt = 0; mt < 4; mt++) {
        int mA = m0 + wr * 64 + mt * 16 + lq;
        int mB = mA + 8;
        float aA, bA, aB, bB;
        filmAB(mA, fb, aA, bA);
        filmAB(mB, fb, aB, bB);
#pragma unroll
        for (int nt = 0; nt < 4; nt++) {
            int cc = n0 + wc * 32 + nt * 8 + 2 * lr;
            __nv_bfloat162 o0 = __floats2bfloat162_rn(fmaf(aA, acc[mt][nt][0], bA),
                                                      fmaf(aA, acc[mt][nt][1], bA));
            __nv_bfloat162 o1 = __floats2bfloat162_rn(fmaf(aB, acc[mt][nt][2], bB),
                                                      fmaf(aB, acc[mt][nt][3], bB));
            *(__nv_bfloat162*)&C[(size_t)mA * NPOS + cc] = o0;
            *(__nv_bfloat162*)&C[(size_t)mB * NPOS + cc] = o1;
        }
    }
}

// ================= ctx via mma (unchanged) =================
#define KSE 520
__global__ void __launch_bounds__(256) ctx_mma() {
    extern __shared__ __nv_bfloat16 cs[];
    __nv_bfloat16* Ks = cs;
    __nv_bfloat16* Vs = cs + 32 * KSE;

    int b = blockIdx.z, h = blockIdx.y, chunk = blockIdx.x;
    int t = threadIdx.x;

    const __nv_bfloat16* Kg = g_qkvh + ((size_t)b * 384 + 128 + h * 32) * NPOS + chunk * 512;
    const __nv_bfloat16* Vg = Kg + (size_t)128 * NPOS;
    for (int i = t; i < 2048; i += 256) {
        int row = i >> 6, col = i & 63;
        *(uint4*)&Ks[row * KSE + col * 8] = *(const uint4*)(Kg + (size_t)row * NPOS + col * 8);
        *(uint4*)&Vs[row * KSE + col * 8] = *(const uint4*)(Vg + (size_t)row * NPOS + col * 8);
    }
    __syncthreads();

    int c = t >> 3, sub = t & 7;
    __nv_bfloat16* Kr = Ks + c * KSE + sub * 64;
    float m = -1e30f;
#pragma unroll
    for (int j4 = 0; j4 < 8; j4++) {
        uint4 kv = *(uint4*)&Kr[j4 * 8];
        __nv_bfloat162* kp = (__nv_bfloat162*)&kv;
#pragma unroll
        for (int p = 0; p < 4; p++) {
            float2 f = __bfloat1622float2(kp[p]);
            m = fmaxf(m, fmaxf(f.x, f.y));
        }
    }
#pragma unroll
    for (int o = 1; o < 8; o <<= 1) m = fmaxf(m, __shfl_xor_sync(0xffffffffu, m, o));

    float z = 0.f;
#pragma unroll
    for (int j4 = 0; j4 < 8; j4++) {
        uint4 kv = *(uint4*)&Kr[j4 * 8];
        __nv_bfloat162* kp = (__nv_bfloat162*)&kv;
        uint4 ev;
        __nv_bfloat162* ep = (__nv_bfloat162*)&ev;
#pragma unroll
        for (int p = 0; p < 4; p++) {
            float2 f = __bfloat1622float2(kp[p]);
            __nv_bfloat162 e2 = __floats2bfloat162_rn(__expf(f.x - m), __expf(f.y - m));
            ep[p] = e2;
            float2 ef = __bfloat1622float2(e2);
            z += ef.x + ef.y;
        }
        *(uint4*)&Kr[j4 * 8] = ev;
    }
#pragma unroll
    for (int o = 1; o < 8; o <<= 1) z += __shfl_xor_sync(0xffffffffu, z, o);
    if (sub == 0) g_Zp[((size_t)chunk * NB + b) * 128 + h * 32 + c] = z;
    if (sub == 1) g_Mx[((size_t)chunk * NB + b) * 128 + h * 32 + c] = m;
    __syncthreads();

    int w = t >> 5, lane = t & 31;
    int mrow = (w & 1) * 16, ncol = (w >> 1) * 8;
    uint32_t Eb = smem_u32(Ks), Vb = smem_u32(Vs);
    uint32_t aAddr = Eb + ((mrow + (lane & 15)) * KSE + ((lane >> 4) << 3)) * 2;
    uint32_t bAddr = Vb + ((ncol + (lane & 7)) * KSE + (((lane >> 3) & 3) << 3)) * 2;
    float acc[4] = {0.f, 0.f, 0.f, 0.f};
#pragma unroll 8
    for (int ks = 0; ks < 32; ks++) {
        uint32_t a[4], bb[2];
        ldm_x4(a, aAddr + ks * 32);
        ldm_x2(bb, bAddr + ks * 32);
        mma_bf16(acc, a, bb);
    }
    int lq = lane >> 2, lr = lane & 3;
    float* Sp = g_Sp + (((size_t)chunk * NB + b) * 4 + h) * 1024;
    Sp[(mrow + lq) * 32 + ncol + 2 * lr] = acc[0];
    Sp[(mrow + lq) * 32 + ncol + 2 * lr + 1] = acc[1];
    Sp[(mrow + lq + 8) * 32 + ncol + 2 * lr] = acc[2];
    Sp[(mrow + lq + 8) * 32 + ncol + 2 * lr + 1] = acc[3];
}

// ---------------- build M_b: 64 CTAs (4 row-segments x batch) ----------------
__global__ void buildM_kernel(const float* __restrict__ Wout) {
    int seg = blockIdx.x, b = blockIdx.y, t = threadIdx.x;
    __shared__ float ctxs[4096];
    __shared__ float zsm[128];
    __shared__ float scl[NCHUNK * 128];
    if (t < 128) {
        float mloc[NCHUNK];
        float mg = -1e30f;
#pragma unroll
        for (int ch = 0; ch < NCHUNK; ch++) {
            mloc[ch] = g_Mx[((size_t)ch * NB + b) * 128 + t];
            mg = fmaxf(mg, mloc[ch]);
        }
        float zz = 0.f;
#pragma unroll
        for (int ch = 0; ch < NCHUNK; ch++) {
            float s = __expf(mloc[ch] - mg);
            scl[ch * 128 + t] = s;
            zz += g_Zp[((size_t)ch * NB + b) * 128 + t] * s;
        }
        zsm[t] = zz;
    }
    __syncthreads();
    for (int i = t; i < 4096; i += 256) {
        int h = i >> 10, c = (i >> 5) & 31;
        int chan = h * 32 + c;
        float s = 0.f;
#pragma unroll
        for (int ch = 0; ch < NCHUNK; ch++)
            s += g_Sp[((size_t)ch * NB + b) * 4096 + i] * scl[ch * 128 + chan];
        ctxs[i] = s / zsm[chan];
    }
    __syncthreads();
    // 256 threads: row = seg*64 + (t & 63), head g = t >> 6
    int row = seg * 64 + (t & 63);
    int g = t >> 6;
    const float* wr = Wout + row * 128 + g * 32;
    float wv[32];
#pragma unroll
    for (int e = 0; e < 32; e++) wv[e] = wr[e];
    __nv_bfloat16* Mr = g_Mb + (size_t)b * 32768 + row * 128 + g * 32;
    for (int c2 = 0; c2 < 32; c2++) {
        float s = 0.f;
#pragma unroll
        for (int e = 0; e < 32; e++) s += wv[e] * ctxs[g * 1024 + c2 * 32 + e];
        Mr[c2] = __float2bfloat16(s);
    }
}

// ---------------- final v2 (unchanged from R8) ----------------
#define KW2 72
#define FO_M   0
#define FO_Q   18432
#define FO_T   27648
#define FO_B   36352
#define FO_G   36608
#define FO_WS  36864
#define FO_WQ  37376
#define FO_CS  37888
#define FO_CQ  38016
#define F_TOT  38144

__global__ void __launch_bounds__(512) final_mma(const float* __restrict__ bout,
                                                 const float* __restrict__ gam,
                                                 float* __restrict__ out) {
    extern __shared__ uint32_t fsm[];
    uint32_t* Msm = fsm + FO_M;
    uint32_t* Qsm = fsm + FO_Q;
    uint16_t* qh = (uint16_t*)(fsm + FO_T);
    float* bsm = (float*)(fsm + FO_B);
    float* gsm = (float*)(fsm + FO_G);
    float* wsum = (float*)(fsm + FO_WS);
    float* wsq = (float*)(fsm + FO_WQ);
    float* csum = (float*)(fsm + FO_CS);
    float* csq = (float*)(fsm + FO_CQ);

    int b = blockIdx.y, n0 = blockIdx.x * 128, t = threadIdx.x;
    int lane = t & 31, w = t >> 5;
    int wm = w >> 2, wn = w & 3;
    int lq = lane >> 2, lr = lane & 3;

    const __nv_bfloat16* Qg = g_qkvh + (size_t)b * 384 * NPOS + n0;
#pragma unroll
    for (int j = 0; j < 4; j++) {
        int c = t + 512 * j;
        int row = c >> 4, seg = c & 15;
        cpa16(smem_u32(&qh[row * 136 + seg * 8]), Qg + (size_t)row * NPOS + seg * 8);
    }
    CPA_COMMIT();
    const __nv_bfloat16* Mg = g_Mb + (size_t)b * 32768;
#pragma unroll
    for (int j = 0; j < 8; j++) {
        int c = t + 512 * j;
        int row = c >> 4, seg = c & 15;
        cpa16(smem_u32(&Msm[row * KW2 + seg * 4]), Mg + row * 128 + seg * 8);
    }
    CPA_COMMIT();

    if (t < 256) {
        bsm[t] = bout[t];
        gsm[t] = gam[t];
    }
    CPA_WAIT1();
    __syncthreads();

    {
        int h = t >> 7, col = t & 127;
        float v[32];
        float mx = -1e30f;
#pragma unroll
        for (int i = 0; i < 32; i++) {
            uint16_t raw = qh[(h * 32 + i) * 136 + col];
            v[i] = __bfloat162float(*(__nv_bfloat16*)&raw);
            mx = fmaxf(mx, v[i]);
        }
        float ssum = 0.f;
#pragma unroll
        for (int i = 0; i < 32; i++) {
            v[i] = __expf(v[i] - mx);
            ssum += v[i];
        }
        float inv = SCALE / ssum;
#pragma unroll
        for (int i2 = 0; i2 < 16; i2++) {
            __nv_bfloat162 p = __floats2bfloat162_rn(v[2 * i2] * inv, v[2 * i2 + 1] * inv);
            Qsm[col * KW2 + h * 16 + i2] = *(uint32_t*)&p;
        }
    }
    CPA_WAIT0();
    __syncthreads();

    float acc[4][4][4];
#pragma unroll
    for (int mt = 0; mt < 4; mt++)
#pragma unroll
        for (int nt = 0; nt < 4; nt++)
#pragma unroll
            for (int r = 0; r < 4; r++) acc[mt][nt][r] = 0.0f;

#pragma unroll
    for (int ks = 0; ks < 8; ks++) {
        int ksw = ks * 8;
        uint32_t af[4][4], bfr[4][2];
#pragma unroll
        for (int mt = 0; mt < 4; mt++) {
            int r0 = wm * 64 + mt * 16 + lq;
            af[mt][0] = Msm[r0 * KW2 + ksw + lr];
            af[mt][1] = Msm[(r0 + 8) * KW2 + ksw + lr];
            af[mt][2] = Msm[r0 * KW2 + ksw + lr + 4];
            af[mt][3] = Msm[(r0 + 8) * KW2 + ksw + lr + 4];
        }
#pragma unroll
        for (int nt = 0; nt < 4; nt++) {
            int n = wn * 32 + nt * 8 + lq;
            bfr[nt][0] = Qsm[n * KW2 + ksw + lr];
            bfr[nt][1] = Qsm[n * KW2 + ksw + lr + 4];
        }
#pragma unroll
        for (int mt = 0; mt < 4; mt++)
#pragma unroll
            for (int nt = 0; nt < 4; nt++) mma_bf16(acc[mt][nt], af[mt], bfr[nt]);
    }

    float ps[4][2], pq[4][2];
#pragma unroll
    for (int nt = 0; nt < 4; nt++)
#pragma unroll
        for (int j = 0; j < 2; j++) { ps[nt][j] = 0.f; pq[nt][j] = 0.f; }
#pragma unroll
    for (int mt = 0; mt < 4; mt++) {
        float b0v = bsm[wm * 64 + mt * 16 + lq];
        float b1v = bsm[wm * 64 + mt * 16 + lq + 8];
#pragma unroll
        for (int nt = 0; nt < 4; nt++) {
            acc[mt][nt][0] += b0v; acc[mt][nt][1] += b0v;
            acc[mt][nt][2] += b1v; acc[mt][nt][3] += b1v;
#pragma unroll
            for (int j = 0; j < 2; j++) {
                float v0 = acc[mt][nt][j], v1 = acc[mt][nt][2 + j];
                ps[nt][j] += v0 + v1;
                pq[nt][j] += v0 * v0 + v1 * v1;
            }
        }
    }
#pragma unroll
    for (int nt = 0; nt < 4; nt++)
#pragma unroll
        for (int j = 0; j < 2; j++) {
#pragma unroll
            for (int o = 4; o <= 16; o <<= 1) {
                ps[nt][j] += __shfl_xor_sync(0xffffffffu, ps[nt][j], o);
                pq[nt][j] += __shfl_xor_sync(0xffffffffu, pq[nt][j], o);
            }
        }
    if (lq == 0) {
#pragma unroll
        for (int nt = 0; nt < 4; nt++)
#pragma unroll
            for (int j = 0; j < 2; j++) {
                wsum[w * 32 + nt * 8 + 2 * lr + j] = ps[nt][j];
                wsq[w * 32 + nt * 8 + 2 * lr + j] = pq[nt][j];
            }
    }
    __syncthreads();
    if (t < 128) {
        int wnc = t >> 5, cl = t & 31;
        float sx = 0.f, sq2 = 0.f;
#pragma unroll
        for (int k = 0; k < 4; k++) {
            sx += wsum[(k * 4 + wnc) * 32 + cl];
            sq2 += wsq[(k * 4 + wnc) * 32 + cl];
        }
        csum[t] = sx;
        csq[t] = sq2;
    }
    __syncthreads();

    float mean[4][2], rs[4][2];
#pragma unroll
    for (int nt = 0; nt < 4; nt++)
#pragma unroll
        for (int j = 0; j < 2; j++) {
            int cg = wn * 32 + nt * 8 + 2 * lr + j;
            float mu = csum[cg] * (1.0f / 256.0f);
            float var = csq[cg] * (1.0f / 256.0f) - mu * mu;
            mean[nt][j] = mu;
            rs[nt][j] = rsqrtf(var + 1e-5f);
        }
#pragma unroll
    for (int mt = 0; mt < 4; mt++) {
        int r0 = wm * 64 + mt * 16 + lq;
        float g0 = gsm[r0], g1 = gsm[r0 + 8];
#pragma unroll
        for (int nt = 0; nt < 4; nt++) {
            int cc = n0 + wn * 32 + nt * 8 + 2 * lr;
            float2 o0, o1;
            o0.x = (acc[mt][nt][0] - mean[nt][0]) * rs[nt][0] * g0;
            o0.y = (acc[mt][nt][1] - mean[nt][1]) * rs[nt][1] * g0;
            o1.x = (acc[mt][nt][2] - mean[nt][0]) * rs[nt][0] * g1;
            o1.y = (acc[mt][nt][3] - mean[nt][1]) * rs[nt][1] * g1;
            *(float2*)&out[((size_t)(b * 256 + r0)) * NPOS + cc] = o0;
            *(float2*)&out[((size_t)(b * 256 + r0 + 8)) * NPOS + cc] = o1;
        }
    }
}

// ---------------- launch ----------------
extern "C" void kernel_launch(void* const* d_in, const int* in_sizes, int n_in,
                              void* d_out, int out_size) {
    (void)in_sizes; (void)n_in; (void)out_size;
    const float* x = (const float*)d_in[0];
    const float* cond = (const float*)d_in[1];
    const float* W_qkv = (const float*)d_in[2];
    const float* W_cond = (const float*)d_in[3];
    const float* b_cond = (const float*)d_in[4];
    const float* W_out = (const float*)d_in[5];
    const float* b_out = (const float*)d_in[6];
    const float* g = (const float*)d_in[7];
    float* out = (float*)d_out;

    film_kernel<<<NB, 512>>>(cond, W_cond, b_cond);
    wconv_kernel<<<96, 1024>>>(W_qkv);
    xconv_kernel<<<(NB * 256 * NPOS) / 1024, 256>>>(x);

    cudaFuncSetAttribute(qkv_mma, cudaFuncAttributeMaxDynamicSharedMemorySize, QKV_SMEM);
    qkv_mma<<<dim3(3, 32, NB), 256, QKV_SMEM>>>();

    int ctx_smem = 2 * 32 * KSE * (int)sizeof(__nv_bfloat16);
    cudaFuncSetAttribute(ctx_mma, cudaFuncAttributeMaxDynamicSharedMemorySize, ctx_smem);
    ctx_mma<<<dim3(NCHUNK, 4, NB), 256, ctx_smem>>>();

    buildM_kernel<<<dim3(4, NB), 256>>>(W_out);

    int smbytes = F_TOT * (int)sizeof(uint32_t);
    cudaFuncSetAttribute(final_mma, cudaFuncAttributeMaxDynamicSharedMemorySize, smbytes);
    final_mma<<<dim3(32, NB), 512, smbytes>>>(b_out, g, out);
}

// round 10
// speedup vs baseline: 2.8978x; 1.0152x over previous
#include <cuda_runtime.h>
#include <cuda_bf16.h>
#include <cstdint>

#define NB 16
#define NPOS 4096
#define SCALE 0.17677669529663687f   // 32^-0.5
#define INVN (1.0f / 4096.0f)
#define NCHUNK 8

// ---------------- scratch (device globals; no runtime allocation) ----------------
__device__ __nv_bfloat16 g_qkvh[(size_t)NB * 384 * NPOS]; // q(raw)/k(FiLM)/v(FiLM,/n) bf16
__device__ __nv_bfloat16 g_xh[(size_t)NB * 256 * NPOS];   // X bf16, same [b][k][n] layout
__device__ float g_film[NB * 512];
__device__ float g_Sp[NCHUNK * NB * 4 * 32 * 32];
__device__ float g_Zp[NCHUNK * NB * 128];
__device__ __nv_bfloat16 g_Mb[NB * 256 * 128];            // M_b bf16, k contiguous
__device__ __nv_bfloat16 g_wt[384 * 256];                 // W_qkv bf16, k contiguous

// ---------------- FiLM ----------------
__global__ void film_kernel(const float* __restrict__ cond,
                            const float* __restrict__ Wc,
                            const float* __restrict__ bc) {
    int b = blockIdx.x, t = threadIdx.x;
    __shared__ float sc[256];
    if (t < 256) {
        float xv = cond[b * 256 + t];
        sc[t] = xv / (1.0f + __expf(-xv));
    }
    __syncthreads();
    const float* wr = Wc + t * 256;
    float acc = bc[t];
#pragma unroll 8
    for (int j = 0; j < 256; j++) acc += wr[j] * sc[j];
    g_film[b * 512 + t] = acc;
}

__global__ void wconv_kernel(const float* __restrict__ W) {
    int i = blockIdx.x * 1024 + threadIdx.x;
    if (i < 384 * 256) g_wt[i] = __float2bfloat16(W[i]);
}

// X fp32 -> bf16, identity layout, vectorized
__global__ void xconv_kernel(const float* __restrict__ X) {
    size_t i = ((size_t)blockIdx.x * 256 + threadIdx.x) * 4;
    float4 v = *(const float4*)(X + i);
    __nv_bfloat162 p0 = __floats2bfloat162_rn(v.x, v.y);
    __nv_bfloat162 p1 = __floats2bfloat162_rn(v.z, v.w);
    uint2 u;
    u.x = *(uint32_t*)&p0;
    u.y = *(uint32_t*)&p1;
    *(uint2*)(g_xh + i) = u;
}

// ================= helpers =================
__device__ __forceinline__ uint32_t smem_u32(const void* p) {
    uint32_t a;
    asm("{ .reg .u64 t; cvta.to.shared.u64 t, %1; cvt.u32.u64 %0, t; }" : "=r"(a) : "l"(p));
    return a;
}
__device__ __forceinline__ void cpa16(uint32_t dst, const void* src) {
    asm volatile("cp.async.cg.shared.global [%0], [%1], 16;"
                 :: "r"(dst), "l"(__cvta_generic_to_global(src)));
}
#define CPA_COMMIT() asm volatile("cp.async.commit_group;" ::: "memory")
#define CPA_WAIT0()  asm volatile("cp.async.wait_group 0;" ::: "memory")
#define CPA_WAIT1()  asm volatile("cp.async.wait_group 1;" ::: "memory")
#define CPA_WAIT2()  asm volatile("cp.async.wait_group 2;" ::: "memory")

__device__ __forceinline__ void mma_bf16(float c[4], const uint32_t a[4], const uint32_t b[2]) {
    asm volatile(
        "mma.sync.aligned.m16n8k16.row.col.f32.bf16.bf16.f32 "
        "{%0,%1,%2,%3}, {%4,%5,%6,%7}, {%8,%9}, {%0,%1,%2,%3};\n"
        : "+f"(c[0]), "+f"(c[1]), "+f"(c[2]), "+f"(c[3])
        : "r"(a[0]), "r"(a[1]), "r"(a[2]), "r"(a[3]), "r"(b[0]), "r"(b[1]));
}
__device__ __forceinline__ void ldm_x4(uint32_t r[4], uint32_t addr) {
    asm volatile("ldmatrix.sync.aligned.m8n8.x4.shared.b16 {%0,%1,%2,%3}, [%4];"
                 : "=r"(r[0]), "=r"(r[1]), "=r"(r[2]), "=r"(r[3]) : "r"(addr));
}
__device__ __forceinline__ void ldm_x2(uint32_t r[2], uint32_t addr) {
    asm volatile("ldmatrix.sync.aligned.m8n8.x2.shared.b16 {%0,%1}, [%2];"
                 : "=r"(r[0]), "=r"(r[1]) : "r"(addr));
}
__device__ __forceinline__ void ldm_x4t(uint32_t& r0, uint32_t& r1, uint32_t& r2, uint32_t& r3,
                                        uint32_t addr) {
    asm volatile("ldmatrix.sync.aligned.m8n8.x4.trans.shared.b16 {%0,%1,%2,%3}, [%4];"
                 : "=r"(r0), "=r"(r1), "=r"(r2), "=r"(r3) : "r"(addr));
}
__device__ __forceinline__ void filmAB(int m, const float* __restrict__ fb,
                                       float& alpha, float& beta) {
    alpha = 1.0f; beta = 0.0f;
    if (m >= 256) {
        int c = m - 256;
        alpha = (1.0f + fb[256 + c]) * INVN;
        beta = fb[384 + c] * INVN;
    } else if (m >= 128) {
        int c = m - 128;
        alpha = 1.0f + fb[c];
        beta = fb[128 + c];
    }
}

// ================= qkv GEMM: 4-stage cp.async, all-bf16 operands =================
#define QST 18944   // stage stride bytes = 10240 (A) + 8704 (B)
#define QKV_SMEM (4 * QST)

__global__ void __launch_bounds__(256, 2) qkv_mma(void) {
    extern __shared__ uint8_t qs[];
    uint32_t sb = smem_u32(qs);

    int b = blockIdx.z, grp = blockIdx.x;
    int m0 = grp * 128, n0 = blockIdx.y * 128;
    int t = threadIdx.x, lane = t & 31, w = t >> 5;
    int wr = w >> 2, wc = w & 3;
    int lq = lane >> 2, lr = lane & 3;

    float acc[4][4][4];
#pragma unroll
    for (int mt = 0; mt < 4; mt++)
#pragma unroll
        for (int nt = 0; nt < 4; nt++)
#pragma unroll
            for (int r = 0; r < 4; r++) acc[mt][nt][r] = 0.0f;

    int cA0 = 2 * t, cA1 = 2 * t + 1;
    int aR0 = cA0 >> 2, aS0 = cA0 & 3;
    int aR1 = cA1 >> 2, aS1 = cA1 & 3;
    int bR0 = cA0 >> 4, bS0 = cA0 & 15;
    int bR1 = cA1 >> 4, bS1 = cA1 & 15;
    const __nv_bfloat16* gA0 = g_wt + (size_t)(m0 + aR0) * 256 + aS0 * 8;
    const __nv_bfloat16* gA1 = g_wt + (size_t)(m0 + aR1) * 256 + aS1 * 8;
    const __nv_bfloat16* gB0 = g_xh + ((size_t)b * 256 + bR0) * NPOS + n0 + bS0 * 8;
    const __nv_bfloat16* gB1 = g_xh + ((size_t)b * 256 + bR1) * NPOS + n0 + bS1 * 8;
    uint32_t dA0 = aR0 * 80 + aS0 * 16, dA1 = aR1 * 80 + aS1 * 16;
    uint32_t dB0 = 10240 + bR0 * 272 + bS0 * 16, dB1 = 10240 + bR1 * 272 + bS1 * 16;

#define LOADSTAGE(s, k0)                                                   \
    {                                                                      \
        uint32_t stb = sb + (s) * QST;                                     \
        cpa16(stb + dA0, gA0 + (k0));                                      \
        cpa16(stb + dA1, gA1 + (k0));                                      \
        cpa16(stb + dB0, gB0 + (size_t)(k0) * NPOS);                       \
        cpa16(stb + dB1, gB1 + (size_t)(k0) * NPOS);                       \
        CPA_COMMIT();                                                      \
    }

    uint32_t aOff = (uint32_t)(wr * 64 + (lane & 15)) * 80 + ((lane >> 4) << 3) * 2;
    uint32_t bOff = 10240 + (uint32_t)(((lane >> 3) & 1) * 8 + (lane & 7)) * 272 +
                    (uint32_t)(wc * 32 + ((lane >> 4) << 3)) * 2;

    LOADSTAGE(0, 0);
    LOADSTAGE(1, 32);
    LOADSTAGE(2, 64);

    for (int kk = 0; kk < 8; kk++) {
        int st = kk & 3;
        if (kk <= 5) { CPA_WAIT2(); } else if (kk == 6) { CPA_WAIT1(); } else { CPA_WAIT0(); }
        __syncthreads();
        if (kk + 3 < 8) LOADSTAGE((kk + 3) & 3, (kk + 3) * 32);
        uint32_t stb = sb + st * QST;
#pragma unroll
        for (int kh = 0; kh < 2; kh++) {
            uint32_t af[4][4];
#pragma unroll
            for (int mt = 0; mt < 4; mt++)
                ldm_x4(af[mt], stb + aOff + mt * 1280 + kh * 32);
            uint32_t bfr[4][2];
#pragma unroll
            for (int pr = 0; pr < 2; pr++) {
                uint32_t r0, r1, r2, r3;
                ldm_x4t(r0, r1, r2, r3, stb + bOff + kh * 4352 + pr * 32);
                bfr[2 * pr][0] = r0; bfr[2 * pr][1] = r1;
                bfr[2 * pr + 1][0] = r2; bfr[2 * pr + 1][1] = r3;
            }
#pragma unroll
            for (int mt = 0; mt < 4; mt++)
#pragma unroll
                for (int nt = 0; nt < 4; nt++) mma_bf16(acc[mt][nt], af[mt], bfr[nt]);
        }
    }

    const float* fb = g_film + b * 512;
    __nv_bfloat16* C = g_qkvh + (size_t)b * 384 * NPOS;
#pragma unroll
    for (int mt = 0; mt < 4; mt++) {
        int mA = m0 + wr * 64 + mt * 16 + lq;
        int mB = mA + 8;
        float aA, bA, aB, bB;
        filmAB(mA, fb, aA, bA);
        filmAB(mB, fb, aB, bB);
#pragma unroll
        for (int nt = 0; nt < 4; nt++) {
            int cc = n0 + wc * 32 + nt * 8 + 2 * lr;
            __nv_bfloat162 o0 = __floats2bfloat162_rn(fmaf(aA, acc[mt][nt][0], bA),
                                                      fmaf(aA, acc[mt][nt][1], bA));
            __nv_bfloat162 o1 = __floats2bfloat162_rn(fmaf(aB, acc[mt][nt][2], bB),
                                                      fmaf(aB, acc[mt][nt][3], bB));
            *(__nv_bfloat162*)&C[(size_t)mA * NPOS + cc] = o0;
            *(__nv_bfloat162*)&C[(size_t)mB * NPOS + cc] = o1;
        }
    }
}

// ================= ctx via mma: no-max softmax (|k| <= ~6, exp safe), S = E @ V^T ========
#define KSE 520
__global__ void __launch_bounds__(256) ctx_mma() {
    extern __shared__ __nv_bfloat16 cs[];
    __nv_bfloat16* Ks = cs;
    __nv_bfloat16* Vs = cs + 32 * KSE;

    int b = blockIdx.z, h = blockIdx.y, chunk = blockIdx.x;
    int t = threadIdx.x;

    const __nv_bfloat16* Kg = g_qkvh + ((size_t)b * 384 + 128 + h * 32) * NPOS + chunk * 512;
    const __nv_bfloat16* Vg = Kg + (size_t)128 * NPOS;
    for (int i = t; i < 2048; i += 256) {
        int row = i >> 6, col = i & 63;
        *(uint4*)&Ks[row * KSE + col * 8] = *(const uint4*)(Kg + (size_t)row * NPOS + col * 8);
        *(uint4*)&Vs[row * KSE + col * 8] = *(const uint4*)(Vg + (size_t)row * NPOS + col * 8);
    }
    __syncthreads();

    // single pass: E = exp(k) in place (bf16), z = sum E
    int c = t >> 3, sub = t & 7;
    __nv_bfloat16* Kr = Ks + c * KSE + sub * 64;
    float z = 0.f;
#pragma unroll
    for (int j4 = 0; j4 < 8; j4++) {
        uint4 kv = *(uint4*)&Kr[j4 * 8];
        __nv_bfloat162* kp = (__nv_bfloat162*)&kv;
        uint4 ev;
        __nv_bfloat162* ep = (__nv_bfloat162*)&ev;
#pragma unroll
        for (int p = 0; p < 4; p++) {
            float2 f = __bfloat1622float2(kp[p]);
            __nv_bfloat162 e2 = __floats2bfloat162_rn(__expf(f.x), __expf(f.y));
            ep[p] = e2;
            float2 ef = __bfloat1622float2(e2);
            z += ef.x + ef.y;
        }
        *(uint4*)&Kr[j4 * 8] = ev;
    }
#pragma unroll
    for (int o = 1; o < 8; o <<= 1) z += __shfl_xor_sync(0xffffffffu, z, o);
    if (sub == 0) g_Zp[((size_t)chunk * NB + b) * 128 + h * 32 + c] = z;
    __syncthreads();

    int w = t >> 5, lane = t & 31;
    int mrow = (w & 1) * 16, ncol = (w >> 1) * 8;
    uint32_t Eb = smem_u32(Ks), Vb = smem_u32(Vs);
    uint32_t aAddr = Eb + ((mrow + (lane & 15)) * KSE + ((lane >> 4) << 3)) * 2;
    uint32_t bAddr = Vb + ((ncol + (lane & 7)) * KSE + (((lane >> 3) & 3) << 3)) * 2;
    float acc[4] = {0.f, 0.f, 0.f, 0.f};
#pragma unroll 8
    for (int ks = 0; ks < 32; ks++) {
        uint32_t a[4], bb[2];
        ldm_x4(a, aAddr + ks * 32);
        ldm_x2(bb, bAddr + ks * 32);
        mma_bf16(acc, a, bb);
    }
    int lq = lane >> 2, lr = lane & 3;
    float* Sp = g_Sp + (((size_t)chunk * NB + b) * 4 + h) * 1024;
    Sp[(mrow + lq) * 32 + ncol + 2 * lr] = acc[0];
    Sp[(mrow + lq) * 32 + ncol + 2 * lr + 1] = acc[1];
    Sp[(mrow + lq + 8) * 32 + ncol + 2 * lr] = acc[2];
    Sp[(mrow + lq + 8) * 32 + ncol + 2 * lr + 1] = acc[3];
}

// ---------------- build M_b: 64 CTAs (4 row-segments x batch), no rescale ----------------
__global__ void buildM_kernel(const float* __restrict__ Wout) {
    int seg = blockIdx.x, b = blockIdx.y, t = threadIdx.x;
    __shared__ float ctxs[4096];
    __shared__ float zsm[128];
    if (t < 128) {
        float zz = 0.f;
#pragma unroll
        for (int ch = 0; ch < NCHUNK; ch++) zz += g_Zp[((size_t)ch * NB + b) * 128 + t];
        zsm[t] = zz;
    }
    __syncthreads();
    for (int i = t; i < 4096; i += 256) {
        int h = i >> 10, c = (i >> 5) & 31;
        int chan = h * 32 + c;
        float s = 0.f;
#pragma unroll
        for (int ch = 0; ch < NCHUNK; ch++)
            s += g_Sp[((size_t)ch * NB + b) * 4096 + i];
        ctxs[i] = s / zsm[chan];
    }
    __syncthreads();
    int row = seg * 64 + (t & 63);
    int g = t >> 6;
    const float* wr = Wout + row * 128 + g * 32;
    float wv[32];
#pragma unroll
    for (int e = 0; e < 32; e++) wv[e] = wr[e];
    __nv_bfloat16* Mr = g_Mb + (size_t)b * 32768 + row * 128 + g * 32;
    for (int c2 = 0; c2 < 32; c2++) {
        float s = 0.f;
#pragma unroll
        for (int e = 0; e < 32; e++) s += wv[e] * ctxs[g * 1024 + c2 * 32 + e];
        Mr[c2] = __float2bfloat16(s);
    }
}

// ---------------- final v3: register q-softmax (no staging), M via cp.async, mma + LN ----
#define KW2 72
#define FO_M   0               // 256*72 = 18432 words
#define FO_Q   18432           // 128*72 = 9216 words
#define FO_B   27648
#define FO_G   27904
#define FO_WS  28160           // 16*32
#define FO_WQ  28672
#define FO_CS  29184           // 128
#define FO_CQ  29312
#define F_TOT  29440           // words = 117760 bytes

__global__ void __launch_bounds__(512) final_mma(const float* __restrict__ bout,
                                                 const float* __restrict__ gam,
                                                 float* __restrict__ out) {
    extern __shared__ uint32_t fsm[];
    uint32_t* Msm = fsm + FO_M;
    uint32_t* Qsm = fsm + FO_Q;
    float* bsm = (float*)(fsm + FO_B);
    float* gsm = (float*)(fsm + FO_G);
    float* wsum = (float*)(fsm + FO_WS);
    float* wsq = (float*)(fsm + FO_WQ);
    float* csum = (float*)(fsm + FO_CS);
    float* csq = (float*)(fsm + FO_CQ);

    int b = blockIdx.y, n0 = blockIdx.x * 128, t = threadIdx.x;
    int lane = t & 31, w = t >> 5;
    int wm = w >> 2, wn = w & 3;
    int lq = lane >> 2, lr = lane & 3;

    // M tile via one cp.async group (overlaps with register q softmax below)
    const __nv_bfloat16* Mg = g_Mb + (size_t)b * 32768;
#pragma unroll
    for (int j = 0; j < 8; j++) {
        int c = t + 512 * j;
        int row = c >> 4, seg = c & 15;
        cpa16(smem_u32(&Msm[row * KW2 + seg * 4]), Mg + row * 128 + seg * 8);
    }
    CPA_COMMIT();

    if (t < 256) {
        bsm[t] = bout[t];
        gsm[t] = gam[t];
    }

    // q softmax from global into Qsm fragments: thread = (head h, col)
    {
        int h = t >> 7, col = t & 127;
        const __nv_bfloat16* Qc = g_qkvh + (size_t)b * 384 * NPOS + (size_t)(h * 32) * NPOS + n0 + col;
        float v[32];
        float ssum = 0.f;
#pragma unroll
        for (int i = 0; i < 32; i++) {
            v[i] = __expf(__bfloat162float(Qc[(size_t)i * NPOS]));
            ssum += v[i];
        }
        float inv = SCALE / ssum;
#pragma unroll
        for (int i2 = 0; i2 < 16; i2++) {
            __nv_bfloat162 p = __floats2bfloat162_rn(v[2 * i2] * inv, v[2 * i2 + 1] * inv);
            Qsm[col * KW2 + h * 16 + i2] = *(uint32_t*)&p;
        }
    }
    CPA_WAIT0();
    __syncthreads();

    float acc[4][4][4];
#pragma unroll
    for (int mt = 0; mt < 4; mt++)
#pragma unroll
        for (int nt = 0; nt < 4; nt++)
#pragma unroll
            for (int r = 0; r < 4; r++) acc[mt][nt][r] = 0.0f;

#pragma unroll
    for (int ks = 0; ks < 8; ks++) {
        int ksw = ks * 8;
        uint32_t af[4][4], bfr[4][2];
#pragma unroll
        for (int mt = 0; mt < 4; mt++) {
            int r0 = wm * 64 + mt * 16 + lq;
            af[mt][0] = Msm[r0 * KW2 + ksw + lr];
            af[mt][1] = Msm[(r0 + 8) * KW2 + ksw + lr];
            af[mt][2] = Msm[r0 * KW2 + ksw + lr + 4];
            af[mt][3] = Msm[(r0 + 8) * KW2 + ksw + lr + 4];
        }
#pragma unroll
        for (int nt = 0; nt < 4; nt++) {
            int n = wn * 32 + nt * 8 + lq;
            bfr[nt][0] = Qsm[n * KW2 + ksw + lr];
            bfr[nt][1] = Qsm[n * KW2 + ksw + lr + 4];
        }
#pragma unroll
        for (int mt = 0; mt < 4; mt++)
#pragma unroll
            for (int nt = 0; nt < 4; nt++) mma_bf16(acc[mt][nt], af[mt], bfr[nt]);
    }

    float ps[4][2], pq[4][2];
#pragma unroll
    for (int nt = 0; nt < 4; nt++)
#pragma unroll
        for (int j = 0; j < 2; j++) { ps[nt][j] = 0.f; pq[nt][j] = 0.f; }
#pragma unroll
    for (int mt = 0; mt < 4; mt++) {
        float b0v = bsm[wm * 64 + mt * 16 + lq];
        float b1v = bsm[wm * 64 + mt * 16 + lq + 8];
#pragma unroll
        for (int nt = 0; nt < 4; nt++) {
            acc[mt][nt][0] += b0v; acc[mt][nt][1] += b0v;
            acc[mt][nt][2] += b1v; acc[mt][nt][3] += b1v;
#pragma unroll
            for (int j = 0; j < 2; j++) {
                float v0 = acc[mt][nt][j], v1 = acc[mt][nt][2 + j];
                ps[nt][j] += v0 + v1;
                pq[nt][j] += v0 * v0 + v1 * v1;
            }
        }
    }
#pragma unroll
    for (int nt = 0; nt < 4; nt++)
#pragma unroll
        for (int j = 0; j < 2; j++) {
#pragma unroll
            for (int o = 4; o <= 16; o <<= 1) {
                ps[nt][j] += __shfl_xor_sync(0xffffffffu, ps[nt][j], o);
                pq[nt][j] += __shfl_xor_sync(0xffffffffu, pq[nt][j], o);
            }
        }
    if (lq == 0) {
#pragma unroll
        for (int nt = 0; nt < 4; nt++)
#pragma unroll
            for (int j = 0; j < 2; j++) {
                wsum[w * 32 + nt * 8 + 2 * lr + j] = ps[nt][j];
                wsq[w * 32 + nt * 8 + 2 * lr + j] = pq[nt][j];
            }
    }
    __syncthreads();
    if (t < 128) {
        int wnc = t >> 5, cl = t & 31;
        float sx = 0.f, sq2 = 0.f;
#pragma unroll
        for (int k = 0; k < 4; k++) {
            sx += wsum[(k * 4 + wnc) * 32 + cl];
            sq2 += wsq[(k * 4 + wnc) * 32 + cl];
        }
        csum[t] = sx;
        csq[t] = sq2;
    }
    __syncthreads();

    float mean[4][2], rs[4][2];
#pragma unroll
    for (int nt = 0; nt < 4; nt++)
#pragma unroll
        for (int j = 0; j < 2; j++) {
            int cg = wn * 32 + nt * 8 + 2 * lr + j;
            float mu = csum[cg] * (1.0f / 256.0f);
            float var = csq[cg] * (1.0f / 256.0f) - mu * mu;
            mean[nt][j] = mu;
            rs[nt][j] = rsqrtf(var + 1e-5f);
        }
#pragma unroll
    for (int mt = 0; mt < 4; mt++) {
        int r0 = wm * 64 + mt * 16 + lq;
        float g0 = gsm[r0], g1 = gsm[r0 + 8];
#pragma unroll
        for (int nt = 0; nt < 4; nt++) {
            int cc = n0 + wn * 32 + nt * 8 + 2 * lr;
            float2 o0, o1;
            o0.x = (acc[mt][nt][0] - mean[nt][0]) * rs[nt][0] * g0;
            o0.y = (acc[mt][nt][1] - mean[nt][1]) * rs[nt][1] * g0;
            o1.x = (acc[mt][nt][2] - mean[nt][0]) * rs[nt][0] * g1;
            o1.y = (acc[mt][nt][3] - mean[nt][1]) * rs[nt][1] * g1;
            *(float2*)&out[((size_t)(b * 256 + r0)) * NPOS + cc] = o0;
            *(float2*)&out[((size_t)(b * 256 + r0 + 8)) * NPOS + cc] = o1;
        }
    }
}

// ---------------- launch ----------------
extern "C" void kernel_launch(void* const* d_in, const int* in_sizes, int n_in,
                              void* d_out, int out_size) {
    (void)in_sizes; (void)n_in; (void)out_size;
    const float* x = (const float*)d_in[0];
    const float* cond = (const float*)d_in[1];
    const float* W_qkv = (const float*)d_in[2];
    const float* W_cond = (const float*)d_in[3];
    const float* b_cond = (const float*)d_in[4];
    const float* W_out = (const float*)d_in[5];
    const float* b_out = (const float*)d_in[6];
    const float* g = (const float*)d_in[7];
    float* out = (float*)d_out;

    film_kernel<<<NB, 512>>>(cond, W_cond, b_cond);
    wconv_kernel<<<96, 1024>>>(W_qkv);
    xconv_kernel<<<(NB * 256 * NPOS) / 1024, 256>>>(x);

    cudaFuncSetAttribute(qkv_mma, cudaFuncAttributeMaxDynamicSharedMemorySize, QKV_SMEM);
    qkv_mma<<<dim3(3, 32, NB), 256, QKV_SMEM>>>();

    int ctx_smem = 2 * 32 * KSE * (int)sizeof(__nv_bfloat16);
    cudaFuncSetAttribute(ctx_mma, cudaFuncAttributeMaxDynamicSharedMemorySize, ctx_smem);
    ctx_mma<<<dim3(NCHUNK, 4, NB), 256, ctx_smem>>>();

    buildM_kernel<<<dim3(4, NB), 256>>>(W_out);

    int smbytes = F_TOT * (int)sizeof(uint32_t);
    cudaFuncSetAttribute(final_mma, cudaFuncAttributeMaxDynamicSharedMemorySize, smbytes);
    final_mma<<<dim3(32, NB), 512, smbytes>>>(b_out, g, out);
}